// round 9
// baseline (speedup 1.0000x reference)
#include <cuda_runtime.h>
#include <cuda_fp16.h>
#include <cstdint>
#include <cstddef>

// ---------------------------------------------------------------------------
// Dimensions: B=4, H=W=8, M=16, C=256, NH=8, HD=32, GW=2
// ---------------------------------------------------------------------------
#define T0      65536
#define T1      4096
#define NWIN0   256
#define NWIN1   16

// gemm_mma config (wide-N GEMMs): 128x128 tile, BK=64, 3-stage, 2 tiles
#define TILE_BYTES 16384
#define BUF_BYTES  (2 * TILE_BYTES)
#define GEMM_SMEM  (3 * BUF_BYTES)

// gemm_ln config (N=256 GEMMs): 128x256 tile, BK=64, 2-stage
#define GLN_STAGE  49152                 // A 16KB + B 32KB
#define GLN_SMEM   (2 * GLN_STAGE)       // 98304

// Attention smem: Q,K,V fp16 256 rows x 80B stride
#define ATTN_ROWB  80
#define ATTN_SMEM  (3 * 256 * ATTN_ROWB)

// ---------------------------------------------------------------------------
// PTX helpers (sm_80-class only)
// ---------------------------------------------------------------------------
__device__ __forceinline__ uint32_t smem_u32(const void* p) {
    uint32_t a;
    asm("{ .reg .u64 t; cvta.to.shared.u64 t, %1; cvt.u32.u64 %0, t; }" : "=r"(a) : "l"(p));
    return a;
}
__device__ __forceinline__ void cp16(uint32_t dst, const void* src) {
    asm volatile("cp.async.cg.shared.global [%0], [%1], 16;" :: "r"(dst), "l"(src) : "memory");
}
#define CP_COMMIT() asm volatile("cp.async.commit_group;" ::: "memory")
#define CP_WAIT2()  asm volatile("cp.async.wait_group 2;" ::: "memory")
#define CP_WAIT1()  asm volatile("cp.async.wait_group 1;" ::: "memory")
#define CP_WAIT0()  asm volatile("cp.async.wait_group 0;" ::: "memory")

__device__ __forceinline__ void ldsm4(uint32_t& r0, uint32_t& r1, uint32_t& r2,
                                      uint32_t& r3, uint32_t addr) {
    asm volatile("ldmatrix.sync.aligned.m8n8.x4.shared.b16 {%0,%1,%2,%3}, [%4];"
                 : "=r"(r0), "=r"(r1), "=r"(r2), "=r"(r3) : "r"(addr));
}
__device__ __forceinline__ void ldsm4t(uint32_t& r0, uint32_t& r1, uint32_t& r2,
                                       uint32_t& r3, uint32_t addr) {
    asm volatile("ldmatrix.sync.aligned.m8n8.x4.trans.shared.b16 {%0,%1,%2,%3}, [%4];"
                 : "=r"(r0), "=r"(r1), "=r"(r2), "=r"(r3) : "r"(addr));
}
__device__ __forceinline__ void mma16816(float* c, const uint32_t* a, const uint32_t* b) {
    asm volatile(
        "mma.sync.aligned.m16n8k16.row.col.f32.f16.f16.f32 "
        "{%0,%1,%2,%3}, {%4,%5,%6,%7}, {%8,%9}, {%0,%1,%2,%3};"
        : "+f"(c[0]), "+f"(c[1]), "+f"(c[2]), "+f"(c[3])
        : "r"(a[0]), "r"(a[1]), "r"(a[2]), "r"(a[3]), "r"(b[0]), "r"(b[1]));
}
__device__ __forceinline__ uint32_t packh2(float a, float b) {
    __half2 h = __floats2half2_rn(a, b);
    return *(uint32_t*)&h;
}

// Row-level permutations (all bijective on row indices)
__device__ __forceinline__ int fine_perm(int r) {      // out-row -> fidx
    int fw = r >> 8, n = r & 255;
    int i = n >> 4, j = n & 15;
    return fw * 256 + ((i >> 2) * 4 + (j >> 2)) * 16 + ((i & 3) * 4 + (j & 3));
}
__device__ __forceinline__ int gather_perm(int r) {    // X1-row -> gidx
    int win = r >> 8, tok = r & 255;
    int b = win >> 2, gi = (win >> 1) & 1, gj = win & 1;
    int ti = tok >> 4, tj = tok & 15;
    int R = gi * 16 + ti, Cc = gj * 16 + tj;
    return ((b * 8 + (R >> 2)) * 8 + (Cc >> 2)) * 16 + (R & 3) * 4 + (Cc & 3);
}
__device__ __forceinline__ int scatter_perm(int g) {   // gidx -> o1-row
    int rr = g & 15, r1 = rr >> 2, r2 = rr & 3;
    int bhw = g >> 4;
    int w = bhw & 7, h = (bhw >> 3) & 7, b = bhw >> 6;
    int R = h * 4 + r1, Cc = w * 4 + r2;
    return (((b * 2 + (R >> 4)) * 2 + (Cc >> 4)) << 8) + (R & 15) * 16 + (Cc & 15);
}

// ---------------------------------------------------------------------------
// Scratch
// ---------------------------------------------------------------------------
__device__ float g_PE [2 * 256 * 256];
__device__ float g_X0 [(size_t)T0 * 256];
__device__ float g_X1 [(size_t)T1 * 256];
__device__ float g_G  [(size_t)T1 * 256];
__device__ float g_Qb [(size_t)T1 * 256];
__device__ __half g_QKVh[(size_t)T0 * 768];
__device__ __half g_A  [(size_t)T0 * 256];
__device__ __half g_Ac [(size_t)T1 * 256];
__device__ __half g_H1 [(size_t)T0 * 1024];
__device__ __half g_A3 [(size_t)T1 * 256];
__device__ __half g_WqkvT[2 * 768 * 256];
__device__ __half g_WoT  [2 * 256 * 256];
__device__ __half g_W1T  [2 * 1024 * 256];
__device__ __half g_W2T  [2 * 256 * 1024];

// ---------------------------------------------------------------------------
// LN helper: warp-per-token stats + fp16 output
// ---------------------------------------------------------------------------
__device__ __forceinline__ void ln_warp_store(float4 v0, float4 v1, int lane,
                                              const float* __restrict__ gamma,
                                              const float* __restrict__ beta,
                                              __half* __restrict__ orow) {
    float s = v0.x + v0.y + v0.z + v0.w + v1.x + v1.y + v1.z + v1.w;
#pragma unroll
    for (int d = 16; d; d >>= 1) s += __shfl_xor_sync(0xffffffffu, s, d);
    float mean = s * (1.f / 256.f);
    float d0x = v0.x - mean, d0y = v0.y - mean, d0z = v0.z - mean, d0w = v0.w - mean;
    float d1x = v1.x - mean, d1y = v1.y - mean, d1z = v1.z - mean, d1w = v1.w - mean;
    float q = d0x*d0x + d0y*d0y + d0z*d0z + d0w*d0w +
              d1x*d1x + d1y*d1y + d1z*d1z + d1w*d1w;
#pragma unroll
    for (int d = 16; d; d >>= 1) q += __shfl_xor_sync(0xffffffffu, q, d);
    float rstd = rsqrtf(q * (1.f / 256.f) + 1e-5f);
    float4 g0 = ((const float4*)gamma)[lane], g1 = ((const float4*)gamma)[lane + 32];
    float4 b0 = ((const float4*)beta)[lane],  b1 = ((const float4*)beta)[lane + 32];
    uint2 o0, o1;
    o0.x = packh2(fmaf(d0x * rstd, g0.x, b0.x), fmaf(d0y * rstd, g0.y, b0.y));
    o0.y = packh2(fmaf(d0z * rstd, g0.z, b0.z), fmaf(d0w * rstd, g0.w, b0.w));
    o1.x = packh2(fmaf(d1x * rstd, g1.x, b1.x), fmaf(d1y * rstd, g1.y, b1.y));
    o1.y = packh2(fmaf(d1z * rstd, g1.z, b1.z), fmaf(d1w * rstd, g1.w, b1.w));
    uint2* ou = (uint2*)orow;
    ou[lane] = o0;
    ou[lane + 32] = o1;
}

// ---------------------------------------------------------------------------
// Small kernels
// ---------------------------------------------------------------------------
__global__ void posemb_kernel(const float* __restrict__ pe_w1,
                              const float* __restrict__ pe_b1,
                              const float* __restrict__ pe_w2,
                              float* __restrict__ PE) {
    int s = blockIdx.x >> 8;
    int n = blockIdx.x & 255;
    int i = n >> 4, j = n & 15;
    float cy = (i - 8) * 0.125f;
    float cx = (j - 8) * 0.125f;
    __shared__ float hid[512];
    const float* w1 = pe_w1 + s * 2 * 512;
    const float* b1 = pe_b1 + s * 512;
    for (int k = threadIdx.x; k < 512; k += 256)
        hid[k] = fmaxf(0.f, fmaf(cy, w1[k], fmaf(cx, w1[512 + k], b1[k])));
    __syncthreads();
    const float* w2 = pe_w2 + (size_t)s * 512 * 256;
    int c = threadIdx.x;
    float acc = 0.f;
#pragma unroll 8
    for (int k = 0; k < 512; k++) acc = fmaf(hid[k], w2[(size_t)k * 256 + c], acc);
    PE[((size_t)s * 256 + n) * 256 + c] = acc;
}

__global__ void __launch_bounds__(256)
add_pe0_ln_kernel(const float* __restrict__ s0, const float* __restrict__ PE,
                  float* __restrict__ X0, __half* __restrict__ A,
                  const float* __restrict__ gamma, const float* __restrict__ beta) {
    int token = blockIdx.x * 8 + (threadIdx.x >> 5);
    int lane = threadIdx.x & 31;
    const float4* sr = (const float4*)(s0 + (size_t)token * 256);
    const float4* pr = (const float4*)(PE + (size_t)(token & 255) * 256);
    float4 v0 = sr[lane], v1 = sr[lane + 32];
    float4 p0 = pr[lane], p1 = pr[lane + 32];
    v0.x += p0.x; v0.y += p0.y; v0.z += p0.z; v0.w += p0.w;
    v1.x += p1.x; v1.y += p1.y; v1.z += p1.z; v1.w += p1.w;
    float4* xr = (float4*)(X0 + (size_t)token * 256);
    xr[lane] = v0; xr[lane + 32] = v1;
    ln_warp_store(v0, v1, lane, gamma, beta, A + (size_t)token * 256);
}

__global__ void __launch_bounds__(256)
pool_add_ln_kernel(const float* __restrict__ s1, const float* __restrict__ PE,
                   const float* __restrict__ X0, float* __restrict__ X1,
                   __half* __restrict__ Ac,
                   const float* __restrict__ gamma, const float* __restrict__ beta) {
    int token = blockIdx.x * 8 + (threadIdx.x >> 5);
    int lane = threadIdx.x & 31;
    int t  = token & 255;
    int gw = token >> 8;
    int b = gw >> 2, gi = (gw >> 1) & 1, gj = gw & 1;
    int ti = t >> 4, tj = t & 15;
    int R  = gi * 16 + ti, Cc = gj * 16 + tj;
    int h = R >> 2, r1 = R & 3, w = Cc >> 2, r2 = Cc & 3;
    int fw = b * 64 + h * 8 + w;
    float4 m0 = make_float4(-1e30f, -1e30f, -1e30f, -1e30f), m1 = m0;
#pragma unroll
    for (int p1 = 0; p1 < 4; p1++)
#pragma unroll
        for (int p2 = 0; p2 < 4; p2++) {
            int n = (r1 * 4 + p1) * 16 + r2 * 4 + p2;
            const float4* row = (const float4*)(X0 + ((size_t)fw * 256 + n) * 256);
            float4 a = row[lane], c = row[lane + 32];
            m0.x = fmaxf(m0.x, a.x); m0.y = fmaxf(m0.y, a.y);
            m0.z = fmaxf(m0.z, a.z); m0.w = fmaxf(m0.w, a.w);
            m1.x = fmaxf(m1.x, c.x); m1.y = fmaxf(m1.y, c.y);
            m1.z = fmaxf(m1.z, c.z); m1.w = fmaxf(m1.w, c.w);
        }
    const float4* sr = (const float4*)(s1 + (size_t)token * 256);
    const float4* pr = (const float4*)(PE + (size_t)(256 + t) * 256);
    float4 s0v = sr[lane], s1v = sr[lane + 32];
    float4 p0 = pr[lane], p1v = pr[lane + 32];
    m0.x += s0v.x + p0.x; m0.y += s0v.y + p0.y;
    m0.z += s0v.z + p0.z; m0.w += s0v.w + p0.w;
    m1.x += s1v.x + p1v.x; m1.y += s1v.y + p1v.y;
    m1.z += s1v.z + p1v.z; m1.w += s1v.w + p1v.w;
    float4* xr = (float4*)(X1 + (size_t)token * 256);
    xr[lane] = m0; xr[lane + 32] = m1;
    ln_warp_store(m0, m1, lane, gamma, beta, Ac + (size_t)token * 256);
}

__global__ void wconv_all_kernel(const float* __restrict__ wqkv,
                                 const float* __restrict__ wo,
                                 const float* __restrict__ mw1,
                                 const float* __restrict__ mw2,
                                 __half* __restrict__ Tqkv, __half* __restrict__ To,
                                 __half* __restrict__ Tm1,  __half* __restrict__ Tm2) {
    int bid = blockIdx.x;
    int s = bid / 2304, r = bid % 2304;
    const float* W; __half* T; int K, N, n;
    if (r < 768)       { W = wqkv + (size_t)s * 196608; T = Tqkv + (size_t)s * 196608; K = 256;  N = 768;  n = r; }
    else if (r < 1024) { W = wo   + (size_t)s * 65536;  T = To   + (size_t)s * 65536;  K = 256;  N = 256;  n = r - 768; }
    else if (r < 2048) { W = mw1  + (size_t)s * 262144; T = Tm1  + (size_t)s * 262144; K = 256;  N = 1024; n = r - 1024; }
    else               { W = mw2  + (size_t)s * 262144; T = Tm2  + (size_t)s * 262144; K = 1024; N = 256;  n = r - 2048; }
    for (int k = threadIdx.x; k < K; k += 256)
        T[(size_t)n * K + k] = __float2half(W[(size_t)k * N + n]);
}

// ---------------------------------------------------------------------------
// fp16 1-pass GEMM, wide N (grid.x = N/128).  EPI 0: fp32. 1: GELU->fp16. 3: fp16.
// ---------------------------------------------------------------------------
template <int EPI>
__global__ void __launch_bounds__(256)
gemm_mma(const __half* __restrict__ A, const __half* __restrict__ B,
         const float* __restrict__ bias,
         float* __restrict__ Cp, __half* __restrict__ Oh,
         int K, int ldc) {
    extern __shared__ char smc[];
    const uint32_t sb = smem_u32(smc);
    int tid = threadIdx.x, lane = tid & 31, wid = tid >> 5;
    int wm = wid >> 2, wn = wid & 3;
    int bm = blockIdx.y, bn = blockIdx.x;

    const __half* src0 = A + (size_t)bm * 128 * K;
    const __half* src1 = B + (size_t)bn * 128 * K;

    int nc = K >> 6;
    int crow0 = tid >> 3, ccol = tid & 7;

#define PREFETCH(CH, BUF) do {                                                 \
    int _k0 = (CH) << 6;                                                       \
    const __half* _s[2] = {src0 + _k0, src1 + _k0};                            \
    _Pragma("unroll")                                                          \
    for (int _op = 0; _op < 2; _op++) {                                        \
        uint32_t _db = sb + (BUF) * BUF_BYTES + _op * TILE_BYTES;              \
        _Pragma("unroll")                                                      \
        for (int _i = 0; _i < 4; _i++) {                                       \
            int _row = crow0 + _i * 32;                                        \
            uint32_t _doff = _db + _row * 128 + ((ccol ^ (_row & 7)) << 4);    \
            cp16(_doff, _s[_op] + (size_t)_row * K + ccol * 8);                \
        }                                                                      \
    }                                                                          \
} while (0)

    float acc[4][4][4];
#pragma unroll
    for (int mi = 0; mi < 4; mi++)
#pragma unroll
        for (int ni = 0; ni < 4; ni++)
#pragma unroll
            for (int r = 0; r < 4; r++) acc[mi][ni][r] = 0.f;

    PREFETCH(0, 0);
    CP_COMMIT();
    if (nc > 1) { PREFETCH(1, 1); CP_COMMIT(); }

    int a_rl = lane & 15;
    int b_rl = ((lane >> 4) << 3) + (lane & 7);

    for (int ch = 0; ch < nc; ch++) {
        int buf = ch % 3;
        if (ch + 2 < nc) {
            PREFETCH(ch + 2, (ch + 2) % 3);
            CP_COMMIT();
            CP_WAIT2();
        } else if (ch + 1 < nc) {
            CP_WAIT1();
        } else {
            CP_WAIT0();
        }
        __syncthreads();

        uint32_t base = sb + buf * BUF_BYTES;
#pragma unroll
        for (int ks = 0; ks < 4; ks++) {
            uint32_t ah[4][4], bh[4][2];
            int achunk = ks * 2 + (lane >> 4);
            int bchunk = ks * 2 + ((lane >> 3) & 1);
#pragma unroll
            for (int mi = 0; mi < 4; mi++) {
                int row = wm * 64 + mi * 16 + a_rl;
                uint32_t off = (uint32_t)(row * 128 + ((achunk ^ (row & 7)) << 4));
                ldsm4(ah[mi][0], ah[mi][1], ah[mi][2], ah[mi][3], base + off);
            }
#pragma unroll
            for (int np = 0; np < 2; np++) {
                int row = wn * 32 + np * 16 + b_rl;
                uint32_t off = (uint32_t)(row * 128 + ((bchunk ^ (row & 7)) << 4));
                uint32_t r0, r1, r2, r3;
                ldsm4(r0, r1, r2, r3, base + TILE_BYTES + off);
                bh[np * 2][0] = r0; bh[np * 2][1] = r1;
                bh[np * 2 + 1][0] = r2; bh[np * 2 + 1][1] = r3;
            }
#pragma unroll
            for (int mi = 0; mi < 4; mi++)
#pragma unroll
                for (int ni = 0; ni < 4; ni++)
                    mma16816(acc[mi][ni], ah[mi], bh[ni]);
        }
        __syncthreads();
    }
#undef PREFETCH

    int l4 = lane >> 2, l2 = (lane & 3) << 1;
#pragma unroll
    for (int mi = 0; mi < 4; mi++) {
        int r0 = bm * 128 + wm * 64 + mi * 16 + l4;
#pragma unroll
        for (int ni = 0; ni < 4; ni++) {
            int cc = bn * 128 + wn * 32 + ni * 8 + l2;
            float b0 = bias[cc], b1 = bias[cc + 1];
            float v00 = acc[mi][ni][0] + b0, v01 = acc[mi][ni][1] + b1;
            float v10 = acc[mi][ni][2] + b0, v11 = acc[mi][ni][3] + b1;
            size_t o0 = (size_t)r0 * ldc + cc;
            size_t o1 = (size_t)(r0 + 8) * ldc + cc;
            if (EPI == 1) {
                const float is2 = 0.7071067811865476f;
                float g00 = 0.5f * v00 * (1.f + erff(v00 * is2));
                float g01 = 0.5f * v01 * (1.f + erff(v01 * is2));
                float g10 = 0.5f * v10 * (1.f + erff(v10 * is2));
                float g11 = 0.5f * v11 * (1.f + erff(v11 * is2));
                *(uint32_t*)(Oh + o0) = packh2(g00, g01);
                *(uint32_t*)(Oh + o1) = packh2(g10, g11);
            } else if (EPI == 3) {
                *(uint32_t*)(Oh + o0) = packh2(v00, v01);
                *(uint32_t*)(Oh + o1) = packh2(v10, v11);
            } else {
                *(float2*)(Cp + o0) = make_float2(v00, v01);
                *(float2*)(Cp + o1) = make_float2(v10, v11);
            }
        }
    }
}

// ---------------------------------------------------------------------------
// gemm_ln: N=256 GEMM, full row per CTA, residual add + fused row-LN epilogue.
// 128x256 tile, 512 threads (16 warps, 4x4 of 32x64), BK=64, 2-stage.
// MODE 0: Cp[r]=v, Oh[r]=LN(v)
// MODE 1: Cp[r]=v, Oh[fine_perm(r)]=LN(v)
// MODE 2: Cp[r]=v, Gc[gather_perm(r)]=v, Oh[gather_perm(r)]=LN(v)
// MODE 3: Cp[scatter_perm(r)]=v   (no LN)
// ---------------------------------------------------------------------------
template <int MODE>
__global__ void __launch_bounds__(512)
gemm_ln(const __half* __restrict__ A, const __half* __restrict__ B,
        const float* __restrict__ bias, const float* __restrict__ res,
        float* __restrict__ Cp, float* __restrict__ Gc, __half* __restrict__ Oh,
        const float* __restrict__ gamma, const float* __restrict__ beta, int K) {
    extern __shared__ char smc[];
    const uint32_t sb = smem_u32(smc);
    int tid = threadIdx.x, lane = tid & 31, wid = tid >> 5;
    int wm = wid >> 2, wn = wid & 3;          // warp tile: rows wm*32, cols wn*64
    int bm = blockIdx.y;
    const __half* srcA = A + (size_t)bm * 128 * K;
    int nc = K >> 6;
    int crow0 = tid >> 3, ccol = tid & 7;

#define PF(CH, BUF) do {                                                       \
    int _k0 = (CH) << 6;                                                       \
    uint32_t _db = sb + (BUF) * GLN_STAGE;                                     \
    _Pragma("unroll")                                                          \
    for (int _i = 0; _i < 2; _i++) {                                           \
        int _row = crow0 + _i * 64;                                            \
        cp16(_db + _row * 128 + ((ccol ^ (_row & 7)) << 4),                    \
             srcA + (size_t)_row * K + _k0 + ccol * 8);                        \
    }                                                                          \
    _Pragma("unroll")                                                          \
    for (int _i = 0; _i < 4; _i++) {                                           \
        int _row = crow0 + _i * 64;                                            \
        cp16(_db + 16384 + _row * 128 + ((ccol ^ (_row & 7)) << 4),            \
             B + (size_t)_row * K + _k0 + ccol * 8);                           \
    }                                                                          \
} while (0)

    float acc[2][8][4];
#pragma unroll
    for (int mi = 0; mi < 2; mi++)
#pragma unroll
        for (int ni = 0; ni < 8; ni++)
#pragma unroll
            for (int r = 0; r < 4; r++) acc[mi][ni][r] = 0.f;

    PF(0, 0);
    CP_COMMIT();

    int a_rl = lane & 15;
    int b_rl = ((lane >> 4) << 3) + (lane & 7);

    for (int ch = 0; ch < nc; ch++) {
        if (ch + 1 < nc) {
            PF(ch + 1, (ch + 1) & 1);
            CP_COMMIT();
            CP_WAIT1();
        } else {
            CP_WAIT0();
        }
        __syncthreads();
        uint32_t base = sb + (ch & 1) * GLN_STAGE;
#pragma unroll
        for (int ks = 0; ks < 4; ks++) {
            uint32_t ah[2][4], bh[8][2];
            int achunk = ks * 2 + (lane >> 4);
            int bchunk = ks * 2 + ((lane >> 3) & 1);
#pragma unroll
            for (int mi = 0; mi < 2; mi++) {
                int row = wm * 32 + mi * 16 + a_rl;
                uint32_t off = (uint32_t)(row * 128 + ((achunk ^ (row & 7)) << 4));
                ldsm4(ah[mi][0], ah[mi][1], ah[mi][2], ah[mi][3], base + off);
            }
#pragma unroll
            for (int np = 0; np < 4; np++) {
                int row = wn * 64 + np * 16 + b_rl;
                uint32_t off = (uint32_t)(row * 128 + ((bchunk ^ (row & 7)) << 4));
                uint32_t r0, r1, r2, r3;
                ldsm4(r0, r1, r2, r3, base + 16384 + off);
                bh[np * 2][0] = r0; bh[np * 2][1] = r1;
                bh[np * 2 + 1][0] = r2; bh[np * 2 + 1][1] = r3;
            }
#pragma unroll
            for (int mi = 0; mi < 2; mi++)
#pragma unroll
                for (int ni = 0; ni < 8; ni++)
                    mma16816(acc[mi][ni], ah[mi], bh[ni]);
        }
        __syncthreads();
    }
#undef PF

    // --- Epilogue: bias + residual, main writes, fused row LN ---
    int l4 = lane >> 2, l2 = (lane & 3) << 1;
    float* red = (float*)smc;   // [128][8]: (sum, sq) per (row, wn); mainloop done

#pragma unroll
    for (int mi = 0; mi < 2; mi++)
#pragma unroll
        for (int h = 0; h < 2; h++) {
            int lrow = wm * 32 + mi * 16 + h * 8 + l4;
            int grow = bm * 128 + lrow;
            size_t rbase = (size_t)grow * 256;
            float s = 0.f, q = 0.f;
#pragma unroll
            for (int ni = 0; ni < 8; ni++) {
                int cc = wn * 64 + ni * 8 + l2;
                float2 bv = *(const float2*)(bias + cc);
                float2 rv = *(const float2*)(res + rbase + cc);
                float v0 = acc[mi][ni][h * 2]     + bv.x + rv.x;
                float v1 = acc[mi][ni][h * 2 + 1] + bv.y + rv.y;
                acc[mi][ni][h * 2]     = v0;
                acc[mi][ni][h * 2 + 1] = v1;
                s += v0 + v1;
                q += v0 * v0 + v1 * v1;
            }
            // main output
            if (MODE == 3) {
                size_t ob = (size_t)scatter_perm(grow) * 256;
#pragma unroll
                for (int ni = 0; ni < 8; ni++) {
                    int cc = wn * 64 + ni * 8 + l2;
                    *(float2*)(Cp + ob + cc) =
                        make_float2(acc[mi][ni][h * 2], acc[mi][ni][h * 2 + 1]);
                }
            } else {
#pragma unroll
                for (int ni = 0; ni < 8; ni++) {
                    int cc = wn * 64 + ni * 8 + l2;
                    *(float2*)(Cp + rbase + cc) =
                        make_float2(acc[mi][ni][h * 2], acc[mi][ni][h * 2 + 1]);
                }
                if (MODE == 2) {
                    size_t gb = (size_t)gather_perm(grow) * 256;
#pragma unroll
                    for (int ni = 0; ni < 8; ni++) {
                        int cc = wn * 64 + ni * 8 + l2;
                        *(float2*)(Gc + gb + cc) =
                            make_float2(acc[mi][ni][h * 2], acc[mi][ni][h * 2 + 1]);
                    }
                }
                // LN partials: quad-reduce then per-warp slot
                s += __shfl_xor_sync(0xffffffffu, s, 1);
                s += __shfl_xor_sync(0xffffffffu, s, 2);
                q += __shfl_xor_sync(0xffffffffu, q, 1);
                q += __shfl_xor_sync(0xffffffffu, q, 2);
                if ((lane & 3) == 0) {
                    red[lrow * 8 + wn * 2]     = s;
                    red[lrow * 8 + wn * 2 + 1] = q;
                }
            }
        }

    if (MODE != 3) {
        __syncthreads();
#pragma unroll
        for (int mi = 0; mi < 2; mi++)
#pragma unroll
            for (int h = 0; h < 2; h++) {
                int lrow = wm * 32 + mi * 16 + h * 8 + l4;
                int grow = bm * 128 + lrow;
                float ssum = red[lrow * 8 + 0] + red[lrow * 8 + 2] +
                             red[lrow * 8 + 4] + red[lrow * 8 + 6];
                float qsum = red[lrow * 8 + 1] + red[lrow * 8 + 3] +
                             red[lrow * 8 + 5] + red[lrow * 8 + 7];
                float mean = ssum * (1.f / 256.f);
                float var = qsum * (1.f / 256.f) - mean * mean;
                float rstd = rsqrtf(var + 1e-5f);
                int prow = (MODE == 0) ? grow
                         : (MODE == 1) ? fine_perm(grow) : gather_perm(grow);
                size_t ob = (size_t)prow * 256;
#pragma unroll
                for (int ni = 0; ni < 8; ni++) {
                    int cc = wn * 64 + ni * 8 + l2;
                    float2 gv = *(const float2*)(gamma + cc);
                    float2 bv = *(const float2*)(beta + cc);
                    float a0 = (acc[mi][ni][h * 2]     - mean) * rstd * gv.x + bv.x;
                    float a1 = (acc[mi][ni][h * 2 + 1] - mean) * rstd * gv.y + bv.y;
                    *(uint32_t*)(Oh + ob + cc) = packh2(a0, a1);
                }
            }
    }
}

// ---------------------------------------------------------------------------
// Tensor-core flash attention, no-max single-pass softmax.
// ---------------------------------------------------------------------------
__global__ void __launch_bounds__(256)
attn_mma_kernel(const __half* __restrict__ qkv, __half* __restrict__ out) {
    extern __shared__ char smc[];
    const uint32_t sb = smem_u32(smc);
    const uint32_t sbQ = sb, sbK = sb + 256 * ATTN_ROWB, sbV = sb + 512 * ATTN_ROWB;
    int win = blockIdx.x >> 3, head = blockIdx.x & 7;
    int tid = threadIdx.x, lane = tid & 31, wid = tid >> 5;

    {
        const uint4* src = (const uint4*)(qkv + ((size_t)(win * 256 + tid) * 768 + head * 32));
        uint4* dq = (uint4*)(smc + tid * ATTN_ROWB);
        uint4* dk = (uint4*)(smc + 256 * ATTN_ROWB + tid * ATTN_ROWB);
        uint4* dv = (uint4*)(smc + 512 * ATTN_ROWB + tid * ATTN_ROWB);
#pragma unroll
        for (int c = 0; c < 4; c++) dq[c] = src[c];
#pragma unroll
        for (int c = 0; c < 4; c++) dk[c] = src[32 + c];
#pragma unroll
        for (int c = 0; c < 4; c++) dv[c] = src[64 + c];
    }
    __syncthreads();

    uint32_t aq[2][2][4];
#pragma unroll
    for (int mi = 0; mi < 2; mi++)
#pragma unroll
        for (int kt = 0; kt < 2; kt++) {
            int row = wid * 32 + mi * 16 + (lane & 15);
            uint32_t addr = sbQ + row * ATTN_ROWB + (kt * 2 + (lane >> 4)) * 16;
            ldsm4(aq[mi][kt][0], aq[mi][kt][1], aq[mi][kt][2], aq[mi][kt][3], addr);
        }

    float o[2][4][4];
#pragma unroll
    for (int mi = 0; mi < 2; mi++)
#pragma unroll
        for (int ni = 0; ni < 4; ni++)
#pragma unroll
            for (int r = 0; r < 4; r++) o[mi][ni][r] = 0.f;
    float l[2][2] = {{0.f, 0.f}, {0.f, 0.f}};
    const float sc = 0.17677669529663687f * 1.4426950408889634f;

    for (int kc = 0; kc < 4; kc++) {
        float s[2][8][4];
#pragma unroll
        for (int mi = 0; mi < 2; mi++)
#pragma unroll
            for (int ni = 0; ni < 8; ni++)
#pragma unroll
                for (int r = 0; r < 4; r++) s[mi][ni][r] = 0.f;

#pragma unroll
        for (int nt = 0; nt < 4; nt++) {
            int keyrow = kc * 64 + nt * 16 + (lane & 15);
#pragma unroll
            for (int kt = 0; kt < 2; kt++) {
                uint32_t addr = sbK + keyrow * ATTN_ROWB + (kt * 2 + (lane >> 4)) * 16;
                uint32_t r0, r1, r2, r3;
                ldsm4(r0, r1, r2, r3, addr);
                uint32_t blo[2] = {r0, r2}, bhi[2] = {r1, r3};
#pragma unroll
                for (int mi = 0; mi < 2; mi++) {
                    mma16816(s[mi][nt * 2],     aq[mi][kt], blo);
                    mma16816(s[mi][nt * 2 + 1], aq[mi][kt], bhi);
                }
            }
        }

#pragma unroll
        for (int mi = 0; mi < 2; mi++)
#pragma unroll
            for (int ni = 0; ni < 8; ni++) {
                float p0 = exp2f(s[mi][ni][0] * sc);
                float p1 = exp2f(s[mi][ni][1] * sc);
                float p2 = exp2f(s[mi][ni][2] * sc);
                float p3 = exp2f(s[mi][ni][3] * sc);
                s[mi][ni][0] = p0; s[mi][ni][1] = p1;
                s[mi][ni][2] = p2; s[mi][ni][3] = p3;
                l[mi][0] += p0 + p1;
                l[mi][1] += p2 + p3;
            }

        uint32_t pa[2][4][4];
#pragma unroll
        for (int mi = 0; mi < 2; mi++)
#pragma unroll
            for (int kt = 0; kt < 4; kt++) {
                pa[mi][kt][0] = packh2(s[mi][kt * 2][0], s[mi][kt * 2][1]);
                pa[mi][kt][1] = packh2(s[mi][kt * 2][2], s[mi][kt * 2][3]);
                pa[mi][kt][2] = packh2(s[mi][kt * 2 + 1][0], s[mi][kt * 2 + 1][1]);
                pa[mi][kt][3] = packh2(s[mi][kt * 2 + 1][2], s[mi][kt * 2 + 1][3]);
            }

#pragma unroll
        for (int kt = 0; kt < 4; kt++) {
            int keyrow = kc * 64 + kt * 16 + (lane & 15);
#pragma unroll
            for (int dc = 0; dc < 2; dc++) {
                uint32_t addr = sbV + keyrow * ATTN_ROWB + (dc * 2 + (lane >> 4)) * 16;
                uint32_t r0, r1, r2, r3;
                ldsm4t(r0, r1, r2, r3, addr);
                uint32_t b0[2] = {r0, r1}, b1[2] = {r2, r3};
#pragma unroll
                for (int mi = 0; mi < 2; mi++) {
                    mma16816(o[mi][dc * 2],     pa[mi][kt], b0);
                    mma16816(o[mi][dc * 2 + 1], pa[mi][kt], b1);
                }
            }
        }
    }

#pragma unroll
    for (int mi = 0; mi < 2; mi++)
#pragma unroll
        for (int h = 0; h < 2; h++) {
            float v = l[mi][h];
            v += __shfl_xor_sync(0xffffffffu, v, 1);
            v += __shfl_xor_sync(0xffffffffu, v, 2);
            l[mi][h] = v;
        }

    int l4 = lane >> 2, l2 = (lane & 3) << 1;
#pragma unroll
    for (int mi = 0; mi < 2; mi++)
#pragma unroll
        for (int h = 0; h < 2; h++) {
            float inv = 1.f / l[mi][h];
            int row = wid * 32 + mi * 16 + l4 + h * 8;
            size_t ob = ((size_t)(win * 256 + row)) * 256 + head * 32;
#pragma unroll
            for (int ni = 0; ni < 4; ni++) {
                *(uint32_t*)(out + ob + ni * 8 + l2) =
                    packh2(o[mi][ni][h * 2] * inv, o[mi][ni][h * 2 + 1] * inv);
            }
        }
}

// ---------------------------------------------------------------------------
// Cross attention: 1 query x 16 keys, warp per head
// ---------------------------------------------------------------------------
__global__ void __launch_bounds__(256)
cross_attn_kernel(const float* __restrict__ Q, const __half* __restrict__ KV,
                  __half* __restrict__ oh) {
    int g = blockIdx.x;
    int head = threadIdx.x >> 5, lane = threadIdx.x & 31;
    float qd = Q[(size_t)g * 256 + head * 32 + lane];
    size_t kvbase = (size_t)g * 16 * 512 + head * 32 + lane;
    const float sc = 0.17677669529663687f * 1.4426950408889634f;
    float s[16];
#pragma unroll
    for (int j = 0; j < 16; j++) {
        float p = qd * __half2float(KV[kvbase + (size_t)j * 512]);
#pragma unroll
        for (int o = 16; o; o >>= 1) p += __shfl_xor_sync(0xffffffffu, p, o);
        s[j] = p * sc;
    }
    float l = 0.f;
#pragma unroll
    for (int j = 0; j < 16; j++) { s[j] = exp2f(s[j]); l += s[j]; }
    float inv = 1.f / l, acc = 0.f;
#pragma unroll
    for (int j = 0; j < 16; j++)
        acc = fmaf(s[j], __half2float(KV[kvbase + 256 + (size_t)j * 512]), acc);
    oh[(size_t)g * 256 + head * 32 + lane] = __float2half(acc * inv);
}

// ---------------------------------------------------------------------------
// Host launch
// ---------------------------------------------------------------------------
extern "C" void kernel_launch(void* const* d_in, const int* in_sizes, int n_in,
                              void* d_out, int out_size) {
    const float* scale0 = (const float*)d_in[0];
    const float* scale1 = (const float*)d_in[1];
    const float* pe_w1  = (const float*)d_in[2];
    const float* pe_b1  = (const float*)d_in[3];
    const float* pe_w2  = (const float*)d_in[4];
    const float* ln1_g  = (const float*)d_in[5];
    const float* ln1_b  = (const float*)d_in[6];
    const float* wqkv   = (const float*)d_in[7];
    const float* bqkv   = (const float*)d_in[8];
    const float* wo     = (const float*)d_in[9];
    const float* bo     = (const float*)d_in[10];
    const float* ln2_g  = (const float*)d_in[11];
    const float* ln2_b  = (const float*)d_in[12];
    const float* mw1    = (const float*)d_in[13];
    const float* mb1    = (const float*)d_in[14];
    const float* mw2    = (const float*)d_in[15];
    const float* mb2    = (const float*)d_in[16];
    float* out = (float*)d_out;

    float *PE, *X0, *X1, *G, *Qb;
    __half *QKVh, *A, *Ac, *H1, *A3;
    __half *WqkvT, *WoT, *W1T, *W2T;
    cudaGetSymbolAddress((void**)&PE,   g_PE);
    cudaGetSymbolAddress((void**)&X0,   g_X0);
    cudaGetSymbolAddress((void**)&X1,   g_X1);
    cudaGetSymbolAddress((void**)&G,    g_G);
    cudaGetSymbolAddress((void**)&Qb,   g_Qb);
    cudaGetSymbolAddress((void**)&QKVh, g_QKVh);
    cudaGetSymbolAddress((void**)&A,    g_A);
    cudaGetSymbolAddress((void**)&Ac,   g_Ac);
    cudaGetSymbolAddress((void**)&H1,   g_H1);
    cudaGetSymbolAddress((void**)&A3,   g_A3);
    cudaGetSymbolAddress((void**)&WqkvT, g_WqkvT);
    cudaGetSymbolAddress((void**)&WoT,   g_WoT);
    cudaGetSymbolAddress((void**)&W1T,   g_W1T);
    cudaGetSymbolAddress((void**)&W2T,   g_W2T);

    cudaFuncSetAttribute(attn_mma_kernel, cudaFuncAttributeMaxDynamicSharedMemorySize, ATTN_SMEM);
    cudaFuncSetAttribute(gemm_mma<0>, cudaFuncAttributeMaxDynamicSharedMemorySize, GEMM_SMEM);
    cudaFuncSetAttribute(gemm_mma<1>, cudaFuncAttributeMaxDynamicSharedMemorySize, GEMM_SMEM);
    cudaFuncSetAttribute(gemm_mma<3>, cudaFuncAttributeMaxDynamicSharedMemorySize, GEMM_SMEM);
    cudaFuncSetAttribute(gemm_ln<0>, cudaFuncAttributeMaxDynamicSharedMemorySize, GLN_SMEM);
    cudaFuncSetAttribute(gemm_ln<1>, cudaFuncAttributeMaxDynamicSharedMemorySize, GLN_SMEM);
    cudaFuncSetAttribute(gemm_ln<2>, cudaFuncAttributeMaxDynamicSharedMemorySize, GLN_SMEM);
    cudaFuncSetAttribute(gemm_ln<3>, cudaFuncAttributeMaxDynamicSharedMemorySize, GLN_SMEM);

    // 0) weights + position embeddings
    wconv_all_kernel<<<4608, 256>>>(wqkv, wo, mw1, mw2, WqkvT, WoT, W1T, W2T);
    posemb_kernel<<<512, 256>>>(pe_w1, pe_b1, pe_w2, PE);

    // 1) inputs with fused LN1
    add_pe0_ln_kernel<<<T0 / 8, 256>>>(scale0, PE, X0, A, ln1_g, ln1_b);
    pool_add_ln_kernel<<<T1 / 8, 256>>>(scale1, PE, X0, X1, Ac,
                                        ln1_g + 256, ln1_b + 256);

    // 2a) coarse self-attention block (s=1)
    gemm_mma<3><<<dim3(6, 32), 256, GEMM_SMEM>>>(
        Ac, WqkvT + 196608, bqkv + 768, nullptr, QKVh, 256, 768);
    attn_mma_kernel<<<NWIN1 * 8, 256, ATTN_SMEM>>>(QKVh, Ac);
    gemm_ln<0><<<dim3(1, 32), 512, GLN_SMEM>>>(
        Ac, WoT + 65536, bo + 256, X1, X1, nullptr, Ac,
        ln2_g + 256, ln2_b + 256, 256);
    gemm_mma<1><<<dim3(8, 32), 256, GEMM_SMEM>>>(
        Ac, W1T + 262144, mb1 + 1024, nullptr, H1, 256, 1024);
    gemm_ln<2><<<dim3(1, 32), 512, GLN_SMEM>>>(
        H1, W2T + 262144, mb2 + 256, X1, X1, G, A3,
        ln1_g + 256, ln1_b + 256, 1024);   // X1 final; G=perm copy; A3=LN1[1] perm

    // 2b) fine self-attention block (s=0)
    gemm_mma<3><<<dim3(6, 512), 256, GEMM_SMEM>>>(
        A, WqkvT, bqkv, nullptr, QKVh, 256, 768);
    attn_mma_kernel<<<NWIN0 * 8, 256, ATTN_SMEM>>>(QKVh, A);
    gemm_ln<0><<<dim3(1, 512), 512, GLN_SMEM>>>(
        A, WoT, bo, X0, X0, nullptr, A, ln2_g, ln2_b, 256);
    gemm_mma<1><<<dim3(8, 512), 256, GEMM_SMEM>>>(
        A, W1T, mb1, nullptr, H1, 256, 1024);
    gemm_ln<1><<<dim3(1, 512), 512, GLN_SMEM>>>(
        H1, W2T, mb2, X0, out, nullptr, A,
        ln1_g + 256, ln1_b + 256, 1024);   // out=o0; A=LN1[1](fine-perm) for cross KV

    // 3) one2one cross-attention aggregation (scale-1 weights)
    gemm_mma<0><<<dim3(2, 32), 256, GEMM_SMEM>>>(
        A3, WqkvT + 196608, bqkv + 768, Qb, nullptr, 256, 256);
    gemm_mma<3><<<dim3(4, 512), 256, GEMM_SMEM>>>(
        A, WqkvT + 196608 + 65536, bqkv + 768 + 256, nullptr, QKVh, 256, 512);
    cross_attn_kernel<<<T1, 256>>>(Qb, QKVh, A3);
    gemm_ln<0><<<dim3(1, 32), 512, GLN_SMEM>>>(
        A3, WoT + 65536, bo + 256, G, G, nullptr, A3,
        ln2_g + 256, ln2_b + 256, 256);
    gemm_mma<1><<<dim3(8, 32), 256, GEMM_SMEM>>>(
        A3, W1T + 262144, mb1 + 1024, nullptr, H1, 256, 1024);
    gemm_ln<3><<<dim3(1, 32), 512, GLN_SMEM>>>(
        H1, W2T + 262144, mb2 + 256, G, out + (size_t)NWIN0 * 256 * 256,
        nullptr, nullptr, nullptr, nullptr, 1024);
}

// round 10
// speedup vs baseline: 1.0425x; 1.0425x over previous
#include <cuda_runtime.h>
#include <cuda_fp16.h>
#include <cstdint>
#include <cstddef>

// ---------------------------------------------------------------------------
// Dimensions: B=4, H=W=8, M=16, C=256, NH=8, HD=32, GW=2
// ---------------------------------------------------------------------------
#define T0      65536
#define T1      4096
#define NWIN0   256
#define NWIN1   16

// gemm_mma config (wide-N GEMMs): 128x128 tile, BK=64, 3-stage, 2 tiles
#define TILE_BYTES 16384
#define BUF_BYTES  (2 * TILE_BYTES)
#define GEMM_SMEM  (3 * BUF_BYTES)

// gemm_ln64 config: 64x256 tile, BK=64, 2-stage, 256 threads -> 2 CTA/SM
#define GL64_STAGE 40960                 // A 8KB + B 32KB
#define GL64_SMEM  (2 * GL64_STAGE)      // 81920

// Attention smem: Q,K,V fp16 256 rows x 80B stride
#define ATTN_ROWB  80
#define ATTN_SMEM  (3 * 256 * ATTN_ROWB)

// ---------------------------------------------------------------------------
// PTX helpers (sm_80-class only)
// ---------------------------------------------------------------------------
__device__ __forceinline__ uint32_t smem_u32(const void* p) {
    uint32_t a;
    asm("{ .reg .u64 t; cvta.to.shared.u64 t, %1; cvt.u32.u64 %0, t; }" : "=r"(a) : "l"(p));
    return a;
}
__device__ __forceinline__ void cp16(uint32_t dst, const void* src) {
    asm volatile("cp.async.cg.shared.global [%0], [%1], 16;" :: "r"(dst), "l"(src) : "memory");
}
#define CP_COMMIT() asm volatile("cp.async.commit_group;" ::: "memory")
#define CP_WAIT2()  asm volatile("cp.async.wait_group 2;" ::: "memory")
#define CP_WAIT1()  asm volatile("cp.async.wait_group 1;" ::: "memory")
#define CP_WAIT0()  asm volatile("cp.async.wait_group 0;" ::: "memory")

__device__ __forceinline__ void ldsm4(uint32_t& r0, uint32_t& r1, uint32_t& r2,
                                      uint32_t& r3, uint32_t addr) {
    asm volatile("ldmatrix.sync.aligned.m8n8.x4.shared.b16 {%0,%1,%2,%3}, [%4];"
                 : "=r"(r0), "=r"(r1), "=r"(r2), "=r"(r3) : "r"(addr));
}
__device__ __forceinline__ void ldsm4t(uint32_t& r0, uint32_t& r1, uint32_t& r2,
                                       uint32_t& r3, uint32_t addr) {
    asm volatile("ldmatrix.sync.aligned.m8n8.x4.trans.shared.b16 {%0,%1,%2,%3}, [%4];"
                 : "=r"(r0), "=r"(r1), "=r"(r2), "=r"(r3) : "r"(addr));
}
__device__ __forceinline__ void mma16816(float* c, const uint32_t* a, const uint32_t* b) {
    asm volatile(
        "mma.sync.aligned.m16n8k16.row.col.f32.f16.f16.f32 "
        "{%0,%1,%2,%3}, {%4,%5,%6,%7}, {%8,%9}, {%0,%1,%2,%3};"
        : "+f"(c[0]), "+f"(c[1]), "+f"(c[2]), "+f"(c[3])
        : "r"(a[0]), "r"(a[1]), "r"(a[2]), "r"(a[3]), "r"(b[0]), "r"(b[1]));
}
__device__ __forceinline__ uint32_t packh2(float a, float b) {
    __half2 h = __floats2half2_rn(a, b);
    return *(uint32_t*)&h;
}

// Row-level permutations (bijective)
__device__ __forceinline__ int fine_perm(int r) {      // o0-row -> fidx
    int fw = r >> 8, n = r & 255;
    int i = n >> 4, j = n & 15;
    return fw * 256 + ((i >> 2) * 4 + (j >> 2)) * 16 + ((i & 3) * 4 + (j & 3));
}
__device__ __forceinline__ int gather_perm(int r) {    // X1-row -> gidx
    int win = r >> 8, tok = r & 255;
    int b = win >> 2, gi = (win >> 1) & 1, gj = win & 1;
    int ti = tok >> 4, tj = tok & 15;
    int R = gi * 16 + ti, Cc = gj * 16 + tj;
    return ((b * 8 + (R >> 2)) * 8 + (Cc >> 2)) * 16 + (R & 3) * 4 + (Cc & 3);
}
__device__ __forceinline__ int scatter_perm(int g) {   // gidx -> o1-row
    int rr = g & 15, r1 = rr >> 2, r2 = rr & 3;
    int bhw = g >> 4;
    int w = bhw & 7, h = (bhw >> 3) & 7, b = bhw >> 6;
    int R = h * 4 + r1, Cc = w * 4 + r2;
    return (((b * 2 + (R >> 4)) * 2 + (Cc >> 4)) << 8) + (R & 15) * 16 + (Cc & 15);
}

// ---------------------------------------------------------------------------
// Scratch
// ---------------------------------------------------------------------------
__device__ float g_PE [2 * 256 * 256];
__device__ float g_X0 [(size_t)T0 * 256];
__device__ float g_X1 [(size_t)T1 * 256];
__device__ float g_G  [(size_t)T1 * 256];
__device__ float g_Qb [(size_t)T1 * 256];
__device__ __half g_QKVh[(size_t)T0 * 768];
__device__ __half g_A  [(size_t)T0 * 256];
__device__ __half g_Ac [(size_t)T1 * 256];
__device__ __half g_H1 [(size_t)T0 * 1024];
__device__ __half g_A3 [(size_t)T1 * 256];
__device__ __half g_WqkvT[2 * 768 * 256];
__device__ __half g_WoT  [2 * 256 * 256];
__device__ __half g_W1T  [2 * 1024 * 256];
__device__ __half g_W2T  [2 * 256 * 1024];

// ---------------------------------------------------------------------------
// LN helper (warp per token)
// ---------------------------------------------------------------------------
__device__ __forceinline__ void ln_warp_store(float4 v0, float4 v1, int lane,
                                              const float* __restrict__ gamma,
                                              const float* __restrict__ beta,
                                              __half* __restrict__ orow) {
    float s = v0.x + v0.y + v0.z + v0.w + v1.x + v1.y + v1.z + v1.w;
#pragma unroll
    for (int d = 16; d; d >>= 1) s += __shfl_xor_sync(0xffffffffu, s, d);
    float mean = s * (1.f / 256.f);
    float d0x = v0.x - mean, d0y = v0.y - mean, d0z = v0.z - mean, d0w = v0.w - mean;
    float d1x = v1.x - mean, d1y = v1.y - mean, d1z = v1.z - mean, d1w = v1.w - mean;
    float q = d0x*d0x + d0y*d0y + d0z*d0z + d0w*d0w +
              d1x*d1x + d1y*d1y + d1z*d1z + d1w*d1w;
#pragma unroll
    for (int d = 16; d; d >>= 1) q += __shfl_xor_sync(0xffffffffu, q, d);
    float rstd = rsqrtf(q * (1.f / 256.f) + 1e-5f);
    float4 g0 = ((const float4*)gamma)[lane], g1 = ((const float4*)gamma)[lane + 32];
    float4 b0 = ((const float4*)beta)[lane],  b1 = ((const float4*)beta)[lane + 32];
    uint2 o0, o1;
    o0.x = packh2(fmaf(d0x * rstd, g0.x, b0.x), fmaf(d0y * rstd, g0.y, b0.y));
    o0.y = packh2(fmaf(d0z * rstd, g0.z, b0.z), fmaf(d0w * rstd, g0.w, b0.w));
    o1.x = packh2(fmaf(d1x * rstd, g1.x, b1.x), fmaf(d1y * rstd, g1.y, b1.y));
    o1.y = packh2(fmaf(d1z * rstd, g1.z, b1.z), fmaf(d1w * rstd, g1.w, b1.w));
    uint2* ou = (uint2*)orow;
    ou[lane] = o0;
    ou[lane + 32] = o1;
}

// ---------------------------------------------------------------------------
// Small kernels
// ---------------------------------------------------------------------------
__global__ void posemb_kernel(const float* __restrict__ pe_w1,
                              const float* __restrict__ pe_b1,
                              const float* __restrict__ pe_w2,
                              float* __restrict__ PE) {
    int s = blockIdx.x >> 8;
    int n = blockIdx.x & 255;
    int i = n >> 4, j = n & 15;
    float cy = (i - 8) * 0.125f;
    float cx = (j - 8) * 0.125f;
    __shared__ float hid[512];
    const float* w1 = pe_w1 + s * 2 * 512;
    const float* b1 = pe_b1 + s * 512;
    for (int k = threadIdx.x; k < 512; k += 256)
        hid[k] = fmaxf(0.f, fmaf(cy, w1[k], fmaf(cx, w1[512 + k], b1[k])));
    __syncthreads();
    const float* w2 = pe_w2 + (size_t)s * 512 * 256;
    int c = threadIdx.x;
    float acc = 0.f;
#pragma unroll 8
    for (int k = 0; k < 512; k++) acc = fmaf(hid[k], w2[(size_t)k * 256 + c], acc);
    PE[((size_t)s * 256 + n) * 256 + c] = acc;
}

__global__ void __launch_bounds__(256)
add_pe0_ln_kernel(const float* __restrict__ s0, const float* __restrict__ PE,
                  float* __restrict__ X0, __half* __restrict__ A,
                  const float* __restrict__ gamma, const float* __restrict__ beta) {
    int token = blockIdx.x * 8 + (threadIdx.x >> 5);
    int lane = threadIdx.x & 31;
    const float4* sr = (const float4*)(s0 + (size_t)token * 256);
    const float4* pr = (const float4*)(PE + (size_t)(token & 255) * 256);
    float4 v0 = sr[lane], v1 = sr[lane + 32];
    float4 p0 = pr[lane], p1 = pr[lane + 32];
    v0.x += p0.x; v0.y += p0.y; v0.z += p0.z; v0.w += p0.w;
    v1.x += p1.x; v1.y += p1.y; v1.z += p1.z; v1.w += p1.w;
    float4* xr = (float4*)(X0 + (size_t)token * 256);
    xr[lane] = v0; xr[lane + 32] = v1;
    ln_warp_store(v0, v1, lane, gamma, beta, A + (size_t)token * 256);
}

__global__ void __launch_bounds__(256)
pool_add_ln_kernel(const float* __restrict__ s1, const float* __restrict__ PE,
                   const float* __restrict__ X0, float* __restrict__ X1,
                   __half* __restrict__ Ac,
                   const float* __restrict__ gamma, const float* __restrict__ beta) {
    int token = blockIdx.x * 8 + (threadIdx.x >> 5);
    int lane = threadIdx.x & 31;
    int t  = token & 255;
    int gw = token >> 8;
    int b = gw >> 2, gi = (gw >> 1) & 1, gj = gw & 1;
    int ti = t >> 4, tj = t & 15;
    int R  = gi * 16 + ti, Cc = gj * 16 + tj;
    int h = R >> 2, r1 = R & 3, w = Cc >> 2, r2 = Cc & 3;
    int fw = b * 64 + h * 8 + w;
    float4 m0 = make_float4(-1e30f, -1e30f, -1e30f, -1e30f), m1 = m0;
#pragma unroll
    for (int p1 = 0; p1 < 4; p1++)
#pragma unroll
        for (int p2 = 0; p2 < 4; p2++) {
            int n = (r1 * 4 + p1) * 16 + r2 * 4 + p2;
            const float4* row = (const float4*)(X0 + ((size_t)fw * 256 + n) * 256);
            float4 a = row[lane], c = row[lane + 32];
            m0.x = fmaxf(m0.x, a.x); m0.y = fmaxf(m0.y, a.y);
            m0.z = fmaxf(m0.z, a.z); m0.w = fmaxf(m0.w, a.w);
            m1.x = fmaxf(m1.x, c.x); m1.y = fmaxf(m1.y, c.y);
            m1.z = fmaxf(m1.z, c.z); m1.w = fmaxf(m1.w, c.w);
        }
    const float4* sr = (const float4*)(s1 + (size_t)token * 256);
    const float4* pr = (const float4*)(PE + (size_t)(256 + t) * 256);
    float4 s0v = sr[lane], s1v = sr[lane + 32];
    float4 p0 = pr[lane], p1v = pr[lane + 32];
    m0.x += s0v.x + p0.x; m0.y += s0v.y + p0.y;
    m0.z += s0v.z + p0.z; m0.w += s0v.w + p0.w;
    m1.x += s1v.x + p1v.x; m1.y += s1v.y + p1v.y;
    m1.z += s1v.z + p1v.z; m1.w += s1v.w + p1v.w;
    float4* xr = (float4*)(X1 + (size_t)token * 256);
    xr[lane] = m0; xr[lane + 32] = m1;
    ln_warp_store(m0, m1, lane, gamma, beta, Ac + (size_t)token * 256);
}

__global__ void wconv_all_kernel(const float* __restrict__ wqkv,
                                 const float* __restrict__ wo,
                                 const float* __restrict__ mw1,
                                 const float* __restrict__ mw2,
                                 __half* __restrict__ Tqkv, __half* __restrict__ To,
                                 __half* __restrict__ Tm1,  __half* __restrict__ Tm2) {
    int bid = blockIdx.x;
    int s = bid / 2304, r = bid % 2304;
    const float* W; __half* T; int K, N, n;
    if (r < 768)       { W = wqkv + (size_t)s * 196608; T = Tqkv + (size_t)s * 196608; K = 256;  N = 768;  n = r; }
    else if (r < 1024) { W = wo   + (size_t)s * 65536;  T = To   + (size_t)s * 65536;  K = 256;  N = 256;  n = r - 768; }
    else if (r < 2048) { W = mw1  + (size_t)s * 262144; T = Tm1  + (size_t)s * 262144; K = 256;  N = 1024; n = r - 1024; }
    else               { W = mw2  + (size_t)s * 262144; T = Tm2  + (size_t)s * 262144; K = 1024; N = 256;  n = r - 2048; }
    for (int k = threadIdx.x; k < K; k += 256)
        T[(size_t)n * K + k] = __float2half(W[(size_t)k * N + n]);
}

// ---------------------------------------------------------------------------
// fp16 1-pass GEMM, wide N (grid.x = N/128).  EPI 0: fp32. 1: GELU->fp16. 3: fp16.
// (round-8 passing config: 256 thr, 96KB 3-stage, 2 CTA/SM)
// ---------------------------------------------------------------------------
template <int EPI>
__global__ void __launch_bounds__(256)
gemm_mma(const __half* __restrict__ A, const __half* __restrict__ B,
         const float* __restrict__ bias,
         float* __restrict__ Cp, __half* __restrict__ Oh,
         int K, int ldc) {
    extern __shared__ char smc[];
    const uint32_t sb = smem_u32(smc);
    int tid = threadIdx.x, lane = tid & 31, wid = tid >> 5;
    int wm = wid >> 2, wn = wid & 3;
    int bm = blockIdx.y, bn = blockIdx.x;

    const __half* src0 = A + (size_t)bm * 128 * K;
    const __half* src1 = B + (size_t)bn * 128 * K;

    int nc = K >> 6;
    int crow0 = tid >> 3, ccol = tid & 7;

#define PREFETCH(CH, BUF) do {                                                 \
    int _k0 = (CH) << 6;                                                       \
    const __half* _s[2] = {src0 + _k0, src1 + _k0};                            \
    _Pragma("unroll")                                                          \
    for (int _op = 0; _op < 2; _op++) {                                        \
        uint32_t _db = sb + (BUF) * BUF_BYTES + _op * TILE_BYTES;              \
        _Pragma("unroll")                                                      \
        for (int _i = 0; _i < 4; _i++) {                                       \
            int _row = crow0 + _i * 32;                                        \
            uint32_t _doff = _db + _row * 128 + ((ccol ^ (_row & 7)) << 4);    \
            cp16(_doff, _s[_op] + (size_t)_row * K + ccol * 8);                \
        }                                                                      \
    }                                                                          \
} while (0)

    float acc[4][4][4];
#pragma unroll
    for (int mi = 0; mi < 4; mi++)
#pragma unroll
        for (int ni = 0; ni < 4; ni++)
#pragma unroll
            for (int r = 0; r < 4; r++) acc[mi][ni][r] = 0.f;

    PREFETCH(0, 0);
    CP_COMMIT();
    if (nc > 1) { PREFETCH(1, 1); CP_COMMIT(); }

    int a_rl = lane & 15;
    int b_rl = ((lane >> 4) << 3) + (lane & 7);

    for (int ch = 0; ch < nc; ch++) {
        int buf = ch % 3;
        if (ch + 2 < nc) {
            PREFETCH(ch + 2, (ch + 2) % 3);
            CP_COMMIT();
            CP_WAIT2();
        } else if (ch + 1 < nc) {
            CP_WAIT1();
        } else {
            CP_WAIT0();
        }
        __syncthreads();

        uint32_t base = sb + buf * BUF_BYTES;
#pragma unroll
        for (int ks = 0; ks < 4; ks++) {
            uint32_t ah[4][4], bh[4][2];
            int achunk = ks * 2 + (lane >> 4);
            int bchunk = ks * 2 + ((lane >> 3) & 1);
#pragma unroll
            for (int mi = 0; mi < 4; mi++) {
                int row = wm * 64 + mi * 16 + a_rl;
                uint32_t off = (uint32_t)(row * 128 + ((achunk ^ (row & 7)) << 4));
                ldsm4(ah[mi][0], ah[mi][1], ah[mi][2], ah[mi][3], base + off);
            }
#pragma unroll
            for (int np = 0; np < 2; np++) {
                int row = wn * 32 + np * 16 + b_rl;
                uint32_t off = (uint32_t)(row * 128 + ((bchunk ^ (row & 7)) << 4));
                uint32_t r0, r1, r2, r3;
                ldsm4(r0, r1, r2, r3, base + TILE_BYTES + off);
                bh[np * 2][0] = r0; bh[np * 2][1] = r1;
                bh[np * 2 + 1][0] = r2; bh[np * 2 + 1][1] = r3;
            }
#pragma unroll
            for (int mi = 0; mi < 4; mi++)
#pragma unroll
                for (int ni = 0; ni < 4; ni++)
                    mma16816(acc[mi][ni], ah[mi], bh[ni]);
        }
        __syncthreads();
    }
#undef PREFETCH

    int l4 = lane >> 2, l2 = (lane & 3) << 1;
#pragma unroll
    for (int mi = 0; mi < 4; mi++) {
        int r0 = bm * 128 + wm * 64 + mi * 16 + l4;
#pragma unroll
        for (int ni = 0; ni < 4; ni++) {
            int cc = bn * 128 + wn * 32 + ni * 8 + l2;
            float b0 = bias[cc], b1 = bias[cc + 1];
            float v00 = acc[mi][ni][0] + b0, v01 = acc[mi][ni][1] + b1;
            float v10 = acc[mi][ni][2] + b0, v11 = acc[mi][ni][3] + b1;
            size_t o0 = (size_t)r0 * ldc + cc;
            size_t o1 = (size_t)(r0 + 8) * ldc + cc;
            if (EPI == 1) {
                const float is2 = 0.7071067811865476f;
                float g00 = 0.5f * v00 * (1.f + erff(v00 * is2));
                float g01 = 0.5f * v01 * (1.f + erff(v01 * is2));
                float g10 = 0.5f * v10 * (1.f + erff(v10 * is2));
                float g11 = 0.5f * v11 * (1.f + erff(v11 * is2));
                *(uint32_t*)(Oh + o0) = packh2(g00, g01);
                *(uint32_t*)(Oh + o1) = packh2(g10, g11);
            } else if (EPI == 3) {
                *(uint32_t*)(Oh + o0) = packh2(v00, v01);
                *(uint32_t*)(Oh + o1) = packh2(v10, v11);
            } else {
                *(float2*)(Cp + o0) = make_float2(v00, v01);
                *(float2*)(Cp + o1) = make_float2(v10, v11);
            }
        }
    }
}

// ---------------------------------------------------------------------------
// gemm_ln64: N=256 GEMM, full row per CTA, residual + fused row-LN epilogue.
// 64x256 tile, 256 threads (8 warps, 2x4 of 32x64), BK=64, 2-stage, 80KB.
// MODE 0: Cp[r]=v, Oh[r]=LN(v)
// MODE 1: Cp[r]=v, Oh[fine_perm(r)]=LN(v)
// MODE 2: Cp[r]=v, Gc[gather_perm(r)]=v, Oh[gather_perm(r)]=LN(v)
// MODE 3: Cp[scatter_perm(r)]=v   (no LN)
// ---------------------------------------------------------------------------
template <int MODE>
__global__ void __launch_bounds__(256)
gemm_ln64(const __half* __restrict__ A, const __half* __restrict__ B,
          const float* __restrict__ bias, const float* __restrict__ res,
          float* __restrict__ Cp, float* __restrict__ Gc, __half* __restrict__ Oh,
          const float* __restrict__ gamma, const float* __restrict__ beta, int K) {
    extern __shared__ char smc[];
    const uint32_t sb = smem_u32(smc);
    int tid = threadIdx.x, lane = tid & 31, wid = tid >> 5;
    int wm = wid >> 2, wn = wid & 3;     // warp tile: rows wm*32, cols wn*64
    int bm = blockIdx.y;
    const __half* srcA = A + (size_t)bm * 64 * K;
    int nc = K >> 6;
    int crow0 = tid >> 3, ccol = tid & 7;

#define PF(CH, BUF) do {                                                       \
    int _k0 = (CH) << 6;                                                       \
    uint32_t _db = sb + (BUF) * GL64_STAGE;                                    \
    _Pragma("unroll")                                                          \
    for (int _i = 0; _i < 2; _i++) {                                           \
        int _row = crow0 + _i * 32;                                            \
        cp16(_db + _row * 128 + ((ccol ^ (_row & 7)) << 4),                    \
             srcA + (size_t)_row * K + _k0 + ccol * 8);                        \
    }                                                                          \
    _Pragma("unroll")                                                          \
    for (int _i = 0; _i < 8; _i++) {                                           \
        int _row = crow0 + _i * 32;                                            \
        cp16(_db + 8192 + _row * 128 + ((ccol ^ (_row & 7)) << 4),             \
             B + (size_t)_row * K + _k0 + ccol * 8);                           \
    }                                                                          \
} while (0)

    float acc[2][8][4];
#pragma unroll
    for (int mi = 0; mi < 2; mi++)
#pragma unroll
        for (int ni = 0; ni < 8; ni++)
#pragma unroll
            for (int r = 0; r < 4; r++) acc[mi][ni][r] = 0.f;

    PF(0, 0);
    CP_COMMIT();

    int a_rl = lane & 15;
    int b_rl = ((lane >> 4) << 3) + (lane & 7);

    for (int ch = 0; ch < nc; ch++) {
        if (ch + 1 < nc) {
            PF(ch + 1, (ch + 1) & 1);
            CP_COMMIT();
            CP_WAIT1();
        } else {
            CP_WAIT0();
        }
        __syncthreads();
        uint32_t base = sb + (ch & 1) * GL64_STAGE;
#pragma unroll
        for (int ks = 0; ks < 4; ks++) {
            uint32_t ah[2][4], bh[8][2];
            int achunk = ks * 2 + (lane >> 4);
            int bchunk = ks * 2 + ((lane >> 3) & 1);
#pragma unroll
            for (int mi = 0; mi < 2; mi++) {
                int row = wm * 32 + mi * 16 + a_rl;
                uint32_t off = (uint32_t)(row * 128 + ((achunk ^ (row & 7)) << 4));
                ldsm4(ah[mi][0], ah[mi][1], ah[mi][2], ah[mi][3], base + off);
            }
#pragma unroll
            for (int np = 0; np < 4; np++) {
                int row = wn * 64 + np * 16 + b_rl;
                uint32_t off = (uint32_t)(row * 128 + ((bchunk ^ (row & 7)) << 4));
                uint32_t r0, r1, r2, r3;
                ldsm4(r0, r1, r2, r3, base + 8192 + off);
                bh[np * 2][0] = r0; bh[np * 2][1] = r1;
                bh[np * 2 + 1][0] = r2; bh[np * 2 + 1][1] = r3;
            }
#pragma unroll
            for (int mi = 0; mi < 2; mi++)
#pragma unroll
                for (int ni = 0; ni < 8; ni++)
                    mma16816(acc[mi][ni], ah[mi], bh[ni]);
        }
        __syncthreads();
    }
#undef PF

    // --- Epilogue: bias + residual, main writes, fused row LN ---
    int l4 = lane >> 2, l2 = (lane & 3) << 1;
    float* red = (float*)smc;  // [64][8]: (sum, sq) per (row, wn)

#pragma unroll
    for (int mi = 0; mi < 2; mi++)
#pragma unroll
        for (int h = 0; h < 2; h++) {
            int lrow = wm * 32 + mi * 16 + h * 8 + l4;
            int grow = bm * 64 + lrow;
            size_t rbase = (size_t)grow * 256;
            float s = 0.f, q = 0.f;
#pragma unroll
            for (int ni = 0; ni < 8; ni++) {
                int cc = wn * 64 + ni * 8 + l2;
                float2 bv = *(const float2*)(bias + cc);
                float2 rv = *(const float2*)(res + rbase + cc);
                float v0 = acc[mi][ni][h * 2]     + bv.x + rv.x;
                float v1 = acc[mi][ni][h * 2 + 1] + bv.y + rv.y;
                acc[mi][ni][h * 2]     = v0;
                acc[mi][ni][h * 2 + 1] = v1;
                s += v0 + v1;
                q += v0 * v0 + v1 * v1;
            }
            if (MODE == 3) {
                size_t ob = (size_t)scatter_perm(grow) * 256;
#pragma unroll
                for (int ni = 0; ni < 8; ni++) {
                    int cc = wn * 64 + ni * 8 + l2;
                    *(float2*)(Cp + ob + cc) =
                        make_float2(acc[mi][ni][h * 2], acc[mi][ni][h * 2 + 1]);
                }
            } else {
#pragma unroll
                for (int ni = 0; ni < 8; ni++) {
                    int cc = wn * 64 + ni * 8 + l2;
                    *(float2*)(Cp + rbase + cc) =
                        make_float2(acc[mi][ni][h * 2], acc[mi][ni][h * 2 + 1]);
                }
                if (MODE == 2) {
                    size_t gb = (size_t)gather_perm(grow) * 256;
#pragma unroll
                    for (int ni = 0; ni < 8; ni++) {
                        int cc = wn * 64 + ni * 8 + l2;
                        *(float2*)(Gc + gb + cc) =
                            make_float2(acc[mi][ni][h * 2], acc[mi][ni][h * 2 + 1]);
                    }
                }
                s += __shfl_xor_sync(0xffffffffu, s, 1);
                s += __shfl_xor_sync(0xffffffffu, s, 2);
                q += __shfl_xor_sync(0xffffffffu, q, 1);
                q += __shfl_xor_sync(0xffffffffu, q, 2);
                if ((lane & 3) == 0) {
                    red[lrow * 8 + wn * 2]     = s;
                    red[lrow * 8 + wn * 2 + 1] = q;
                }
            }
        }

    if (MODE != 3) {
        __syncthreads();
#pragma unroll
        for (int mi = 0; mi < 2; mi++)
#pragma unroll
            for (int h = 0; h < 2; h++) {
                int lrow = wm * 32 + mi * 16 + h * 8 + l4;
                int grow = bm * 64 + lrow;
                float ssum = red[lrow * 8 + 0] + red[lrow * 8 + 2] +
                             red[lrow * 8 + 4] + red[lrow * 8 + 6];
                float qsum = red[lrow * 8 + 1] + red[lrow * 8 + 3] +
                             red[lrow * 8 + 5] + red[lrow * 8 + 7];
                float mean = ssum * (1.f / 256.f);
                float var = qsum * (1.f / 256.f) - mean * mean;
                float rstd = rsqrtf(var + 1e-5f);
                int prow = (MODE == 0) ? grow
                         : (MODE == 1) ? fine_perm(grow) : gather_perm(grow);
                size_t ob = (size_t)prow * 256;
#pragma unroll
                for (int ni = 0; ni < 8; ni++) {
                    int cc = wn * 64 + ni * 8 + l2;
                    float2 gv = *(const float2*)(gamma + cc);
                    float2 bv = *(const float2*)(beta + cc);
                    float a0 = (acc[mi][ni][h * 2]     - mean) * rstd * gv.x + bv.x;
                    float a1 = (acc[mi][ni][h * 2 + 1] - mean) * rstd * gv.y + bv.y;
                    *(uint32_t*)(Oh + ob + cc) = packh2(a0, a1);
                }
            }
    }
}

// ---------------------------------------------------------------------------
// Tensor-core flash attention, no-max single-pass softmax.
// ---------------------------------------------------------------------------
__global__ void __launch_bounds__(256)
attn_mma_kernel(const __half* __restrict__ qkv, __half* __restrict__ out) {
    extern __shared__ char smc[];
    const uint32_t sb = smem_u32(smc);
    const uint32_t sbQ = sb, sbK = sb + 256 * ATTN_ROWB, sbV = sb + 512 * ATTN_ROWB;
    int win = blockIdx.x >> 3, head = blockIdx.x & 7;
    int tid = threadIdx.x, lane = tid & 31, wid = tid >> 5;

    {
        const uint4* src = (const uint4*)(qkv + ((size_t)(win * 256 + tid) * 768 + head * 32));
        uint4* dq = (uint4*)(smc + tid * ATTN_ROWB);
        uint4* dk = (uint4*)(smc + 256 * ATTN_ROWB + tid * ATTN_ROWB);
        uint4* dv = (uint4*)(smc + 512 * ATTN_ROWB + tid * ATTN_ROWB);
#pragma unroll
        for (int c = 0; c < 4; c++) dq[c] = src[c];
#pragma unroll
        for (int c = 0; c < 4; c++) dk[c] = src[32 + c];
#pragma unroll
        for (int c = 0; c < 4; c++) dv[c] = src[64 + c];
    }
    __syncthreads();

    uint32_t aq[2][2][4];
#pragma unroll
    for (int mi = 0; mi < 2; mi++)
#pragma unroll
        for (int kt = 0; kt < 2; kt++) {
            int row = wid * 32 + mi * 16 + (lane & 15);
            uint32_t addr = sbQ + row * ATTN_ROWB + (kt * 2 + (lane >> 4)) * 16;
            ldsm4(aq[mi][kt][0], aq[mi][kt][1], aq[mi][kt][2], aq[mi][kt][3], addr);
        }

    float o[2][4][4];
#pragma unroll
    for (int mi = 0; mi < 2; mi++)
#pragma unroll
        for (int ni = 0; ni < 4; ni++)
#pragma unroll
            for (int r = 0; r < 4; r++) o[mi][ni][r] = 0.f;
    float l[2][2] = {{0.f, 0.f}, {0.f, 0.f}};
    const float sc = 0.17677669529663687f * 1.4426950408889634f;

    for (int kc = 0; kc < 4; kc++) {
        float s[2][8][4];
#pragma unroll
        for (int mi = 0; mi < 2; mi++)
#pragma unroll
            for (int ni = 0; ni < 8; ni++)
#pragma unroll
                for (int r = 0; r < 4; r++) s[mi][ni][r] = 0.f;

#pragma unroll
        for (int nt = 0; nt < 4; nt++) {
            int keyrow = kc * 64 + nt * 16 + (lane & 15);
#pragma unroll
            for (int kt = 0; kt < 2; kt++) {
                uint32_t addr = sbK + keyrow * ATTN_ROWB + (kt * 2 + (lane >> 4)) * 16;
                uint32_t r0, r1, r2, r3;
                ldsm4(r0, r1, r2, r3, addr);
                uint32_t blo[2] = {r0, r2}, bhi[2] = {r1, r3};
#pragma unroll
                for (int mi = 0; mi < 2; mi++) {
                    mma16816(s[mi][nt * 2],     aq[mi][kt], blo);
                    mma16816(s[mi][nt * 2 + 1], aq[mi][kt], bhi);
                }
            }
        }

#pragma unroll
        for (int mi = 0; mi < 2; mi++)
#pragma unroll
            for (int ni = 0; ni < 8; ni++) {
                float p0 = exp2f(s[mi][ni][0] * sc);
                float p1 = exp2f(s[mi][ni][1] * sc);
                float p2 = exp2f(s[mi][ni][2] * sc);
                float p3 = exp2f(s[mi][ni][3] * sc);
                s[mi][ni][0] = p0; s[mi][ni][1] = p1;
                s[mi][ni][2] = p2; s[mi][ni][3] = p3;
                l[mi][0] += p0 + p1;
                l[mi][1] += p2 + p3;
            }

        uint32_t pa[2][4][4];
#pragma unroll
        for (int mi = 0; mi < 2; mi++)
#pragma unroll
            for (int kt = 0; kt < 4; kt++) {
                pa[mi][kt][0] = packh2(s[mi][kt * 2][0], s[mi][kt * 2][1]);
                pa[mi][kt][1] = packh2(s[mi][kt * 2][2], s[mi][kt * 2][3]);
                pa[mi][kt][2] = packh2(s[mi][kt * 2 + 1][0], s[mi][kt * 2 + 1][1]);
                pa[mi][kt][3] = packh2(s[mi][kt * 2 + 1][2], s[mi][kt * 2 + 1][3]);
            }

#pragma unroll
        for (int kt = 0; kt < 4; kt++) {
            int keyrow = kc * 64 + kt * 16 + (lane & 15);
#pragma unroll
            for (int dc = 0; dc < 2; dc++) {
                uint32_t addr = sbV + keyrow * ATTN_ROWB + (dc * 2 + (lane >> 4)) * 16;
                uint32_t r0, r1, r2, r3;
                ldsm4t(r0, r1, r2, r3, addr);
                uint32_t b0[2] = {r0, r1}, b1[2] = {r2, r3};
#pragma unroll
                for (int mi = 0; mi < 2; mi++) {
                    mma16816(o[mi][dc * 2],     pa[mi][kt], b0);
                    mma16816(o[mi][dc * 2 + 1], pa[mi][kt], b1);
                }
            }
        }
    }

#pragma unroll
    for (int mi = 0; mi < 2; mi++)
#pragma unroll
        for (int h = 0; h < 2; h++) {
            float v = l[mi][h];
            v += __shfl_xor_sync(0xffffffffu, v, 1);
            v += __shfl_xor_sync(0xffffffffu, v, 2);
            l[mi][h] = v;
        }

    int l4 = lane >> 2, l2 = (lane & 3) << 1;
#pragma unroll
    for (int mi = 0; mi < 2; mi++)
#pragma unroll
        for (int h = 0; h < 2; h++) {
            float inv = 1.f / l[mi][h];
            int row = wid * 32 + mi * 16 + l4 + h * 8;
            size_t ob = ((size_t)(win * 256 + row)) * 256 + head * 32;
#pragma unroll
            for (int ni = 0; ni < 4; ni++) {
                *(uint32_t*)(out + ob + ni * 8 + l2) =
                    packh2(o[mi][ni][h * 2] * inv, o[mi][ni][h * 2 + 1] * inv);
            }
        }
}

// ---------------------------------------------------------------------------
// Cross attention: 1 query x 16 keys, warp per head
// ---------------------------------------------------------------------------
__global__ void __launch_bounds__(256)
cross_attn_kernel(const float* __restrict__ Q, const __half* __restrict__ KV,
                  __half* __restrict__ oh) {
    int g = blockIdx.x;
    int head = threadIdx.x >> 5, lane = threadIdx.x & 31;
    float qd = Q[(size_t)g * 256 + head * 32 + lane];
    size_t kvbase = (size_t)g * 16 * 512 + head * 32 + lane;
    const float sc = 0.17677669529663687f * 1.4426950408889634f;
    float s[16];
#pragma unroll
    for (int j = 0; j < 16; j++) {
        float p = qd * __half2float(KV[kvbase + (size_t)j * 512]);
#pragma unroll
        for (int o = 16; o; o >>= 1) p += __shfl_xor_sync(0xffffffffu, p, o);
        s[j] = p * sc;
    }
    float l = 0.f;
#pragma unroll
    for (int j = 0; j < 16; j++) { s[j] = exp2f(s[j]); l += s[j]; }
    float inv = 1.f / l, acc = 0.f;
#pragma unroll
    for (int j = 0; j < 16; j++)
        acc = fmaf(s[j], __half2float(KV[kvbase + 256 + (size_t)j * 512]), acc);
    oh[(size_t)g * 256 + head * 32 + lane] = __float2half(acc * inv);
}

// ---------------------------------------------------------------------------
// Host launch
// ---------------------------------------------------------------------------
extern "C" void kernel_launch(void* const* d_in, const int* in_sizes, int n_in,
                              void* d_out, int out_size) {
    const float* scale0 = (const float*)d_in[0];
    const float* scale1 = (const float*)d_in[1];
    const float* pe_w1  = (const float*)d_in[2];
    const float* pe_b1  = (const float*)d_in[3];
    const float* pe_w2  = (const float*)d_in[4];
    const float* ln1_g  = (const float*)d_in[5];
    const float* ln1_b  = (const float*)d_in[6];
    const float* wqkv   = (const float*)d_in[7];
    const float* bqkv   = (const float*)d_in[8];
    const float* wo     = (const float*)d_in[9];
    const float* bo     = (const float*)d_in[10];
    const float* ln2_g  = (const float*)d_in[11];
    const float* ln2_b  = (const float*)d_in[12];
    const float* mw1    = (const float*)d_in[13];
    const float* mb1    = (const float*)d_in[14];
    const float* mw2    = (const float*)d_in[15];
    const float* mb2    = (const float*)d_in[16];
    float* out = (float*)d_out;

    float *PE, *X0, *X1, *G, *Qb;
    __half *QKVh, *A, *Ac, *H1, *A3;
    __half *WqkvT, *WoT, *W1T, *W2T;
    cudaGetSymbolAddress((void**)&PE,   g_PE);
    cudaGetSymbolAddress((void**)&X0,   g_X0);
    cudaGetSymbolAddress((void**)&X1,   g_X1);
    cudaGetSymbolAddress((void**)&G,    g_G);
    cudaGetSymbolAddress((void**)&Qb,   g_Qb);
    cudaGetSymbolAddress((void**)&QKVh, g_QKVh);
    cudaGetSymbolAddress((void**)&A,    g_A);
    cudaGetSymbolAddress((void**)&Ac,   g_Ac);
    cudaGetSymbolAddress((void**)&H1,   g_H1);
    cudaGetSymbolAddress((void**)&A3,   g_A3);
    cudaGetSymbolAddress((void**)&WqkvT, g_WqkvT);
    cudaGetSymbolAddress((void**)&WoT,   g_WoT);
    cudaGetSymbolAddress((void**)&W1T,   g_W1T);
    cudaGetSymbolAddress((void**)&W2T,   g_W2T);

    cudaFuncSetAttribute(attn_mma_kernel, cudaFuncAttributeMaxDynamicSharedMemorySize, ATTN_SMEM);
    cudaFuncSetAttribute(gemm_mma<0>, cudaFuncAttributeMaxDynamicSharedMemorySize, GEMM_SMEM);
    cudaFuncSetAttribute(gemm_mma<1>, cudaFuncAttributeMaxDynamicSharedMemorySize, GEMM_SMEM);
    cudaFuncSetAttribute(gemm_mma<3>, cudaFuncAttributeMaxDynamicSharedMemorySize, GEMM_SMEM);
    cudaFuncSetAttribute(gemm_ln64<0>, cudaFuncAttributeMaxDynamicSharedMemorySize, GL64_SMEM);
    cudaFuncSetAttribute(gemm_ln64<1>, cudaFuncAttributeMaxDynamicSharedMemorySize, GL64_SMEM);
    cudaFuncSetAttribute(gemm_ln64<2>, cudaFuncAttributeMaxDynamicSharedMemorySize, GL64_SMEM);
    cudaFuncSetAttribute(gemm_ln64<3>, cudaFuncAttributeMaxDynamicSharedMemorySize, GL64_SMEM);

    // 0) weights + position embeddings
    wconv_all_kernel<<<4608, 256>>>(wqkv, wo, mw1, mw2, WqkvT, WoT, W1T, W2T);
    posemb_kernel<<<512, 256>>>(pe_w1, pe_b1, pe_w2, PE);

    // 1) inputs with fused LN1
    add_pe0_ln_kernel<<<T0 / 8, 256>>>(scale0, PE, X0, A, ln1_g, ln1_b);
    pool_add_ln_kernel<<<T1 / 8, 256>>>(scale1, PE, X0, X1, Ac,
                                        ln1_g + 256, ln1_b + 256);

    // 2a) coarse self-attention block (s=1)
    gemm_mma<3><<<dim3(6, 32), 256, GEMM_SMEM>>>(
        Ac, WqkvT + 196608, bqkv + 768, nullptr, QKVh, 256, 768);
    attn_mma_kernel<<<NWIN1 * 8, 256, ATTN_SMEM>>>(QKVh, Ac);
    gemm_ln64<0><<<dim3(1, 64), 256, GL64_SMEM>>>(
        Ac, WoT + 65536, bo + 256, X1, X1, nullptr, Ac,
        ln2_g + 256, ln2_b + 256, 256);
    gemm_mma<1><<<dim3(8, 32), 256, GEMM_SMEM>>>(
        Ac, W1T + 262144, mb1 + 1024, nullptr, H1, 256, 1024);
    gemm_ln64<2><<<dim3(1, 64), 256, GL64_SMEM>>>(
        H1, W2T + 262144, mb2 + 256, X1, X1, G, A3,
        ln1_g + 256, ln1_b + 256, 1024);   // X1 final; G = gathered copy; A3 = LN1[1]

    // 2b) fine self-attention block (s=0)
    gemm_mma<3><<<dim3(6, 512), 256, GEMM_SMEM>>>(
        A, WqkvT, bqkv, nullptr, QKVh, 256, 768);
    attn_mma_kernel<<<NWIN0 * 8, 256, ATTN_SMEM>>>(QKVh, A);
    gemm_ln64<0><<<dim3(1, 1024), 256, GL64_SMEM>>>(
        A, WoT, bo, X0, X0, nullptr, A, ln2_g, ln2_b, 256);
    gemm_mma<1><<<dim3(8, 512), 256, GEMM_SMEM>>>(
        A, W1T, mb1, nullptr, H1, 256, 1024);
    gemm_ln64<1><<<dim3(1, 1024), 256, GL64_SMEM>>>(
        H1, W2T, mb2, X0, out, nullptr, A,
        ln1_g + 256, ln1_b + 256, 1024);   // out = o0; A = LN1[1](fine-perm) for cross KV

    // 3) one2one cross-attention aggregation (scale-1 weights)
    gemm_mma<0><<<dim3(2, 32), 256, GEMM_SMEM>>>(
        A3, WqkvT + 196608, bqkv + 768, Qb, nullptr, 256, 256);
    gemm_mma<3><<<dim3(4, 512), 256, GEMM_SMEM>>>(
        A, WqkvT + 196608 + 65536, bqkv + 768 + 256, nullptr, QKVh, 256, 512);
    cross_attn_kernel<<<T1, 256>>>(Qb, QKVh, A3);
    gemm_ln64<0><<<dim3(1, 64), 256, GL64_SMEM>>>(
        A3, WoT + 65536, bo + 256, G, G, nullptr, A3,
        ln2_g + 256, ln2_b + 256, 256);
    gemm_mma<1><<<dim3(8, 32), 256, GEMM_SMEM>>>(
        A3, W1T + 262144, mb1 + 1024, nullptr, H1, 256, 1024);
    gemm_ln64<3><<<dim3(1, 64), 256, GL64_SMEM>>>(
        H1, W2T + 262144, mb2 + 256, G, out + (size_t)NWIN0 * 256 * 256,
        nullptr, nullptr, nullptr, nullptr, 1024);
}

// round 11
// speedup vs baseline: 1.0965x; 1.0518x over previous
#include <cuda_runtime.h>
#include <cuda_fp16.h>
#include <cstdint>
#include <cstddef>

// ---------------------------------------------------------------------------
// Dimensions: B=4, H=W=8, M=16, C=256, NH=8, HD=32, GW=2
// ---------------------------------------------------------------------------
#define T0      65536
#define T1      4096
#define NWIN0   256
#define NWIN1   16

// gemm config (round-8 passing): 128x128 tile, BK=64, 3-stage, 2 tiles, 256 thr
#define TILE_BYTES 16384
#define BUF_BYTES  (2 * TILE_BYTES)
#define GEMM_SMEM  (3 * BUF_BYTES)

// Attention smem: Q,K,V fp16 256 rows x 80B stride
#define ATTN_ROWB  80
#define ATTN_SMEM  (3 * 256 * ATTN_ROWB)

// ---------------------------------------------------------------------------
// PTX helpers (sm_80-class only)
// ---------------------------------------------------------------------------
__device__ __forceinline__ uint32_t smem_u32(const void* p) {
    uint32_t a;
    asm("{ .reg .u64 t; cvta.to.shared.u64 t, %1; cvt.u32.u64 %0, t; }" : "=r"(a) : "l"(p));
    return a;
}
__device__ __forceinline__ void cp16(uint32_t dst, const void* src) {
    asm volatile("cp.async.cg.shared.global [%0], [%1], 16;" :: "r"(dst), "l"(src) : "memory");
}
#define CP_COMMIT() asm volatile("cp.async.commit_group;" ::: "memory")
#define CP_WAIT2()  asm volatile("cp.async.wait_group 2;" ::: "memory")
#define CP_WAIT1()  asm volatile("cp.async.wait_group 1;" ::: "memory")
#define CP_WAIT0()  asm volatile("cp.async.wait_group 0;" ::: "memory")

__device__ __forceinline__ void ldsm4(uint32_t& r0, uint32_t& r1, uint32_t& r2,
                                      uint32_t& r3, uint32_t addr) {
    asm volatile("ldmatrix.sync.aligned.m8n8.x4.shared.b16 {%0,%1,%2,%3}, [%4];"
                 : "=r"(r0), "=r"(r1), "=r"(r2), "=r"(r3) : "r"(addr));
}
__device__ __forceinline__ void ldsm4t(uint32_t& r0, uint32_t& r1, uint32_t& r2,
                                       uint32_t& r3, uint32_t addr) {
    asm volatile("ldmatrix.sync.aligned.m8n8.x4.trans.shared.b16 {%0,%1,%2,%3}, [%4];"
                 : "=r"(r0), "=r"(r1), "=r"(r2), "=r"(r3) : "r"(addr));
}
__device__ __forceinline__ void mma16816(float* c, const uint32_t* a, const uint32_t* b) {
    asm volatile(
        "mma.sync.aligned.m16n8k16.row.col.f32.f16.f16.f32 "
        "{%0,%1,%2,%3}, {%4,%5,%6,%7}, {%8,%9}, {%0,%1,%2,%3};"
        : "+f"(c[0]), "+f"(c[1]), "+f"(c[2]), "+f"(c[3])
        : "r"(a[0]), "r"(a[1]), "r"(a[2]), "r"(a[3]), "r"(b[0]), "r"(b[1]));
}
__device__ __forceinline__ uint32_t packh2(float a, float b) {
    __half2 h = __floats2half2_rn(a, b);
    return *(uint32_t*)&h;
}

// ---------------------------------------------------------------------------
// Scratch
// ---------------------------------------------------------------------------
__device__ float g_PE [2 * 256 * 256];
__device__ float g_X0 [(size_t)T0 * 256];
__device__ float g_X1 [(size_t)T1 * 256];
__device__ float g_G  [(size_t)T1 * 256];
__device__ float g_Qb [(size_t)T1 * 256];
__device__ __half g_QKVh[(size_t)T0 * 768];
__device__ __half g_QKVc[(size_t)T1 * 768];   // coarse-private QKV
__device__ __half g_A  [(size_t)T0 * 256];
__device__ __half g_Ac [(size_t)T1 * 256];
__device__ __half g_H1 [(size_t)T0 * 1024];
__device__ __half g_H1c[(size_t)T1 * 1024];   // coarse-private MLP hidden
__device__ __half g_A3 [(size_t)T1 * 256];
__device__ __half g_WqkvT[2 * 768 * 256];
__device__ __half g_WoT  [2 * 256 * 256];
__device__ __half g_W1T  [2 * 1024 * 256];
__device__ __half g_W2T  [2 * 256 * 1024];

// ---------------------------------------------------------------------------
// LN helper (warp per token)
// ---------------------------------------------------------------------------
__device__ __forceinline__ void ln_warp_store(float4 v0, float4 v1, int lane,
                                              const float* __restrict__ gamma,
                                              const float* __restrict__ beta,
                                              __half* __restrict__ orow) {
    float s = v0.x + v0.y + v0.z + v0.w + v1.x + v1.y + v1.z + v1.w;
#pragma unroll
    for (int d = 16; d; d >>= 1) s += __shfl_xor_sync(0xffffffffu, s, d);
    float mean = s * (1.f / 256.f);
    float d0x = v0.x - mean, d0y = v0.y - mean, d0z = v0.z - mean, d0w = v0.w - mean;
    float d1x = v1.x - mean, d1y = v1.y - mean, d1z = v1.z - mean, d1w = v1.w - mean;
    float q = d0x*d0x + d0y*d0y + d0z*d0z + d0w*d0w +
              d1x*d1x + d1y*d1y + d1z*d1z + d1w*d1w;
#pragma unroll
    for (int d = 16; d; d >>= 1) q += __shfl_xor_sync(0xffffffffu, q, d);
    float rstd = rsqrtf(q * (1.f / 256.f) + 1e-5f);
    float4 g0 = ((const float4*)gamma)[lane], g1 = ((const float4*)gamma)[lane + 32];
    float4 b0 = ((const float4*)beta)[lane],  b1 = ((const float4*)beta)[lane + 32];
    uint2 o0, o1;
    o0.x = packh2(fmaf(d0x * rstd, g0.x, b0.x), fmaf(d0y * rstd, g0.y, b0.y));
    o0.y = packh2(fmaf(d0z * rstd, g0.z, b0.z), fmaf(d0w * rstd, g0.w, b0.w));
    o1.x = packh2(fmaf(d1x * rstd, g1.x, b1.x), fmaf(d1y * rstd, g1.y, b1.y));
    o1.y = packh2(fmaf(d1z * rstd, g1.z, b1.z), fmaf(d1w * rstd, g1.w, b1.w));
    uint2* ou = (uint2*)orow;
    ou[lane] = o0;
    ou[lane + 32] = o1;
}

// ---------------------------------------------------------------------------
// Small kernels
// ---------------------------------------------------------------------------
__global__ void posemb_kernel(const float* __restrict__ pe_w1,
                              const float* __restrict__ pe_b1,
                              const float* __restrict__ pe_w2,
                              float* __restrict__ PE) {
    int s = blockIdx.x >> 8;
    int n = blockIdx.x & 255;
    int i = n >> 4, j = n & 15;
    float cy = (i - 8) * 0.125f;
    float cx = (j - 8) * 0.125f;
    __shared__ float hid[512];
    const float* w1 = pe_w1 + s * 2 * 512;
    const float* b1 = pe_b1 + s * 512;
    for (int k = threadIdx.x; k < 512; k += 256)
        hid[k] = fmaxf(0.f, fmaf(cy, w1[k], fmaf(cx, w1[512 + k], b1[k])));
    __syncthreads();
    const float* w2 = pe_w2 + (size_t)s * 512 * 256;
    int c = threadIdx.x;
    float acc = 0.f;
#pragma unroll 8
    for (int k = 0; k < 512; k++) acc = fmaf(hid[k], w2[(size_t)k * 256 + c], acc);
    PE[((size_t)s * 256 + n) * 256 + c] = acc;
}

__global__ void __launch_bounds__(256)
add_pe0_ln_kernel(const float* __restrict__ s0, const float* __restrict__ PE,
                  float* __restrict__ X0, __half* __restrict__ A,
                  const float* __restrict__ gamma, const float* __restrict__ beta) {
    int token = blockIdx.x * 8 + (threadIdx.x >> 5);
    int lane = threadIdx.x & 31;
    const float4* sr = (const float4*)(s0 + (size_t)token * 256);
    const float4* pr = (const float4*)(PE + (size_t)(token & 255) * 256);
    float4 v0 = sr[lane], v1 = sr[lane + 32];
    float4 p0 = pr[lane], p1 = pr[lane + 32];
    v0.x += p0.x; v0.y += p0.y; v0.z += p0.z; v0.w += p0.w;
    v1.x += p1.x; v1.y += p1.y; v1.z += p1.z; v1.w += p1.w;
    float4* xr = (float4*)(X0 + (size_t)token * 256);
    xr[lane] = v0; xr[lane + 32] = v1;
    ln_warp_store(v0, v1, lane, gamma, beta, A + (size_t)token * 256);
}

__global__ void __launch_bounds__(256)
pool_add_ln_kernel(const float* __restrict__ s1, const float* __restrict__ PE,
                   const float* __restrict__ X0, float* __restrict__ X1,
                   __half* __restrict__ Ac,
                   const float* __restrict__ gamma, const float* __restrict__ beta) {
    int token = blockIdx.x * 8 + (threadIdx.x >> 5);
    int lane = threadIdx.x & 31;
    int t  = token & 255;
    int gw = token >> 8;
    int b = gw >> 2, gi = (gw >> 1) & 1, gj = gw & 1;
    int ti = t >> 4, tj = t & 15;
    int R  = gi * 16 + ti, Cc = gj * 16 + tj;
    int h = R >> 2, r1 = R & 3, w = Cc >> 2, r2 = Cc & 3;
    int fw = b * 64 + h * 8 + w;
    float4 m0 = make_float4(-1e30f, -1e30f, -1e30f, -1e30f), m1 = m0;
#pragma unroll
    for (int p1 = 0; p1 < 4; p1++)
#pragma unroll
        for (int p2 = 0; p2 < 4; p2++) {
            int n = (r1 * 4 + p1) * 16 + r2 * 4 + p2;
            const float4* row = (const float4*)(X0 + ((size_t)fw * 256 + n) * 256);
            float4 a = row[lane], c = row[lane + 32];
            m0.x = fmaxf(m0.x, a.x); m0.y = fmaxf(m0.y, a.y);
            m0.z = fmaxf(m0.z, a.z); m0.w = fmaxf(m0.w, a.w);
            m1.x = fmaxf(m1.x, c.x); m1.y = fmaxf(m1.y, c.y);
            m1.z = fmaxf(m1.z, c.z); m1.w = fmaxf(m1.w, c.w);
        }
    const float4* sr = (const float4*)(s1 + (size_t)token * 256);
    const float4* pr = (const float4*)(PE + (size_t)(256 + t) * 256);
    float4 s0v = sr[lane], s1v = sr[lane + 32];
    float4 p0 = pr[lane], p1v = pr[lane + 32];
    m0.x += s0v.x + p0.x; m0.y += s0v.y + p0.y;
    m0.z += s0v.z + p0.z; m0.w += s0v.w + p0.w;
    m1.x += s1v.x + p1v.x; m1.y += s1v.y + p1v.y;
    m1.z += s1v.z + p1v.z; m1.w += s1v.w + p1v.w;
    float4* xr = (float4*)(X1 + (size_t)token * 256);
    xr[lane] = m0; xr[lane + 32] = m1;
    ln_warp_store(m0, m1, lane, gamma, beta, Ac + (size_t)token * 256);
}

// Combined LayerNorm: blocks < split do problem 1, rest problem 2.
__global__ void __launch_bounds__(256)
ln_half_kernel(const float* __restrict__ x, __half* __restrict__ o,
               const float* __restrict__ gamma, const float* __restrict__ beta,
               const float* __restrict__ x2, __half* __restrict__ o2,
               const float* __restrict__ gamma2, const float* __restrict__ beta2,
               int split) {
    int blk = blockIdx.x;
    const float* xp = x; __half* op = o;
    const float* gp = gamma; const float* bp = beta;
    if (blk >= split) { blk -= split; xp = x2; op = o2; gp = gamma2; bp = beta2; }
    int token = blk * 8 + (threadIdx.x >> 5);
    int lane = threadIdx.x & 31;
    const float4* xr = (const float4*)(xp + (size_t)token * 256);
    ln_warp_store(xr[lane], xr[lane + 32], lane, gp, bp, op + (size_t)token * 256);
}

// LN over permuted fine tokens of o0 (cross-attn K/V input), fp16 out.
__global__ void __launch_bounds__(256)
ln_fine_half_kernel(const float* __restrict__ o0, __half* __restrict__ oh,
                    const float* __restrict__ gamma, const float* __restrict__ beta) {
    int fidx = blockIdx.x * 8 + (threadIdx.x >> 5);
    int lane = threadIdx.x & 31;
    int pp = fidx & 15, p1 = pp >> 2, p2 = pp & 3;
    int grp = fidx >> 4;
    int rr = grp & 15, r1 = rr >> 2, r2 = rr & 3;
    int bhw = grp >> 4;
    int w = bhw & 7, h = (bhw >> 3) & 7, b = bhw >> 6;
    int fw = b * 64 + h * 8 + w;
    int n = (r1 * 4 + p1) * 16 + r2 * 4 + p2;
    const float4* xr = (const float4*)(o0 + ((size_t)fw * 256 + n) * 256);
    ln_warp_store(xr[lane], xr[lane + 32], lane, gamma, beta, oh + (size_t)fidx * 256);
}

// Gather coarse token + LN: G = gathered X1 (fp32), A3 = LN1(G).
__global__ void __launch_bounds__(256)
gather_ln_kernel(const float* __restrict__ X1, float* __restrict__ G,
                 __half* __restrict__ A3,
                 const float* __restrict__ gamma, const float* __restrict__ beta) {
    int gidx = blockIdx.x * 8 + (threadIdx.x >> 5);
    int lane = threadIdx.x & 31;
    int rr = gidx & 15, r1 = rr >> 2, r2 = rr & 3;
    int bhw = gidx >> 4;
    int w = bhw & 7, h = (bhw >> 3) & 7, b = bhw >> 6;
    int R = h * 4 + r1, Cc = w * 4 + r2;
    int gi = R >> 4, ti = R & 15, gj = Cc >> 4, tj = Cc & 15;
    int win = (b * 2 + gi) * 2 + gj, tok = ti * 16 + tj;
    const float4* xr = (const float4*)(X1 + ((size_t)win * 256 + tok) * 256);
    float4 v0 = xr[lane], v1 = xr[lane + 32];
    float4* gr = (float4*)(G + (size_t)gidx * 256);
    gr[lane] = v0; gr[lane + 32] = v1;
    ln_warp_store(v0, v1, lane, gamma, beta, A3 + (size_t)gidx * 256);
}

__global__ void wconv_all_kernel(const float* __restrict__ wqkv,
                                 const float* __restrict__ wo,
                                 const float* __restrict__ mw1,
                                 const float* __restrict__ mw2,
                                 __half* __restrict__ Tqkv, __half* __restrict__ To,
                                 __half* __restrict__ Tm1,  __half* __restrict__ Tm2) {
    int bid = blockIdx.x;
    int s = bid / 2304, r = bid % 2304;
    const float* W; __half* T; int K, N, n;
    if (r < 768)       { W = wqkv + (size_t)s * 196608; T = Tqkv + (size_t)s * 196608; K = 256;  N = 768;  n = r; }
    else if (r < 1024) { W = wo   + (size_t)s * 65536;  T = To   + (size_t)s * 65536;  K = 256;  N = 256;  n = r - 768; }
    else if (r < 2048) { W = mw1  + (size_t)s * 262144; T = Tm1  + (size_t)s * 262144; K = 256;  N = 1024; n = r - 1024; }
    else               { W = mw2  + (size_t)s * 262144; T = Tm2  + (size_t)s * 262144; K = 1024; N = 256;  n = r - 2048; }
    for (int k = threadIdx.x; k < K; k += 256)
        T[(size_t)n * K + k] = __float2half(W[(size_t)k * N + n]);
}

// ---------------------------------------------------------------------------
// fp16 1-pass GEMM (round-8 config) with DUAL problem support:
// CTAs with blockIdx.y >= bmSplit switch to the 2nd pointer set (same K/ldc/N).
// EPI 0: fp32 out. 1: GELU->fp16. 2: +res->fp32. 3: fp16.
// ---------------------------------------------------------------------------
template <int EPI>
__global__ void __launch_bounds__(256)
gemm_mma(const __half* A, const __half* B,
         const float* bias, const float* res,
         float* Cp, __half* Oh,
         const __half* A2, const __half* B2,
         const float* bias2, const float* res2,
         float* Cp2, __half* Oh2,
         int bmSplit, int K, int ldc) {
    extern __shared__ char smc[];
    const uint32_t sb = smem_u32(smc);
    int tid = threadIdx.x, lane = tid & 31, wid = tid >> 5;
    int wm = wid >> 2, wn = wid & 3;
    int bm = blockIdx.y, bn = blockIdx.x;
    if (bm >= bmSplit) {
        bm -= bmSplit;
        A = A2; B = B2; bias = bias2; res = res2; Cp = Cp2; Oh = Oh2;
    }

    const __half* src0 = A + (size_t)bm * 128 * K;
    const __half* src1 = B + (size_t)bn * 128 * K;

    int nc = K >> 6;
    int crow0 = tid >> 3, ccol = tid & 7;

#define PREFETCH(CH, BUF) do {                                                 \
    int _k0 = (CH) << 6;                                                       \
    const __half* _s[2] = {src0 + _k0, src1 + _k0};                            \
    _Pragma("unroll")                                                          \
    for (int _op = 0; _op < 2; _op++) {                                        \
        uint32_t _db = sb + (BUF) * BUF_BYTES + _op * TILE_BYTES;              \
        _Pragma("unroll")                                                      \
        for (int _i = 0; _i < 4; _i++) {                                       \
            int _row = crow0 + _i * 32;                                        \
            uint32_t _doff = _db + _row * 128 + ((ccol ^ (_row & 7)) << 4);    \
            cp16(_doff, _s[_op] + (size_t)_row * K + ccol * 8);                \
        }                                                                      \
    }                                                                          \
} while (0)

    float acc[4][4][4];
#pragma unroll
    for (int mi = 0; mi < 4; mi++)
#pragma unroll
        for (int ni = 0; ni < 4; ni++)
#pragma unroll
            for (int r = 0; r < 4; r++) acc[mi][ni][r] = 0.f;

    PREFETCH(0, 0);
    CP_COMMIT();
    if (nc > 1) { PREFETCH(1, 1); CP_COMMIT(); }

    int a_rl = lane & 15;
    int b_rl = ((lane >> 4) << 3) + (lane & 7);

    for (int ch = 0; ch < nc; ch++) {
        int buf = ch % 3;
        if (ch + 2 < nc) {
            PREFETCH(ch + 2, (ch + 2) % 3);
            CP_COMMIT();
            CP_WAIT2();
        } else if (ch + 1 < nc) {
            CP_WAIT1();
        } else {
            CP_WAIT0();
        }
        __syncthreads();

        uint32_t base = sb + buf * BUF_BYTES;
#pragma unroll
        for (int ks = 0; ks < 4; ks++) {
            uint32_t ah[4][4], bh[4][2];
            int achunk = ks * 2 + (lane >> 4);
            int bchunk = ks * 2 + ((lane >> 3) & 1);
#pragma unroll
            for (int mi = 0; mi < 4; mi++) {
                int row = wm * 64 + mi * 16 + a_rl;
                uint32_t off = (uint32_t)(row * 128 + ((achunk ^ (row & 7)) << 4));
                ldsm4(ah[mi][0], ah[mi][1], ah[mi][2], ah[mi][3], base + off);
            }
#pragma unroll
            for (int np = 0; np < 2; np++) {
                int row = wn * 32 + np * 16 + b_rl;
                uint32_t off = (uint32_t)(row * 128 + ((bchunk ^ (row & 7)) << 4));
                uint32_t r0, r1, r2, r3;
                ldsm4(r0, r1, r2, r3, base + TILE_BYTES + off);
                bh[np * 2][0] = r0; bh[np * 2][1] = r1;
                bh[np * 2 + 1][0] = r2; bh[np * 2 + 1][1] = r3;
            }
#pragma unroll
            for (int mi = 0; mi < 4; mi++)
#pragma unroll
                for (int ni = 0; ni < 4; ni++)
                    mma16816(acc[mi][ni], ah[mi], bh[ni]);
        }
        __syncthreads();
    }
#undef PREFETCH

    int l4 = lane >> 2, l2 = (lane & 3) << 1;
#pragma unroll
    for (int mi = 0; mi < 4; mi++) {
        int r0 = bm * 128 + wm * 64 + mi * 16 + l4;
#pragma unroll
        for (int ni = 0; ni < 4; ni++) {
            int cc = bn * 128 + wn * 32 + ni * 8 + l2;
            float b0 = bias[cc], b1 = bias[cc + 1];
            float v00 = acc[mi][ni][0] + b0, v01 = acc[mi][ni][1] + b1;
            float v10 = acc[mi][ni][2] + b0, v11 = acc[mi][ni][3] + b1;
            size_t o0 = (size_t)r0 * ldc + cc;
            size_t o1 = (size_t)(r0 + 8) * ldc + cc;
            if (EPI == 1) {
                const float is2 = 0.7071067811865476f;
                float g00 = 0.5f * v00 * (1.f + erff(v00 * is2));
                float g01 = 0.5f * v01 * (1.f + erff(v01 * is2));
                float g10 = 0.5f * v10 * (1.f + erff(v10 * is2));
                float g11 = 0.5f * v11 * (1.f + erff(v11 * is2));
                *(uint32_t*)(Oh + o0) = packh2(g00, g01);
                *(uint32_t*)(Oh + o1) = packh2(g10, g11);
            } else if (EPI == 3) {
                *(uint32_t*)(Oh + o0) = packh2(v00, v01);
                *(uint32_t*)(Oh + o1) = packh2(v10, v11);
            } else {
                if (EPI == 2) {
                    float2 ra = *(const float2*)(res + o0);
                    float2 rb = *(const float2*)(res + o1);
                    v00 += ra.x; v01 += ra.y; v10 += rb.x; v11 += rb.y;
                }
                *(float2*)(Cp + o0) = make_float2(v00, v01);
                *(float2*)(Cp + o1) = make_float2(v10, v11);
            }
        }
    }
}

// ---------------------------------------------------------------------------
// Tensor-core flash attention (no-max softmax), dual-problem.
// CTAs >= ctaSplit use (qkv2, out2).
// ---------------------------------------------------------------------------
__global__ void __launch_bounds__(256)
attn_mma_kernel(const __half* qkv, __half* out,
                const __half* qkv2, __half* out2, int ctaSplit) {
    extern __shared__ char smc[];
    const uint32_t sb = smem_u32(smc);
    const uint32_t sbQ = sb, sbK = sb + 256 * ATTN_ROWB, sbV = sb + 512 * ATTN_ROWB;
    int cta = blockIdx.x;
    if (cta >= ctaSplit) { cta -= ctaSplit; qkv = qkv2; out = out2; }
    int win = cta >> 3, head = cta & 7;
    int tid = threadIdx.x, lane = tid & 31, wid = tid >> 5;

    {
        const uint4* src = (const uint4*)(qkv + ((size_t)(win * 256 + tid) * 768 + head * 32));
        uint4* dq = (uint4*)(smc + tid * ATTN_ROWB);
        uint4* dk = (uint4*)(smc + 256 * ATTN_ROWB + tid * ATTN_ROWB);
        uint4* dv = (uint4*)(smc + 512 * ATTN_ROWB + tid * ATTN_ROWB);
#pragma unroll
        for (int c = 0; c < 4; c++) dq[c] = src[c];
#pragma unroll
        for (int c = 0; c < 4; c++) dk[c] = src[32 + c];
#pragma unroll
        for (int c = 0; c < 4; c++) dv[c] = src[64 + c];
    }
    __syncthreads();

    uint32_t aq[2][2][4];
#pragma unroll
    for (int mi = 0; mi < 2; mi++)
#pragma unroll
        for (int kt = 0; kt < 2; kt++) {
            int row = wid * 32 + mi * 16 + (lane & 15);
            uint32_t addr = sbQ + row * ATTN_ROWB + (kt * 2 + (lane >> 4)) * 16;
            ldsm4(aq[mi][kt][0], aq[mi][kt][1], aq[mi][kt][2], aq[mi][kt][3], addr);
        }

    float o[2][4][4];
#pragma unroll
    for (int mi = 0; mi < 2; mi++)
#pragma unroll
        for (int ni = 0; ni < 4; ni++)
#pragma unroll
            for (int r = 0; r < 4; r++) o[mi][ni][r] = 0.f;
    float l[2][2] = {{0.f, 0.f}, {0.f, 0.f}};
    const float sc = 0.17677669529663687f * 1.4426950408889634f;

    for (int kc = 0; kc < 4; kc++) {
        float s[2][8][4];
#pragma unroll
        for (int mi = 0; mi < 2; mi++)
#pragma unroll
            for (int ni = 0; ni < 8; ni++)
#pragma unroll
                for (int r = 0; r < 4; r++) s[mi][ni][r] = 0.f;

#pragma unroll
        for (int nt = 0; nt < 4; nt++) {
            int keyrow = kc * 64 + nt * 16 + (lane & 15);
#pragma unroll
            for (int kt = 0; kt < 2; kt++) {
                uint32_t addr = sbK + keyrow * ATTN_ROWB + (kt * 2 + (lane >> 4)) * 16;
                uint32_t r0, r1, r2, r3;
                ldsm4(r0, r1, r2, r3, addr);
                uint32_t blo[2] = {r0, r2}, bhi[2] = {r1, r3};
#pragma unroll
                for (int mi = 0; mi < 2; mi++) {
                    mma16816(s[mi][nt * 2],     aq[mi][kt], blo);
                    mma16816(s[mi][nt * 2 + 1], aq[mi][kt], bhi);
                }
            }
        }

#pragma unroll
        for (int mi = 0; mi < 2; mi++)
#pragma unroll
            for (int ni = 0; ni < 8; ni++) {
                float p0 = exp2f(s[mi][ni][0] * sc);
                float p1 = exp2f(s[mi][ni][1] * sc);
                float p2 = exp2f(s[mi][ni][2] * sc);
                float p3 = exp2f(s[mi][ni][3] * sc);
                s[mi][ni][0] = p0; s[mi][ni][1] = p1;
                s[mi][ni][2] = p2; s[mi][ni][3] = p3;
                l[mi][0] += p0 + p1;
                l[mi][1] += p2 + p3;
            }

        uint32_t pa[2][4][4];
#pragma unroll
        for (int mi = 0; mi < 2; mi++)
#pragma unroll
            for (int kt = 0; kt < 4; kt++) {
                pa[mi][kt][0] = packh2(s[mi][kt * 2][0], s[mi][kt * 2][1]);
                pa[mi][kt][1] = packh2(s[mi][kt * 2][2], s[mi][kt * 2][3]);
                pa[mi][kt][2] = packh2(s[mi][kt * 2 + 1][0], s[mi][kt * 2 + 1][1]);
                pa[mi][kt][3] = packh2(s[mi][kt * 2 + 1][2], s[mi][kt * 2 + 1][3]);
            }

#pragma unroll
        for (int kt = 0; kt < 4; kt++) {
            int keyrow = kc * 64 + kt * 16 + (lane & 15);
#pragma unroll
            for (int dc = 0; dc < 2; dc++) {
                uint32_t addr = sbV + keyrow * ATTN_ROWB + (dc * 2 + (lane >> 4)) * 16;
                uint32_t r0, r1, r2, r3;
                ldsm4t(r0, r1, r2, r3, addr);
                uint32_t b0[2] = {r0, r1}, b1[2] = {r2, r3};
#pragma unroll
                for (int mi = 0; mi < 2; mi++) {
                    mma16816(o[mi][dc * 2],     pa[mi][kt], b0);
                    mma16816(o[mi][dc * 2 + 1], pa[mi][kt], b1);
                }
            }
        }
    }

#pragma unroll
    for (int mi = 0; mi < 2; mi++)
#pragma unroll
        for (int h = 0; h < 2; h++) {
            float v = l[mi][h];
            v += __shfl_xor_sync(0xffffffffu, v, 1);
            v += __shfl_xor_sync(0xffffffffu, v, 2);
            l[mi][h] = v;
        }

    int l4 = lane >> 2, l2 = (lane & 3) << 1;
#pragma unroll
    for (int mi = 0; mi < 2; mi++)
#pragma unroll
        for (int h = 0; h < 2; h++) {
            float inv = 1.f / l[mi][h];
            int row = wid * 32 + mi * 16 + l4 + h * 8;
            size_t ob = ((size_t)(win * 256 + row)) * 256 + head * 32;
#pragma unroll
            for (int ni = 0; ni < 4; ni++) {
                *(uint32_t*)(out + ob + ni * 8 + l2) =
                    packh2(o[mi][ni][h * 2] * inv, o[mi][ni][h * 2 + 1] * inv);
            }
        }
}

// ---------------------------------------------------------------------------
// Cross attention: 1 query x 16 keys, warp per head
// ---------------------------------------------------------------------------
__global__ void __launch_bounds__(256)
cross_attn_kernel(const float* __restrict__ Q, const __half* __restrict__ KV,
                  __half* __restrict__ oh) {
    int g = blockIdx.x;
    int head = threadIdx.x >> 5, lane = threadIdx.x & 31;
    float qd = Q[(size_t)g * 256 + head * 32 + lane];
    size_t kvbase = (size_t)g * 16 * 512 + head * 32 + lane;
    const float sc = 0.17677669529663687f * 1.4426950408889634f;
    float s[16];
#pragma unroll
    for (int j = 0; j < 16; j++) {
        float p = qd * __half2float(KV[kvbase + (size_t)j * 512]);
#pragma unroll
        for (int o = 16; o; o >>= 1) p += __shfl_xor_sync(0xffffffffu, p, o);
        s[j] = p * sc;
    }
    float l = 0.f;
#pragma unroll
    for (int j = 0; j < 16; j++) { s[j] = exp2f(s[j]); l += s[j]; }
    float inv = 1.f / l, acc = 0.f;
#pragma unroll
    for (int j = 0; j < 16; j++)
        acc = fmaf(s[j], __half2float(KV[kvbase + 256 + (size_t)j * 512]), acc);
    oh[(size_t)g * 256 + head * 32 + lane] = __float2half(acc * inv);
}

__global__ void scatter_o1_kernel(const float* __restrict__ G, float* __restrict__ out1) {
    int idx = blockIdx.x;
    int win = idx >> 8, tok = idx & 255;
    int b = win >> 2, gi = (win >> 1) & 1, gj = win & 1;
    int ti = tok >> 4, tj = tok & 15;
    int R = gi * 16 + ti, Cc = gj * 16 + tj;
    int h = R >> 2, r1 = R & 3, w = Cc >> 2, r2 = Cc & 3;
    int gidx = ((b * 8 + h) * 8 + w) * 16 + r1 * 4 + r2;
    out1[(size_t)idx * 256 + threadIdx.x] = G[(size_t)gidx * 256 + threadIdx.x];
}

// ---------------------------------------------------------------------------
// Host launch
// ---------------------------------------------------------------------------
extern "C" void kernel_launch(void* const* d_in, const int* in_sizes, int n_in,
                              void* d_out, int out_size) {
    const float* scale0 = (const float*)d_in[0];
    const float* scale1 = (const float*)d_in[1];
    const float* pe_w1  = (const float*)d_in[2];
    const float* pe_b1  = (const float*)d_in[3];
    const float* pe_w2  = (const float*)d_in[4];
    const float* ln1_g  = (const float*)d_in[5];
    const float* ln1_b  = (const float*)d_in[6];
    const float* wqkv   = (const float*)d_in[7];
    const float* bqkv   = (const float*)d_in[8];
    const float* wo     = (const float*)d_in[9];
    const float* bo     = (const float*)d_in[10];
    const float* ln2_g  = (const float*)d_in[11];
    const float* ln2_b  = (const float*)d_in[12];
    const float* mw1    = (const float*)d_in[13];
    const float* mb1    = (const float*)d_in[14];
    const float* mw2    = (const float*)d_in[15];
    const float* mb2    = (const float*)d_in[16];
    float* out = (float*)d_out;

    float *PE, *X0, *X1, *G, *Qb;
    __half *QKVh, *QKVc, *A, *Ac, *H1, *H1c, *A3;
    __half *WqkvT, *WoT, *W1T, *W2T;
    cudaGetSymbolAddress((void**)&PE,   g_PE);
    cudaGetSymbolAddress((void**)&X0,   g_X0);
    cudaGetSymbolAddress((void**)&X1,   g_X1);
    cudaGetSymbolAddress((void**)&G,    g_G);
    cudaGetSymbolAddress((void**)&Qb,   g_Qb);
    cudaGetSymbolAddress((void**)&QKVh, g_QKVh);
    cudaGetSymbolAddress((void**)&QKVc, g_QKVc);
    cudaGetSymbolAddress((void**)&A,    g_A);
    cudaGetSymbolAddress((void**)&Ac,   g_Ac);
    cudaGetSymbolAddress((void**)&H1,   g_H1);
    cudaGetSymbolAddress((void**)&H1c,  g_H1c);
    cudaGetSymbolAddress((void**)&A3,   g_A3);
    cudaGetSymbolAddress((void**)&WqkvT, g_WqkvT);
    cudaGetSymbolAddress((void**)&WoT,   g_WoT);
    cudaGetSymbolAddress((void**)&W1T,   g_W1T);
    cudaGetSymbolAddress((void**)&W2T,   g_W2T);

    cudaFuncSetAttribute(attn_mma_kernel, cudaFuncAttributeMaxDynamicSharedMemorySize, ATTN_SMEM);
    cudaFuncSetAttribute(gemm_mma<0>, cudaFuncAttributeMaxDynamicSharedMemorySize, GEMM_SMEM);
    cudaFuncSetAttribute(gemm_mma<1>, cudaFuncAttributeMaxDynamicSharedMemorySize, GEMM_SMEM);
    cudaFuncSetAttribute(gemm_mma<2>, cudaFuncAttributeMaxDynamicSharedMemorySize, GEMM_SMEM);
    cudaFuncSetAttribute(gemm_mma<3>, cudaFuncAttributeMaxDynamicSharedMemorySize, GEMM_SMEM);

    // 0) weights + position embeddings
    wconv_all_kernel<<<4608, 256>>>(wqkv, wo, mw1, mw2, WqkvT, WoT, W1T, W2T);
    posemb_kernel<<<512, 256>>>(pe_w1, pe_b1, pe_w2, PE);

    // 1) inputs with fused LN1
    add_pe0_ln_kernel<<<T0 / 8, 256>>>(scale0, PE, X0, A, ln1_g, ln1_b);
    pool_add_ln_kernel<<<T1 / 8, 256>>>(scale1, PE, X0, X1, Ac,
                                        ln1_g + 256, ln1_b + 256);

    // 2) self-attention blocks, fine+coarse fused per launch
    // QKV (fine s=0 | coarse s=1)
    gemm_mma<3><<<dim3(6, 512 + 32), 256, GEMM_SMEM>>>(
        A, WqkvT, bqkv, nullptr, nullptr, QKVh,
        Ac, WqkvT + 196608, bqkv + 768, nullptr, nullptr, QKVc,
        512, 256, 768);
    // attention (2048 fine CTAs | 128 coarse)
    attn_mma_kernel<<<NWIN0 * 8 + NWIN1 * 8, 256, ATTN_SMEM>>>(
        QKVh, A, QKVc, Ac, NWIN0 * 8);
    // O-proj + residual
    gemm_mma<2><<<dim3(2, 512 + 32), 256, GEMM_SMEM>>>(
        A, WoT, bo, X0, X0, nullptr,
        Ac, WoT + 65536, bo + 256, X1, X1, nullptr,
        512, 256, 256);
    // LN2 (combined)
    ln_half_kernel<<<T0 / 8 + T1 / 8, 256>>>(
        X0, A, ln2_g, ln2_b, X1, Ac, ln2_g + 256, ln2_b + 256, T0 / 8);
    // MLP1 (GELU)
    gemm_mma<1><<<dim3(8, 512 + 32), 256, GEMM_SMEM>>>(
        A, W1T, mb1, nullptr, nullptr, H1,
        Ac, W1T + 262144, mb1 + 1024, nullptr, nullptr, H1c,
        512, 256, 1024);
    // MLP2 + residual: fine -> out (o0), coarse -> X1 final
    gemm_mma<2><<<dim3(2, 512 + 32), 256, GEMM_SMEM>>>(
        H1, W2T, mb2, X0, out, nullptr,
        H1c, W2T + 262144, mb2 + 256, X1, X1, nullptr,
        512, 1024, 256);

    // 3) one2one cross-attention aggregation (scale-1 weights)
    gather_ln_kernel<<<T1 / 8, 256>>>(X1, G, A3, ln1_g + 256, ln1_b + 256);
    gemm_mma<0><<<dim3(2, 32), 256, GEMM_SMEM>>>(
        A3, WqkvT + 196608, bqkv + 768, nullptr, Qb, nullptr,
        A3, WqkvT + 196608, bqkv + 768, nullptr, Qb, nullptr, 32, 256, 256);
    ln_fine_half_kernel<<<T0 / 8, 256>>>(out, A, ln1_g + 256, ln1_b + 256);
    gemm_mma<3><<<dim3(4, 512), 256, GEMM_SMEM>>>(
        A, WqkvT + 196608 + 65536, bqkv + 768 + 256, nullptr, nullptr, QKVh,
        A, WqkvT + 196608 + 65536, bqkv + 768 + 256, nullptr, nullptr, QKVh,
        512, 256, 512);
    cross_attn_kernel<<<T1, 256>>>(Qb, QKVh, A3);
    gemm_mma<2><<<dim3(2, 32), 256, GEMM_SMEM>>>(
        A3, WoT + 65536, bo + 256, G, G, nullptr,
        A3, WoT + 65536, bo + 256, G, G, nullptr, 32, 256, 256);
    ln_half_kernel<<<T1 / 8, 256>>>(
        G, A3, ln2_g + 256, ln2_b + 256,
        G, A3, ln2_g + 256, ln2_b + 256, T1 / 8);
    gemm_mma<1><<<dim3(8, 32), 256, GEMM_SMEM>>>(
        A3, W1T + 262144, mb1 + 1024, nullptr, nullptr, H1,
        A3, W1T + 262144, mb1 + 1024, nullptr, nullptr, H1, 32, 256, 1024);
    gemm_mma<2><<<dim3(2, 32), 256, GEMM_SMEM>>>(
        H1, W2T + 262144, mb2 + 256, G, G, nullptr,
        H1, W2T + 262144, mb2 + 256, G, G, nullptr, 32, 1024, 256);
    scatter_o1_kernel<<<T1, 256>>>(G, out + (size_t)NWIN0 * 256 * 256);
}

// round 12
// speedup vs baseline: 1.1284x; 1.0291x over previous
#include <cuda_runtime.h>
#include <cuda_fp16.h>
#include <cstdint>
#include <cstddef>

// ---------------------------------------------------------------------------
// Dimensions: B=4, H=W=8, M=16, C=256, NH=8, HD=32, GW=2
// ---------------------------------------------------------------------------
#define T0      65536
#define T1      4096
#define NWIN0   256
#define NWIN1   16

// gemm config (round-8 passing): 128x128 tile, BK=64, 3-stage, 2 tiles, 256 thr
#define TILE_BYTES 16384
#define BUF_BYTES  (2 * TILE_BYTES)
#define GEMM_SMEM  (3 * BUF_BYTES)

// Attention smem: Q,K,V fp16 256 rows x 80B stride
#define ATTN_ROWB  80
#define ATTN_SMEM  (3 * 256 * ATTN_ROWB)

// ---------------------------------------------------------------------------
// PTX helpers (sm_80-class only)
// ---------------------------------------------------------------------------
__device__ __forceinline__ uint32_t smem_u32(const void* p) {
    uint32_t a;
    asm("{ .reg .u64 t; cvta.to.shared.u64 t, %1; cvt.u32.u64 %0, t; }" : "=r"(a) : "l"(p));
    return a;
}
__device__ __forceinline__ void cp16(uint32_t dst, const void* src) {
    asm volatile("cp.async.cg.shared.global [%0], [%1], 16;" :: "r"(dst), "l"(src) : "memory");
}
#define CP_COMMIT() asm volatile("cp.async.commit_group;" ::: "memory")
#define CP_WAIT2()  asm volatile("cp.async.wait_group 2;" ::: "memory")
#define CP_WAIT1()  asm volatile("cp.async.wait_group 1;" ::: "memory")
#define CP_WAIT0()  asm volatile("cp.async.wait_group 0;" ::: "memory")

__device__ __forceinline__ void ldsm4(uint32_t& r0, uint32_t& r1, uint32_t& r2,
                                      uint32_t& r3, uint32_t addr) {
    asm volatile("ldmatrix.sync.aligned.m8n8.x4.shared.b16 {%0,%1,%2,%3}, [%4];"
                 : "=r"(r0), "=r"(r1), "=r"(r2), "=r"(r3) : "r"(addr));
}
__device__ __forceinline__ void ldsm4t(uint32_t& r0, uint32_t& r1, uint32_t& r2,
                                       uint32_t& r3, uint32_t addr) {
    asm volatile("ldmatrix.sync.aligned.m8n8.x4.trans.shared.b16 {%0,%1,%2,%3}, [%4];"
                 : "=r"(r0), "=r"(r1), "=r"(r2), "=r"(r3) : "r"(addr));
}
__device__ __forceinline__ void mma16816(float* c, const uint32_t* a, const uint32_t* b) {
    asm volatile(
        "mma.sync.aligned.m16n8k16.row.col.f32.f16.f16.f32 "
        "{%0,%1,%2,%3}, {%4,%5,%6,%7}, {%8,%9}, {%0,%1,%2,%3};"
        : "+f"(c[0]), "+f"(c[1]), "+f"(c[2]), "+f"(c[3])
        : "r"(a[0]), "r"(a[1]), "r"(a[2]), "r"(a[3]), "r"(b[0]), "r"(b[1]));
}
__device__ __forceinline__ uint32_t packh2(float a, float b) {
    __half2 h = __floats2half2_rn(a, b);
    return *(uint32_t*)&h;
}

// Row-level permutation: gidx -> o1-row
__device__ __forceinline__ int scatter_perm(int g) {
    int rr = g & 15, r1 = rr >> 2, r2 = rr & 3;
    int bhw = g >> 4;
    int w = bhw & 7, h = (bhw >> 3) & 7, b = bhw >> 6;
    int R = h * 4 + r1, Cc = w * 4 + r2;
    return (((b * 2 + (R >> 4)) * 2 + (Cc >> 4)) << 8) + (R & 15) * 16 + (Cc & 15);
}

// ---------------------------------------------------------------------------
// Scratch
// ---------------------------------------------------------------------------
__device__ float g_PE [2 * 256 * 256];
__device__ float g_X0 [(size_t)T0 * 256];
__device__ float g_X1 [(size_t)T1 * 256];
__device__ float g_G  [(size_t)T1 * 256];
__device__ __half g_Qbh[(size_t)T1 * 256];
__device__ __half g_QKVh[(size_t)T0 * 768];
__device__ __half g_QKVc[(size_t)T1 * 768];
__device__ __half g_A  [(size_t)T0 * 256];
__device__ __half g_Ac [(size_t)T1 * 256];
__device__ __half g_H1 [(size_t)T0 * 1024];
__device__ __half g_H1c[(size_t)T1 * 1024];
__device__ __half g_A3 [(size_t)T1 * 256];
__device__ __half g_WqkvT[2 * 768 * 256];
__device__ __half g_WoT  [2 * 256 * 256];
__device__ __half g_W1T  [2 * 1024 * 256];
__device__ __half g_W2T  [2 * 256 * 1024];

// ---------------------------------------------------------------------------
// LN helper (warp per token)
// ---------------------------------------------------------------------------
__device__ __forceinline__ void ln_warp_store(float4 v0, float4 v1, int lane,
                                              const float* __restrict__ gamma,
                                              const float* __restrict__ beta,
                                              __half* __restrict__ orow) {
    float s = v0.x + v0.y + v0.z + v0.w + v1.x + v1.y + v1.z + v1.w;
#pragma unroll
    for (int d = 16; d; d >>= 1) s += __shfl_xor_sync(0xffffffffu, s, d);
    float mean = s * (1.f / 256.f);
    float d0x = v0.x - mean, d0y = v0.y - mean, d0z = v0.z - mean, d0w = v0.w - mean;
    float d1x = v1.x - mean, d1y = v1.y - mean, d1z = v1.z - mean, d1w = v1.w - mean;
    float q = d0x*d0x + d0y*d0y + d0z*d0z + d0w*d0w +
              d1x*d1x + d1y*d1y + d1z*d1z + d1w*d1w;
#pragma unroll
    for (int d = 16; d; d >>= 1) q += __shfl_xor_sync(0xffffffffu, q, d);
    float rstd = rsqrtf(q * (1.f / 256.f) + 1e-5f);
    float4 g0 = ((const float4*)gamma)[lane], g1 = ((const float4*)gamma)[lane + 32];
    float4 b0 = ((const float4*)beta)[lane],  b1 = ((const float4*)beta)[lane + 32];
    uint2 o0, o1;
    o0.x = packh2(fmaf(d0x * rstd, g0.x, b0.x), fmaf(d0y * rstd, g0.y, b0.y));
    o0.y = packh2(fmaf(d0z * rstd, g0.z, b0.z), fmaf(d0w * rstd, g0.w, b0.w));
    o1.x = packh2(fmaf(d1x * rstd, g1.x, b1.x), fmaf(d1y * rstd, g1.y, b1.y));
    o1.y = packh2(fmaf(d1z * rstd, g1.z, b1.z), fmaf(d1w * rstd, g1.w, b1.w));
    uint2* ou = (uint2*)orow;
    ou[lane] = o0;
    ou[lane + 32] = o1;
}

// ---------------------------------------------------------------------------
// Small kernels
// ---------------------------------------------------------------------------
__global__ void posemb_kernel(const float* __restrict__ pe_w1,
                              const float* __restrict__ pe_b1,
                              const float* __restrict__ pe_w2,
                              float* __restrict__ PE) {
    int s = blockIdx.x >> 8;
    int n = blockIdx.x & 255;
    int i = n >> 4, j = n & 15;
    float cy = (i - 8) * 0.125f;
    float cx = (j - 8) * 0.125f;
    __shared__ float hid[512];
    const float* w1 = pe_w1 + s * 2 * 512;
    const float* b1 = pe_b1 + s * 512;
    for (int k = threadIdx.x; k < 512; k += 256)
        hid[k] = fmaxf(0.f, fmaf(cy, w1[k], fmaf(cx, w1[512 + k], b1[k])));
    __syncthreads();
    const float* w2 = pe_w2 + (size_t)s * 512 * 256;
    int c = threadIdx.x;
    float acc = 0.f;
#pragma unroll 8
    for (int k = 0; k < 512; k++) acc = fmaf(hid[k], w2[(size_t)k * 256 + c], acc);
    PE[((size_t)s * 256 + n) * 256 + c] = acc;
}

__global__ void __launch_bounds__(256)
add_pe0_ln_kernel(const float* __restrict__ s0, const float* __restrict__ PE,
                  float* __restrict__ X0, __half* __restrict__ A,
                  const float* __restrict__ gamma, const float* __restrict__ beta) {
    int token = blockIdx.x * 8 + (threadIdx.x >> 5);
    int lane = threadIdx.x & 31;
    const float4* sr = (const float4*)(s0 + (size_t)token * 256);
    const float4* pr = (const float4*)(PE + (size_t)(token & 255) * 256);
    float4 v0 = sr[lane], v1 = sr[lane + 32];
    float4 p0 = pr[lane], p1 = pr[lane + 32];
    v0.x += p0.x; v0.y += p0.y; v0.z += p0.z; v0.w += p0.w;
    v1.x += p1.x; v1.y += p1.y; v1.z += p1.z; v1.w += p1.w;
    float4* xr = (float4*)(X0 + (size_t)token * 256);
    xr[lane] = v0; xr[lane + 32] = v1;
    ln_warp_store(v0, v1, lane, gamma, beta, A + (size_t)token * 256);
}

__global__ void __launch_bounds__(256)
pool_add_ln_kernel(const float* __restrict__ s1, const float* __restrict__ PE,
                   const float* __restrict__ X0, float* __restrict__ X1,
                   __half* __restrict__ Ac,
                   const float* __restrict__ gamma, const float* __restrict__ beta) {
    int token = blockIdx.x * 8 + (threadIdx.x >> 5);
    int lane = threadIdx.x & 31;
    int t  = token & 255;
    int gw = token >> 8;
    int b = gw >> 2, gi = (gw >> 1) & 1, gj = gw & 1;
    int ti = t >> 4, tj = t & 15;
    int R  = gi * 16 + ti, Cc = gj * 16 + tj;
    int h = R >> 2, r1 = R & 3, w = Cc >> 2, r2 = Cc & 3;
    int fw = b * 64 + h * 8 + w;
    float4 m0 = make_float4(-1e30f, -1e30f, -1e30f, -1e30f), m1 = m0;
#pragma unroll
    for (int p1 = 0; p1 < 4; p1++)
#pragma unroll
        for (int p2 = 0; p2 < 4; p2++) {
            int n = (r1 * 4 + p1) * 16 + r2 * 4 + p2;
            const float4* row = (const float4*)(X0 + ((size_t)fw * 256 + n) * 256);
            float4 a = row[lane], c = row[lane + 32];
            m0.x = fmaxf(m0.x, a.x); m0.y = fmaxf(m0.y, a.y);
            m0.z = fmaxf(m0.z, a.z); m0.w = fmaxf(m0.w, a.w);
            m1.x = fmaxf(m1.x, c.x); m1.y = fmaxf(m1.y, c.y);
            m1.z = fmaxf(m1.z, c.z); m1.w = fmaxf(m1.w, c.w);
        }
    const float4* sr = (const float4*)(s1 + (size_t)token * 256);
    const float4* pr = (const float4*)(PE + (size_t)(256 + t) * 256);
    float4 s0v = sr[lane], s1v = sr[lane + 32];
    float4 p0 = pr[lane], p1v = pr[lane + 32];
    m0.x += s0v.x + p0.x; m0.y += s0v.y + p0.y;
    m0.z += s0v.z + p0.z; m0.w += s0v.w + p0.w;
    m1.x += s1v.x + p1v.x; m1.y += s1v.y + p1v.y;
    m1.z += s1v.z + p1v.z; m1.w += s1v.w + p1v.w;
    float4* xr = (float4*)(X1 + (size_t)token * 256);
    xr[lane] = m0; xr[lane + 32] = m1;
    ln_warp_store(m0, m1, lane, gamma, beta, Ac + (size_t)token * 256);
}

// Combined LayerNorm: blocks < split do problem 1, rest problem 2.
__global__ void __launch_bounds__(256)
ln_half_kernel(const float* __restrict__ x, __half* __restrict__ o,
               const float* __restrict__ gamma, const float* __restrict__ beta,
               const float* __restrict__ x2, __half* __restrict__ o2,
               const float* __restrict__ gamma2, const float* __restrict__ beta2,
               int split) {
    int blk = blockIdx.x;
    const float* xp = x; __half* op = o;
    const float* gp = gamma; const float* bp = beta;
    if (blk >= split) { blk -= split; xp = x2; op = o2; gp = gamma2; bp = beta2; }
    int token = blk * 8 + (threadIdx.x >> 5);
    int lane = threadIdx.x & 31;
    const float4* xr = (const float4*)(xp + (size_t)token * 256);
    ln_warp_store(xr[lane], xr[lane + 32], lane, gp, bp, op + (size_t)token * 256);
}

// Combined pre-cross LN:
//  blocks [0, T0/8):  fine-perm LN of o0 -> Afine (KV input)
//  blocks [T0/8, +T1/8): coarse gather of X1 -> G (fp32) + LN -> A3 (Q input)
__global__ void __launch_bounds__(256)
ln_pre_cross_kernel(const float* __restrict__ o0, __half* __restrict__ Afine,
                    const float* __restrict__ X1, float* __restrict__ G,
                    __half* __restrict__ A3,
                    const float* __restrict__ gamma, const float* __restrict__ beta,
                    int split) {
    int blk = blockIdx.x;
    int lane = threadIdx.x & 31;
    if (blk < split) {
        int fidx = blk * 8 + (threadIdx.x >> 5);
        int pp = fidx & 15, p1 = pp >> 2, p2 = pp & 3;
        int grp = fidx >> 4;
        int rr = grp & 15, r1 = rr >> 2, r2 = rr & 3;
        int bhw = grp >> 4;
        int w = bhw & 7, h = (bhw >> 3) & 7, b = bhw >> 6;
        int fw = b * 64 + h * 8 + w;
        int n = (r1 * 4 + p1) * 16 + r2 * 4 + p2;
        const float4* xr = (const float4*)(o0 + ((size_t)fw * 256 + n) * 256);
        ln_warp_store(xr[lane], xr[lane + 32], lane, gamma, beta,
                      Afine + (size_t)fidx * 256);
    } else {
        int gidx = (blk - split) * 8 + (threadIdx.x >> 5);
        int rr = gidx & 15, r1 = rr >> 2, r2 = rr & 3;
        int bhw = gidx >> 4;
        int w = bhw & 7, h = (bhw >> 3) & 7, b = bhw >> 6;
        int R = h * 4 + r1, Cc = w * 4 + r2;
        int gi = R >> 4, ti = R & 15, gj = Cc >> 4, tj = Cc & 15;
        int win = (b * 2 + gi) * 2 + gj, tok = ti * 16 + tj;
        const float4* xr = (const float4*)(X1 + ((size_t)win * 256 + tok) * 256);
        float4 v0 = xr[lane], v1 = xr[lane + 32];
        float4* gr = (float4*)(G + (size_t)gidx * 256);
        gr[lane] = v0; gr[lane + 32] = v1;
        ln_warp_store(v0, v1, lane, gamma, beta, A3 + (size_t)gidx * 256);
    }
}

__global__ void wconv_all_kernel(const float* __restrict__ wqkv,
                                 const float* __restrict__ wo,
                                 const float* __restrict__ mw1,
                                 const float* __restrict__ mw2,
                                 __half* __restrict__ Tqkv, __half* __restrict__ To,
                                 __half* __restrict__ Tm1,  __half* __restrict__ Tm2) {
    int bid = blockIdx.x;
    int s = bid / 2304, r = bid % 2304;
    const float* W; __half* T; int K, N, n;
    if (r < 768)       { W = wqkv + (size_t)s * 196608; T = Tqkv + (size_t)s * 196608; K = 256;  N = 768;  n = r; }
    else if (r < 1024) { W = wo   + (size_t)s * 65536;  T = To   + (size_t)s * 65536;  K = 256;  N = 256;  n = r - 768; }
    else if (r < 2048) { W = mw1  + (size_t)s * 262144; T = Tm1  + (size_t)s * 262144; K = 256;  N = 1024; n = r - 1024; }
    else               { W = mw2  + (size_t)s * 262144; T = Tm2  + (size_t)s * 262144; K = 1024; N = 256;  n = r - 2048; }
    for (int k = threadIdx.x; k < K; k += 256)
        T[(size_t)n * K + k] = __float2half(W[(size_t)k * N + n]);
}

// ---------------------------------------------------------------------------
// fp16 1-pass GEMM, dual-problem. CTAs with blockIdx.y >= bmSplit switch to
// the 2nd set (own ldc2; exit if bn >= bn2Max).
// EPI 0: fp32. 1: GELU->fp16. 2: +res->fp32. 3: fp16. 4: +res->fp32 scattered.
// ---------------------------------------------------------------------------
template <int EPI>
__global__ void __launch_bounds__(256)
gemm_mma(const __half* A, const __half* B,
         const float* bias, const float* res,
         float* Cp, __half* Oh,
         const __half* A2, const __half* B2,
         const float* bias2, const float* res2,
         float* Cp2, __half* Oh2,
         int bmSplit, int K, int ldc, int ldc2, int bn2Max) {
    extern __shared__ char smc[];
    const uint32_t sb = smem_u32(smc);
    int tid = threadIdx.x, lane = tid & 31, wid = tid >> 5;
    int wm = wid >> 2, wn = wid & 3;
    int bm = blockIdx.y, bn = blockIdx.x;
    if (bm >= bmSplit) {
        bm -= bmSplit;
        if (bn >= bn2Max) return;
        A = A2; B = B2; bias = bias2; res = res2; Cp = Cp2; Oh = Oh2;
        ldc = ldc2;
    }

    const __half* src0 = A + (size_t)bm * 128 * K;
    const __half* src1 = B + (size_t)bn * 128 * K;

    int nc = K >> 6;
    int crow0 = tid >> 3, ccol = tid & 7;

#define PREFETCH(CH, BUF) do {                                                 \
    int _k0 = (CH) << 6;                                                       \
    const __half* _s[2] = {src0 + _k0, src1 + _k0};                            \
    _Pragma("unroll")                                                          \
    for (int _op = 0; _op < 2; _op++) {                                        \
        uint32_t _db = sb + (BUF) * BUF_BYTES + _op * TILE_BYTES;              \
        _Pragma("unroll")                                                      \
        for (int _i = 0; _i < 4; _i++) {                                       \
            int _row = crow0 + _i * 32;                                        \
            uint32_t _doff = _db + _row * 128 + ((ccol ^ (_row & 7)) << 4);    \
            cp16(_doff, _s[_op] + (size_t)_row * K + ccol * 8);                \
        }                                                                      \
    }                                                                          \
} while (0)

    float acc[4][4][4];
#pragma unroll
    for (int mi = 0; mi < 4; mi++)
#pragma unroll
        for (int ni = 0; ni < 4; ni++)
#pragma unroll
            for (int r = 0; r < 4; r++) acc[mi][ni][r] = 0.f;

    PREFETCH(0, 0);
    CP_COMMIT();
    if (nc > 1) { PREFETCH(1, 1); CP_COMMIT(); }

    int a_rl = lane & 15;
    int b_rl = ((lane >> 4) << 3) + (lane & 7);

    for (int ch = 0; ch < nc; ch++) {
        int buf = ch % 3;
        if (ch + 2 < nc) {
            PREFETCH(ch + 2, (ch + 2) % 3);
            CP_COMMIT();
            CP_WAIT2();
        } else if (ch + 1 < nc) {
            CP_WAIT1();
        } else {
            CP_WAIT0();
        }
        __syncthreads();

        uint32_t base = sb + buf * BUF_BYTES;
#pragma unroll
        for (int ks = 0; ks < 4; ks++) {
            uint32_t ah[4][4], bh[4][2];
            int achunk = ks * 2 + (lane >> 4);
            int bchunk = ks * 2 + ((lane >> 3) & 1);
#pragma unroll
            for (int mi = 0; mi < 4; mi++) {
                int row = wm * 64 + mi * 16 + a_rl;
                uint32_t off = (uint32_t)(row * 128 + ((achunk ^ (row & 7)) << 4));
                ldsm4(ah[mi][0], ah[mi][1], ah[mi][2], ah[mi][3], base + off);
            }
#pragma unroll
            for (int np = 0; np < 2; np++) {
                int row = wn * 32 + np * 16 + b_rl;
                uint32_t off = (uint32_t)(row * 128 + ((bchunk ^ (row & 7)) << 4));
                uint32_t r0, r1, r2, r3;
                ldsm4(r0, r1, r2, r3, base + TILE_BYTES + off);
                bh[np * 2][0] = r0; bh[np * 2][1] = r1;
                bh[np * 2 + 1][0] = r2; bh[np * 2 + 1][1] = r3;
            }
#pragma unroll
            for (int mi = 0; mi < 4; mi++)
#pragma unroll
                for (int ni = 0; ni < 4; ni++)
                    mma16816(acc[mi][ni], ah[mi], bh[ni]);
        }
        __syncthreads();
    }
#undef PREFETCH

    int l4 = lane >> 2, l2 = (lane & 3) << 1;
#pragma unroll
    for (int mi = 0; mi < 4; mi++) {
        int r0 = bm * 128 + wm * 64 + mi * 16 + l4;
        int sr0 = (EPI == 4) ? scatter_perm(r0) : r0;
        int sr1 = (EPI == 4) ? scatter_perm(r0 + 8) : r0 + 8;
#pragma unroll
        for (int ni = 0; ni < 4; ni++) {
            int cc = bn * 128 + wn * 32 + ni * 8 + l2;
            float b0 = bias[cc], b1 = bias[cc + 1];
            float v00 = acc[mi][ni][0] + b0, v01 = acc[mi][ni][1] + b1;
            float v10 = acc[mi][ni][2] + b0, v11 = acc[mi][ni][3] + b1;
            size_t o0 = (size_t)r0 * ldc + cc;
            size_t o1 = (size_t)(r0 + 8) * ldc + cc;
            if (EPI == 1) {
                const float is2 = 0.7071067811865476f;
                float g00 = 0.5f * v00 * (1.f + erff(v00 * is2));
                float g01 = 0.5f * v01 * (1.f + erff(v01 * is2));
                float g10 = 0.5f * v10 * (1.f + erff(v10 * is2));
                float g11 = 0.5f * v11 * (1.f + erff(v11 * is2));
                *(uint32_t*)(Oh + o0) = packh2(g00, g01);
                *(uint32_t*)(Oh + o1) = packh2(g10, g11);
            } else if (EPI == 3) {
                *(uint32_t*)(Oh + o0) = packh2(v00, v01);
                *(uint32_t*)(Oh + o1) = packh2(v10, v11);
            } else {
                if (EPI == 2 || EPI == 4) {
                    float2 ra = *(const float2*)(res + o0);
                    float2 rb = *(const float2*)(res + o1);
                    v00 += ra.x; v01 += ra.y; v10 += rb.x; v11 += rb.y;
                }
                *(float2*)(Cp + (size_t)sr0 * ldc + cc) = make_float2(v00, v01);
                *(float2*)(Cp + (size_t)sr1 * ldc + cc) = make_float2(v10, v11);
            }
        }
    }
}

// ---------------------------------------------------------------------------
// Tensor-core flash attention (no-max softmax), dual-problem.
// ---------------------------------------------------------------------------
__global__ void __launch_bounds__(256)
attn_mma_kernel(const __half* qkv, __half* out,
                const __half* qkv2, __half* out2, int ctaSplit) {
    extern __shared__ char smc[];
    const uint32_t sb = smem_u32(smc);
    const uint32_t sbQ = sb, sbK = sb + 256 * ATTN_ROWB, sbV = sb + 512 * ATTN_ROWB;
    int cta = blockIdx.x;
    if (cta >= ctaSplit) { cta -= ctaSplit; qkv = qkv2; out = out2; }
    int win = cta >> 3, head = cta & 7;
    int tid = threadIdx.x, lane = tid & 31, wid = tid >> 5;

    {
        const uint4* src = (const uint4*)(qkv + ((size_t)(win * 256 + tid) * 768 + head * 32));
        uint4* dq = (uint4*)(smc + tid * ATTN_ROWB);
        uint4* dk = (uint4*)(smc + 256 * ATTN_ROWB + tid * ATTN_ROWB);
        uint4* dv = (uint4*)(smc + 512 * ATTN_ROWB + tid * ATTN_ROWB);
#pragma unroll
        for (int c = 0; c < 4; c++) dq[c] = src[c];
#pragma unroll
        for (int c = 0; c < 4; c++) dk[c] = src[32 + c];
#pragma unroll
        for (int c = 0; c < 4; c++) dv[c] = src[64 + c];
    }
    __syncthreads();

    uint32_t aq[2][2][4];
#pragma unroll
    for (int mi = 0; mi < 2; mi++)
#pragma unroll
        for (int kt = 0; kt < 2; kt++) {
            int row = wid * 32 + mi * 16 + (lane & 15);
            uint32_t addr = sbQ + row * ATTN_ROWB + (kt * 2 + (lane >> 4)) * 16;
            ldsm4(aq[mi][kt][0], aq[mi][kt][1], aq[mi][kt][2], aq[mi][kt][3], addr);
        }

    float o[2][4][4];
#pragma unroll
    for (int mi = 0; mi < 2; mi++)
#pragma unroll
        for (int ni = 0; ni < 4; ni++)
#pragma unroll
            for (int r = 0; r < 4; r++) o[mi][ni][r] = 0.f;
    float l[2][2] = {{0.f, 0.f}, {0.f, 0.f}};
    const float sc = 0.17677669529663687f * 1.4426950408889634f;

    for (int kc = 0; kc < 4; kc++) {
        float s[2][8][4];
#pragma unroll
        for (int mi = 0; mi < 2; mi++)
#pragma unroll
            for (int ni = 0; ni < 8; ni++)
#pragma unroll
                for (int r = 0; r < 4; r++) s[mi][ni][r] = 0.f;

#pragma unroll
        for (int nt = 0; nt < 4; nt++) {
            int keyrow = kc * 64 + nt * 16 + (lane & 15);
#pragma unroll
            for (int kt = 0; kt < 2; kt++) {
                uint32_t addr = sbK + keyrow * ATTN_ROWB + (kt * 2 + (lane >> 4)) * 16;
                uint32_t r0, r1, r2, r3;
                ldsm4(r0, r1, r2, r3, addr);
                uint32_t blo[2] = {r0, r2}, bhi[2] = {r1, r3};
#pragma unroll
                for (int mi = 0; mi < 2; mi++) {
                    mma16816(s[mi][nt * 2],     aq[mi][kt], blo);
                    mma16816(s[mi][nt * 2 + 1], aq[mi][kt], bhi);
                }
            }
        }

#pragma unroll
        for (int mi = 0; mi < 2; mi++)
#pragma unroll
            for (int ni = 0; ni < 8; ni++) {
                float p0 = exp2f(s[mi][ni][0] * sc);
                float p1 = exp2f(s[mi][ni][1] * sc);
                float p2 = exp2f(s[mi][ni][2] * sc);
                float p3 = exp2f(s[mi][ni][3] * sc);
                s[mi][ni][0] = p0; s[mi][ni][1] = p1;
                s[mi][ni][2] = p2; s[mi][ni][3] = p3;
                l[mi][0] += p0 + p1;
                l[mi][1] += p2 + p3;
            }

        uint32_t pa[2][4][4];
#pragma unroll
        for (int mi = 0; mi < 2; mi++)
#pragma unroll
            for (int kt = 0; kt < 4; kt++) {
                pa[mi][kt][0] = packh2(s[mi][kt * 2][0], s[mi][kt * 2][1]);
                pa[mi][kt][1] = packh2(s[mi][kt * 2][2], s[mi][kt * 2][3]);
                pa[mi][kt][2] = packh2(s[mi][kt * 2 + 1][0], s[mi][kt * 2 + 1][1]);
                pa[mi][kt][3] = packh2(s[mi][kt * 2 + 1][2], s[mi][kt * 2 + 1][3]);
            }

#pragma unroll
        for (int kt = 0; kt < 4; kt++) {
            int keyrow = kc * 64 + kt * 16 + (lane & 15);
#pragma unroll
            for (int dc = 0; dc < 2; dc++) {
                uint32_t addr = sbV + keyrow * ATTN_ROWB + (dc * 2 + (lane >> 4)) * 16;
                uint32_t r0, r1, r2, r3;
                ldsm4t(r0, r1, r2, r3, addr);
                uint32_t b0[2] = {r0, r1}, b1[2] = {r2, r3};
#pragma unroll
                for (int mi = 0; mi < 2; mi++) {
                    mma16816(o[mi][dc * 2],     pa[mi][kt], b0);
                    mma16816(o[mi][dc * 2 + 1], pa[mi][kt], b1);
                }
            }
        }
    }

#pragma unroll
    for (int mi = 0; mi < 2; mi++)
#pragma unroll
        for (int h = 0; h < 2; h++) {
            float v = l[mi][h];
            v += __shfl_xor_sync(0xffffffffu, v, 1);
            v += __shfl_xor_sync(0xffffffffu, v, 2);
            l[mi][h] = v;
        }

    int l4 = lane >> 2, l2 = (lane & 3) << 1;
#pragma unroll
    for (int mi = 0; mi < 2; mi++)
#pragma unroll
        for (int h = 0; h < 2; h++) {
            float inv = 1.f / l[mi][h];
            int row = wid * 32 + mi * 16 + l4 + h * 8;
            size_t ob = ((size_t)(win * 256 + row)) * 256 + head * 32;
#pragma unroll
            for (int ni = 0; ni < 4; ni++) {
                *(uint32_t*)(out + ob + ni * 8 + l2) =
                    packh2(o[mi][ni][h * 2] * inv, o[mi][ni][h * 2 + 1] * inv);
            }
        }
}

// ---------------------------------------------------------------------------
// Cross attention: 1 query x 16 keys, warp per head; fp16 Q and KV
// ---------------------------------------------------------------------------
__global__ void __launch_bounds__(256)
cross_attn_kernel(const __half* __restrict__ Q, const __half* __restrict__ KV,
                  __half* __restrict__ oh) {
    int g = blockIdx.x;
    int head = threadIdx.x >> 5, lane = threadIdx.x & 31;
    float qd = __half2float(Q[(size_t)g * 256 + head * 32 + lane]);
    size_t kvbase = (size_t)g * 16 * 512 + head * 32 + lane;
    const float sc = 0.17677669529663687f * 1.4426950408889634f;
    float s[16];
#pragma unroll
    for (int j = 0; j < 16; j++) {
        float p = qd * __half2float(KV[kvbase + (size_t)j * 512]);
#pragma unroll
        for (int o = 16; o; o >>= 1) p += __shfl_xor_sync(0xffffffffu, p, o);
        s[j] = p * sc;
    }
    float l = 0.f;
#pragma unroll
    for (int j = 0; j < 16; j++) { s[j] = exp2f(s[j]); l += s[j]; }
    float inv = 1.f / l, acc = 0.f;
#pragma unroll
    for (int j = 0; j < 16; j++)
        acc = fmaf(s[j], __half2float(KV[kvbase + 256 + (size_t)j * 512]), acc);
    oh[(size_t)g * 256 + head * 32 + lane] = __float2half(acc * inv);
}

// ---------------------------------------------------------------------------
// Host launch
// ---------------------------------------------------------------------------
extern "C" void kernel_launch(void* const* d_in, const int* in_sizes, int n_in,
                              void* d_out, int out_size) {
    const float* scale0 = (const float*)d_in[0];
    const float* scale1 = (const float*)d_in[1];
    const float* pe_w1  = (const float*)d_in[2];
    const float* pe_b1  = (const float*)d_in[3];
    const float* pe_w2  = (const float*)d_in[4];
    const float* ln1_g  = (const float*)d_in[5];
    const float* ln1_b  = (const float*)d_in[6];
    const float* wqkv   = (const float*)d_in[7];
    const float* bqkv   = (const float*)d_in[8];
    const float* wo     = (const float*)d_in[9];
    const float* bo     = (const float*)d_in[10];
    const float* ln2_g  = (const float*)d_in[11];
    const float* ln2_b  = (const float*)d_in[12];
    const float* mw1    = (const float*)d_in[13];
    const float* mb1    = (const float*)d_in[14];
    const float* mw2    = (const float*)d_in[15];
    const float* mb2    = (const float*)d_in[16];
    float* out = (float*)d_out;

    float *PE, *X0, *X1, *G;
    __half *Qbh, *QKVh, *QKVc, *A, *Ac, *H1, *H1c, *A3;
    __half *WqkvT, *WoT, *W1T, *W2T;
    cudaGetSymbolAddress((void**)&PE,   g_PE);
    cudaGetSymbolAddress((void**)&X0,   g_X0);
    cudaGetSymbolAddress((void**)&X1,   g_X1);
    cudaGetSymbolAddress((void**)&G,    g_G);
    cudaGetSymbolAddress((void**)&Qbh,  g_Qbh);
    cudaGetSymbolAddress((void**)&QKVh, g_QKVh);
    cudaGetSymbolAddress((void**)&QKVc, g_QKVc);
    cudaGetSymbolAddress((void**)&A,    g_A);
    cudaGetSymbolAddress((void**)&Ac,   g_Ac);
    cudaGetSymbolAddress((void**)&H1,   g_H1);
    cudaGetSymbolAddress((void**)&H1c,  g_H1c);
    cudaGetSymbolAddress((void**)&A3,   g_A3);
    cudaGetSymbolAddress((void**)&WqkvT, g_WqkvT);
    cudaGetSymbolAddress((void**)&WoT,   g_WoT);
    cudaGetSymbolAddress((void**)&W1T,   g_W1T);
    cudaGetSymbolAddress((void**)&W2T,   g_W2T);

    cudaFuncSetAttribute(attn_mma_kernel, cudaFuncAttributeMaxDynamicSharedMemorySize, ATTN_SMEM);
    cudaFuncSetAttribute(gemm_mma<1>, cudaFuncAttributeMaxDynamicSharedMemorySize, GEMM_SMEM);
    cudaFuncSetAttribute(gemm_mma<2>, cudaFuncAttributeMaxDynamicSharedMemorySize, GEMM_SMEM);
    cudaFuncSetAttribute(gemm_mma<3>, cudaFuncAttributeMaxDynamicSharedMemorySize, GEMM_SMEM);
    cudaFuncSetAttribute(gemm_mma<4>, cudaFuncAttributeMaxDynamicSharedMemorySize, GEMM_SMEM);

    // 0) weights + position embeddings
    wconv_all_kernel<<<4608, 256>>>(wqkv, wo, mw1, mw2, WqkvT, WoT, W1T, W2T);
    posemb_kernel<<<512, 256>>>(pe_w1, pe_b1, pe_w2, PE);

    // 1) inputs with fused LN1
    add_pe0_ln_kernel<<<T0 / 8, 256>>>(scale0, PE, X0, A, ln1_g, ln1_b);
    pool_add_ln_kernel<<<T1 / 8, 256>>>(scale1, PE, X0, X1, Ac,
                                        ln1_g + 256, ln1_b + 256);

    // 2) self-attention blocks, fine+coarse fused per launch
    gemm_mma<3><<<dim3(6, 512 + 32), 256, GEMM_SMEM>>>(
        A, WqkvT, bqkv, nullptr, nullptr, QKVh,
        Ac, WqkvT + 196608, bqkv + 768, nullptr, nullptr, QKVc,
        512, 256, 768, 768, 6);
    attn_mma_kernel<<<NWIN0 * 8 + NWIN1 * 8, 256, ATTN_SMEM>>>(
        QKVh, A, QKVc, Ac, NWIN0 * 8);
    gemm_mma<2><<<dim3(2, 512 + 32), 256, GEMM_SMEM>>>(
        A, WoT, bo, X0, X0, nullptr,
        Ac, WoT + 65536, bo + 256, X1, X1, nullptr,
        512, 256, 256, 256, 2);
    ln_half_kernel<<<T0 / 8 + T1 / 8, 256>>>(
        X0, A, ln2_g, ln2_b, X1, Ac, ln2_g + 256, ln2_b + 256, T0 / 8);
    gemm_mma<1><<<dim3(8, 512 + 32), 256, GEMM_SMEM>>>(
        A, W1T, mb1, nullptr, nullptr, H1,
        Ac, W1T + 262144, mb1 + 1024, nullptr, nullptr, H1c,
        512, 256, 1024, 1024, 8);
    gemm_mma<2><<<dim3(2, 512 + 32), 256, GEMM_SMEM>>>(
        H1, W2T, mb2, X0, out, nullptr,
        H1c, W2T + 262144, mb2 + 256, X1, X1, nullptr,
        512, 1024, 256, 256, 2);

    // 3) one2one cross-attention aggregation (scale-1 weights)
    // fused fine-perm LN (KV input) + coarse gather LN (Q input)
    ln_pre_cross_kernel<<<T0 / 8 + T1 / 8, 256>>>(
        out, A, X1, G, A3, ln1_g + 256, ln1_b + 256, T0 / 8);
    // fused KV GEMM (fine, N=512) + Q GEMM (coarse, N=256, bn<2)
    gemm_mma<3><<<dim3(4, 512 + 32), 256, GEMM_SMEM>>>(
        A, WqkvT + 196608 + 65536, bqkv + 768 + 256, nullptr, nullptr, QKVh,
        A3, WqkvT + 196608, bqkv + 768, nullptr, nullptr, Qbh,
        512, 256, 512, 256, 2);
    cross_attn_kernel<<<T1, 256>>>(Qbh, QKVh, A3);
    gemm_mma<2><<<dim3(2, 32), 256, GEMM_SMEM>>>(
        A3, WoT + 65536, bo + 256, G, G, nullptr,
        A3, WoT + 65536, bo + 256, G, G, nullptr, 32, 256, 256, 256, 2);
    ln_half_kernel<<<T1 / 8, 256>>>(
        G, A3, ln2_g + 256, ln2_b + 256,
        G, A3, ln2_g + 256, ln2_b + 256, T1 / 8);
    gemm_mma<1><<<dim3(8, 32), 256, GEMM_SMEM>>>(
        A3, W1T + 262144, mb1 + 1024, nullptr, nullptr, H1,
        A3, W1T + 262144, mb1 + 1024, nullptr, nullptr, H1, 32, 256, 1024, 1024, 8);
    // MLP2 + residual, written directly to out1 at scatter_perm(row)
    gemm_mma<4><<<dim3(2, 32), 256, GEMM_SMEM>>>(
        H1, W2T + 262144, mb2 + 256, G, out + (size_t)NWIN0 * 256 * 256, nullptr,
        H1, W2T + 262144, mb2 + 256, G, out + (size_t)NWIN0 * 256 * 256, nullptr,
        32, 1024, 256, 256, 2);
}

// round 13
// speedup vs baseline: 1.1366x; 1.0073x over previous
#include <cuda_runtime.h>
#include <cuda_fp16.h>
#include <cstdint>
#include <cstddef>

// ---------------------------------------------------------------------------
// Dimensions: B=4, H=W=8, M=16, C=256, NH=8, HD=32, GW=2
// ---------------------------------------------------------------------------
#define T0      65536
#define T1      4096
#define NWIN0   256
#define NWIN1   16

#define TILE_BYTES 16384
#define BUF_BYTES  (2 * TILE_BYTES)
#define GEMM_SMEM  (3 * BUF_BYTES)

#define ATTN_ROWB  80
#define ATTN_SMEM  (3 * 256 * ATTN_ROWB)

// ---------------------------------------------------------------------------
// PTX helpers
// ---------------------------------------------------------------------------
__device__ __forceinline__ uint32_t smem_u32(const void* p) {
    uint32_t a;
    asm("{ .reg .u64 t; cvta.to.shared.u64 t, %1; cvt.u32.u64 %0, t; }" : "=r"(a) : "l"(p));
    return a;
}
__device__ __forceinline__ void cp16(uint32_t dst, const void* src) {
    asm volatile("cp.async.cg.shared.global [%0], [%1], 16;" :: "r"(dst), "l"(src) : "memory");
}
#define CP_COMMIT() asm volatile("cp.async.commit_group;" ::: "memory")
#define CP_WAIT2()  asm volatile("cp.async.wait_group 2;" ::: "memory")
#define CP_WAIT1()  asm volatile("cp.async.wait_group 1;" ::: "memory")
#define CP_WAIT0()  asm volatile("cp.async.wait_group 0;" ::: "memory")

__device__ __forceinline__ void ldsm4(uint32_t& r0, uint32_t& r1, uint32_t& r2,
                                      uint32_t& r3, uint32_t addr) {
    asm volatile("ldmatrix.sync.aligned.m8n8.x4.shared.b16 {%0,%1,%2,%3}, [%4];"
                 : "=r"(r0), "=r"(r1), "=r"(r2), "=r"(r3) : "r"(addr));
}
__device__ __forceinline__ void ldsm4t(uint32_t& r0, uint32_t& r1, uint32_t& r2,
                                       uint32_t& r3, uint32_t addr) {
    asm volatile("ldmatrix.sync.aligned.m8n8.x4.trans.shared.b16 {%0,%1,%2,%3}, [%4];"
                 : "=r"(r0), "=r"(r1), "=r"(r2), "=r"(r3) : "r"(addr));
}
__device__ __forceinline__ void mma16816(float* c, const uint32_t* a, const uint32_t* b) {
    asm volatile(
        "mma.sync.aligned.m16n8k16.row.col.f32.f16.f16.f32 "
        "{%0,%1,%2,%3}, {%4,%5,%6,%7}, {%8,%9}, {%0,%1,%2,%3};"
        : "+f"(c[0]), "+f"(c[1]), "+f"(c[2]), "+f"(c[3])
        : "r"(a[0]), "r"(a[1]), "r"(a[2]), "r"(a[3]), "r"(b[0]), "r"(b[1]));
}
__device__ __forceinline__ uint32_t packh2(float a, float b) {
    __half2 h = __floats2half2_rn(a, b);
    return *(uint32_t*)&h;
}
__device__ __forceinline__ float2 unpackh2(uint32_t u) {
    return __half22float2(*(__half2*)&u);
}

// Row-level permutation: gidx -> o1-row
__device__ __forceinline__ int scatter_perm(int g) {
    int rr = g & 15, r1 = rr >> 2, r2 = rr & 3;
    int bhw = g >> 4;
    int w = bhw & 7, h = (bhw >> 3) & 7, b = bhw >> 6;
    int R = h * 4 + r1, Cc = w * 4 + r2;
    return (((b * 2 + (R >> 4)) * 2 + (Cc >> 4)) << 8) + (R & 15) * 16 + (Cc & 15);
}

// ---------------------------------------------------------------------------
// Scratch (residual streams now fp16)
// ---------------------------------------------------------------------------
__device__ float g_PE [2 * 256 * 256];
__device__ __half g_X0h[(size_t)T0 * 256];
__device__ __half g_X1h[(size_t)T1 * 256];
__device__ __half g_Gh [(size_t)T1 * 256];
__device__ __half g_Qbh[(size_t)T1 * 256];
__device__ __half g_QKVh[(size_t)T0 * 768];
__device__ __half g_QKVc[(size_t)T1 * 768];
__device__ __half g_A  [(size_t)T0 * 256];
__device__ __half g_Ac [(size_t)T1 * 256];
__device__ __half g_H1 [(size_t)T0 * 1024];
__device__ __half g_H1c[(size_t)T1 * 1024];
__device__ __half g_A3 [(size_t)T1 * 256];
__device__ __half g_WqkvT[2 * 768 * 256];
__device__ __half g_WoT  [2 * 256 * 256];
__device__ __half g_W1T  [2 * 1024 * 256];
__device__ __half g_W2T  [2 * 256 * 1024];

// ---------------------------------------------------------------------------
// Elementwise helpers: contiguous 8 channels per lane (ch 8l..8l+7)
// ---------------------------------------------------------------------------
__device__ __forceinline__ void load8h(const __half* row, int lane,
                                       float4& v0, float4& v1) {
    uint4 u = ((const uint4*)row)[lane];
    float2 f0 = unpackh2(u.x), f1 = unpackh2(u.y);
    float2 f2 = unpackh2(u.z), f3 = unpackh2(u.w);
    v0 = make_float4(f0.x, f0.y, f1.x, f1.y);
    v1 = make_float4(f2.x, f2.y, f3.x, f3.y);
}
__device__ __forceinline__ void store8h(__half* row, int lane, float4 v0, float4 v1) {
    uint4 u;
    u.x = packh2(v0.x, v0.y); u.y = packh2(v0.z, v0.w);
    u.z = packh2(v1.x, v1.y); u.w = packh2(v1.z, v1.w);
    ((uint4*)row)[lane] = u;
}
// warp-per-token LN over (v0,v1) with contiguous-8 layout, fp16 out.
__device__ __forceinline__ void ln_store8(float4 v0, float4 v1, int lane,
                                          const float* __restrict__ gamma,
                                          const float* __restrict__ beta,
                                          __half* __restrict__ orow) {
    float s = v0.x + v0.y + v0.z + v0.w + v1.x + v1.y + v1.z + v1.w;
#pragma unroll
    for (int d = 16; d; d >>= 1) s += __shfl_xor_sync(0xffffffffu, s, d);
    float mean = s * (1.f / 256.f);
    float d0x = v0.x - mean, d0y = v0.y - mean, d0z = v0.z - mean, d0w = v0.w - mean;
    float d1x = v1.x - mean, d1y = v1.y - mean, d1z = v1.z - mean, d1w = v1.w - mean;
    float q = d0x*d0x + d0y*d0y + d0z*d0z + d0w*d0w +
              d1x*d1x + d1y*d1y + d1z*d1z + d1w*d1w;
#pragma unroll
    for (int d = 16; d; d >>= 1) q += __shfl_xor_sync(0xffffffffu, q, d);
    float rstd = rsqrtf(q * (1.f / 256.f) + 1e-5f);
    float4 g0 = ((const float4*)gamma)[2 * lane], g1 = ((const float4*)gamma)[2 * lane + 1];
    float4 b0 = ((const float4*)beta)[2 * lane],  b1 = ((const float4*)beta)[2 * lane + 1];
    uint4 u;
    u.x = packh2(fmaf(d0x * rstd, g0.x, b0.x), fmaf(d0y * rstd, g0.y, b0.y));
    u.y = packh2(fmaf(d0z * rstd, g0.z, b0.z), fmaf(d0w * rstd, g0.w, b0.w));
    u.z = packh2(fmaf(d1x * rstd, g1.x, b1.x), fmaf(d1y * rstd, g1.y, b1.y));
    u.w = packh2(fmaf(d1z * rstd, g1.z, b1.z), fmaf(d1w * rstd, g1.w, b1.w));
    ((uint4*)orow)[lane] = u;
}

// ---------------------------------------------------------------------------
// Small kernels
// ---------------------------------------------------------------------------
__global__ void posemb_kernel(const float* __restrict__ pe_w1,
                              const float* __restrict__ pe_b1,
                              const float* __restrict__ pe_w2,
                              float* __restrict__ PE) {
    int s = blockIdx.x >> 8;
    int n = blockIdx.x & 255;
    int i = n >> 4, j = n & 15;
    float cy = (i - 8) * 0.125f;
    float cx = (j - 8) * 0.125f;
    __shared__ float hid[512];
    const float* w1 = pe_w1 + s * 2 * 512;
    const float* b1 = pe_b1 + s * 512;
    for (int k = threadIdx.x; k < 512; k += 256)
        hid[k] = fmaxf(0.f, fmaf(cy, w1[k], fmaf(cx, w1[512 + k], b1[k])));
    __syncthreads();
    const float* w2 = pe_w2 + (size_t)s * 512 * 256;
    int c = threadIdx.x;
    float acc = 0.f;
#pragma unroll 8
    for (int k = 0; k < 512; k++) acc = fmaf(hid[k], w2[(size_t)k * 256 + c], acc);
    PE[((size_t)s * 256 + n) * 256 + c] = acc;
}

// X0h = fp16(scale0 + PE[0]);  A = LN1(X0).  Warp per token.
__global__ void __launch_bounds__(256)
add_pe0_ln_kernel(const float* __restrict__ s0, const float* __restrict__ PE,
                  __half* __restrict__ X0h, __half* __restrict__ A,
                  const float* __restrict__ gamma, const float* __restrict__ beta) {
    int token = blockIdx.x * 8 + (threadIdx.x >> 5);
    int lane = threadIdx.x & 31;
    const float4* sr = (const float4*)(s0 + (size_t)token * 256);
    const float4* pr = (const float4*)(PE + (size_t)(token & 255) * 256);
    float4 v0 = sr[2 * lane], v1 = sr[2 * lane + 1];
    float4 p0 = pr[2 * lane], p1 = pr[2 * lane + 1];
    v0.x += p0.x; v0.y += p0.y; v0.z += p0.z; v0.w += p0.w;
    v1.x += p1.x; v1.y += p1.y; v1.z += p1.z; v1.w += p1.w;
    store8h(X0h + (size_t)token * 256, lane, v0, v1);
    ln_store8(v0, v1, lane, gamma, beta, A + (size_t)token * 256);
}

// X1h = fp16(scale1 + PE[1] + maxpool(X0h));  Ac = LN1(X1).
__global__ void __launch_bounds__(256)
pool_add_ln_kernel(const float* __restrict__ s1, const float* __restrict__ PE,
                   const __half* __restrict__ X0h, __half* __restrict__ X1h,
                   __half* __restrict__ Ac,
                   const float* __restrict__ gamma, const float* __restrict__ beta) {
    int token = blockIdx.x * 8 + (threadIdx.x >> 5);
    int lane = threadIdx.x & 31;
    int t  = token & 255;
    int gw = token >> 8;
    int b = gw >> 2, gi = (gw >> 1) & 1, gj = gw & 1;
    int ti = t >> 4, tj = t & 15;
    int R  = gi * 16 + ti, Cc = gj * 16 + tj;
    int h = R >> 2, r1 = R & 3, w = Cc >> 2, r2 = Cc & 3;
    int fw = b * 64 + h * 8 + w;
    float4 m0 = make_float4(-1e30f, -1e30f, -1e30f, -1e30f), m1 = m0;
#pragma unroll
    for (int p1 = 0; p1 < 4; p1++)
#pragma unroll
        for (int p2 = 0; p2 < 4; p2++) {
            int n = (r1 * 4 + p1) * 16 + r2 * 4 + p2;
            float4 a, c;
            load8h(X0h + ((size_t)fw * 256 + n) * 256, lane, a, c);
            m0.x = fmaxf(m0.x, a.x); m0.y = fmaxf(m0.y, a.y);
            m0.z = fmaxf(m0.z, a.z); m0.w = fmaxf(m0.w, a.w);
            m1.x = fmaxf(m1.x, c.x); m1.y = fmaxf(m1.y, c.y);
            m1.z = fmaxf(m1.z, c.z); m1.w = fmaxf(m1.w, c.w);
        }
    const float4* sr = (const float4*)(s1 + (size_t)token * 256);
    const float4* pr = (const float4*)(PE + (size_t)(256 + t) * 256);
    float4 s0v = sr[2 * lane], s1v = sr[2 * lane + 1];
    float4 p0 = pr[2 * lane], p1v = pr[2 * lane + 1];
    m0.x += s0v.x + p0.x; m0.y += s0v.y + p0.y;
    m0.z += s0v.z + p0.z; m0.w += s0v.w + p0.w;
    m1.x += s1v.x + p1v.x; m1.y += s1v.y + p1v.y;
    m1.z += s1v.z + p1v.z; m1.w += s1v.w + p1v.w;
    store8h(X1h + (size_t)token * 256, lane, m0, m1);
    ln_store8(m0, m1, lane, gamma, beta, Ac + (size_t)token * 256);
}

// Dual LN over fp16 inputs.
__global__ void __launch_bounds__(256)
ln_half_h_kernel(const __half* __restrict__ x, __half* __restrict__ o,
                 const float* __restrict__ gamma, const float* __restrict__ beta,
                 const __half* __restrict__ x2, __half* __restrict__ o2,
                 const float* __restrict__ gamma2, const float* __restrict__ beta2,
                 int split) {
    int blk = blockIdx.x;
    const __half* xp = x; __half* op = o;
    const float* gp = gamma; const float* bp = beta;
    if (blk >= split) { blk -= split; xp = x2; op = o2; gp = gamma2; bp = beta2; }
    int token = blk * 8 + (threadIdx.x >> 5);
    int lane = threadIdx.x & 31;
    float4 v0, v1;
    load8h(xp + (size_t)token * 256, lane, v0, v1);
    ln_store8(v0, v1, lane, gp, bp, op + (size_t)token * 256);
}

// Combined pre-cross LN:
//  blocks [0, split): fine-perm LN of o0 (fp32) -> Afine (KV input)
//  blocks [split, ..): coarse gather X1h -> Gh (copy) + LN -> A3 (Q input)
__global__ void __launch_bounds__(256)
ln_pre_cross_kernel(const float* __restrict__ o0, __half* __restrict__ Afine,
                    const __half* __restrict__ X1h, __half* __restrict__ Gh,
                    __half* __restrict__ A3,
                    const float* __restrict__ gamma, const float* __restrict__ beta,
                    int split) {
    int blk = blockIdx.x;
    int lane = threadIdx.x & 31;
    if (blk < split) {
        int fidx = blk * 8 + (threadIdx.x >> 5);
        int pp = fidx & 15, p1 = pp >> 2, p2 = pp & 3;
        int grp = fidx >> 4;
        int rr = grp & 15, r1 = rr >> 2, r2 = rr & 3;
        int bhw = grp >> 4;
        int w = bhw & 7, h = (bhw >> 3) & 7, b = bhw >> 6;
        int fw = b * 64 + h * 8 + w;
        int n = (r1 * 4 + p1) * 16 + r2 * 4 + p2;
        const float4* xr = (const float4*)(o0 + ((size_t)fw * 256 + n) * 256);
        ln_store8(xr[2 * lane], xr[2 * lane + 1], lane, gamma, beta,
                  Afine + (size_t)fidx * 256);
    } else {
        int gidx = (blk - split) * 8 + (threadIdx.x >> 5);
        int rr = gidx & 15, r1 = rr >> 2, r2 = rr & 3;
        int bhw = gidx >> 4;
        int w = bhw & 7, h = (bhw >> 3) & 7, b = bhw >> 6;
        int R = h * 4 + r1, Cc = w * 4 + r2;
        int gi = R >> 4, ti = R & 15, gj = Cc >> 4, tj = Cc & 15;
        int win = (b * 2 + gi) * 2 + gj, tok = ti * 16 + tj;
        const __half* src = X1h + ((size_t)win * 256 + tok) * 256;
        uint4 raw = ((const uint4*)src)[lane];
        ((uint4*)(Gh + (size_t)gidx * 256))[lane] = raw;  // exact copy
        float4 v0, v1;
        load8h(src, lane, v0, v1);
        ln_store8(v0, v1, lane, gamma, beta, A3 + (size_t)gidx * 256);
    }
}

__global__ void wconv_all_kernel(const float* __restrict__ wqkv,
                                 const float* __restrict__ wo,
                                 const float* __restrict__ mw1,
                                 const float* __restrict__ mw2,
                                 __half* __restrict__ Tqkv, __half* __restrict__ To,
                                 __half* __restrict__ Tm1,  __half* __restrict__ Tm2) {
    int bid = blockIdx.x;
    int s = bid / 2304, r = bid % 2304;
    const float* W; __half* T; int K, N, n;
    if (r < 768)       { W = wqkv + (size_t)s * 196608; T = Tqkv + (size_t)s * 196608; K = 256;  N = 768;  n = r; }
    else if (r < 1024) { W = wo   + (size_t)s * 65536;  T = To   + (size_t)s * 65536;  K = 256;  N = 256;  n = r - 768; }
    else if (r < 2048) { W = mw1  + (size_t)s * 262144; T = Tm1  + (size_t)s * 262144; K = 256;  N = 1024; n = r - 1024; }
    else               { W = mw2  + (size_t)s * 262144; T = Tm2  + (size_t)s * 262144; K = 1024; N = 256;  n = r - 2048; }
    for (int k = threadIdx.x; k < K; k += 256)
        T[(size_t)n * K + k] = __float2half(W[(size_t)k * N + n]);
}

// ---------------------------------------------------------------------------
// fp16 1-pass GEMM, dual-problem, runtime epilogue code per problem.
// epi 1: GELU -> Oh.  2: +resH -> Cp fp32.  3: -> Oh.
// epi 4: +resH -> Cp fp32 at scatter_perm(row).  5: +resH -> Oh fp16.
// ---------------------------------------------------------------------------
__global__ void __launch_bounds__(256)
gemm_mma(const __half* A, const __half* B,
         const float* bias, const __half* resH,
         float* Cp, __half* Oh, int epiA,
         const __half* A2, const __half* B2,
         const float* bias2, const __half* resH2,
         float* Cp2, __half* Oh2, int epiB,
         int bmSplit, int K, int ldc, int ldc2, int bn2Max) {
    extern __shared__ char smc[];
    const uint32_t sb = smem_u32(smc);
    int tid = threadIdx.x, lane = tid & 31, wid = tid >> 5;
    int wm = wid >> 2, wn = wid & 3;
    int bm = blockIdx.y, bn = blockIdx.x;
    int epi = epiA;
    if (bm >= bmSplit) {
        bm -= bmSplit;
        if (bn >= bn2Max) return;
        A = A2; B = B2; bias = bias2; resH = resH2; Cp = Cp2; Oh = Oh2;
        ldc = ldc2; epi = epiB;
    }

    const __half* src0 = A + (size_t)bm * 128 * K;
    const __half* src1 = B + (size_t)bn * 128 * K;

    int nc = K >> 6;
    int crow0 = tid >> 3, ccol = tid & 7;

#define PREFETCH(CH, BUF) do {                                                 \
    int _k0 = (CH) << 6;                                                       \
    const __half* _s[2] = {src0 + _k0, src1 + _k0};                            \
    _Pragma("unroll")                                                          \
    for (int _op = 0; _op < 2; _op++) {                                        \
        uint32_t _db = sb + (BUF) * BUF_BYTES + _op * TILE_BYTES;              \
        _Pragma("unroll")                                                      \
        for (int _i = 0; _i < 4; _i++) {                                       \
            int _row = crow0 + _i * 32;                                        \
            uint32_t _doff = _db + _row * 128 + ((ccol ^ (_row & 7)) << 4);    \
            cp16(_doff, _s[_op] + (size_t)_row * K + ccol * 8);                \
        }                                                                      \
    }                                                                          \
} while (0)

    float acc[4][4][4];
#pragma unroll
    for (int mi = 0; mi < 4; mi++)
#pragma unroll
        for (int ni = 0; ni < 4; ni++)
#pragma unroll
            for (int r = 0; r < 4; r++) acc[mi][ni][r] = 0.f;

    PREFETCH(0, 0);
    CP_COMMIT();
    if (nc > 1) { PREFETCH(1, 1); CP_COMMIT(); }

    int a_rl = lane & 15;
    int b_rl = ((lane >> 4) << 3) + (lane & 7);

    for (int ch = 0; ch < nc; ch++) {
        int buf = ch % 3;
        if (ch + 2 < nc) {
            PREFETCH(ch + 2, (ch + 2) % 3);
            CP_COMMIT();
            CP_WAIT2();
        } else if (ch + 1 < nc) {
            CP_WAIT1();
        } else {
            CP_WAIT0();
        }
        __syncthreads();

        uint32_t base = sb + buf * BUF_BYTES;
#pragma unroll
        for (int ks = 0; ks < 4; ks++) {
            uint32_t ah[4][4], bh[4][2];
            int achunk = ks * 2 + (lane >> 4);
            int bchunk = ks * 2 + ((lane >> 3) & 1);
#pragma unroll
            for (int mi = 0; mi < 4; mi++) {
                int row = wm * 64 + mi * 16 + a_rl;
                uint32_t off = (uint32_t)(row * 128 + ((achunk ^ (row & 7)) << 4));
                ldsm4(ah[mi][0], ah[mi][1], ah[mi][2], ah[mi][3], base + off);
            }
#pragma unroll
            for (int np = 0; np < 2; np++) {
                int row = wn * 32 + np * 16 + b_rl;
                uint32_t off = (uint32_t)(row * 128 + ((bchunk ^ (row & 7)) << 4));
                uint32_t r0, r1, r2, r3;
                ldsm4(r0, r1, r2, r3, base + TILE_BYTES + off);
                bh[np * 2][0] = r0; bh[np * 2][1] = r1;
                bh[np * 2 + 1][0] = r2; bh[np * 2 + 1][1] = r3;
            }
#pragma unroll
            for (int mi = 0; mi < 4; mi++)
#pragma unroll
                for (int ni = 0; ni < 4; ni++)
                    mma16816(acc[mi][ni], ah[mi], bh[ni]);
        }
        __syncthreads();
    }
#undef PREFETCH

    int l4 = lane >> 2, l2 = (lane & 3) << 1;
#pragma unroll
    for (int mi = 0; mi < 4; mi++) {
        int r0 = bm * 128 + wm * 64 + mi * 16 + l4;
        int sr0 = (epi == 4) ? scatter_perm(r0) : r0;
        int sr1 = (epi == 4) ? scatter_perm(r0 + 8) : r0 + 8;
#pragma unroll
        for (int ni = 0; ni < 4; ni++) {
            int cc = bn * 128 + wn * 32 + ni * 8 + l2;
            float b0 = bias[cc], b1 = bias[cc + 1];
            float v00 = acc[mi][ni][0] + b0, v01 = acc[mi][ni][1] + b1;
            float v10 = acc[mi][ni][2] + b0, v11 = acc[mi][ni][3] + b1;
            size_t o0 = (size_t)r0 * ldc + cc;
            size_t o1 = (size_t)(r0 + 8) * ldc + cc;
            if (epi == 1) {
                const float is2 = 0.7071067811865476f;
                float g00 = 0.5f * v00 * (1.f + erff(v00 * is2));
                float g01 = 0.5f * v01 * (1.f + erff(v01 * is2));
                float g10 = 0.5f * v10 * (1.f + erff(v10 * is2));
                float g11 = 0.5f * v11 * (1.f + erff(v11 * is2));
                *(uint32_t*)(Oh + o0) = packh2(g00, g01);
                *(uint32_t*)(Oh + o1) = packh2(g10, g11);
            } else if (epi == 3) {
                *(uint32_t*)(Oh + o0) = packh2(v00, v01);
                *(uint32_t*)(Oh + o1) = packh2(v10, v11);
            } else {
                float2 ra = unpackh2(*(const uint32_t*)(resH + o0));
                float2 rb = unpackh2(*(const uint32_t*)(resH + o1));
                v00 += ra.x; v01 += ra.y; v10 += rb.x; v11 += rb.y;
                if (epi == 5) {
                    *(uint32_t*)(Oh + o0) = packh2(v00, v01);
                    *(uint32_t*)(Oh + o1) = packh2(v10, v11);
                } else {
                    *(float2*)(Cp + (size_t)sr0 * ldc + cc) = make_float2(v00, v01);
                    *(float2*)(Cp + (size_t)sr1 * ldc + cc) = make_float2(v10, v11);
                }
            }
        }
    }
}

// ---------------------------------------------------------------------------
// Tensor-core flash attention (no-max softmax), dual-problem.
// ---------------------------------------------------------------------------
__global__ void __launch_bounds__(256)
attn_mma_kernel(const __half* qkv, __half* out,
                const __half* qkv2, __half* out2, int ctaSplit) {
    extern __shared__ char smc[];
    const uint32_t sb = smem_u32(smc);
    const uint32_t sbQ = sb, sbK = sb + 256 * ATTN_ROWB, sbV = sb + 512 * ATTN_ROWB;
    int cta = blockIdx.x;
    if (cta >= ctaSplit) { cta -= ctaSplit; qkv = qkv2; out = out2; }
    int win = cta >> 3, head = cta & 7;
    int tid = threadIdx.x, lane = tid & 31, wid = tid >> 5;

    {
        const uint4* src = (const uint4*)(qkv + ((size_t)(win * 256 + tid) * 768 + head * 32));
        uint4* dq = (uint4*)(smc + tid * ATTN_ROWB);
        uint4* dk = (uint4*)(smc + 256 * ATTN_ROWB + tid * ATTN_ROWB);
        uint4* dv = (uint4*)(smc + 512 * ATTN_ROWB + tid * ATTN_ROWB);
#pragma unroll
        for (int c = 0; c < 4; c++) dq[c] = src[c];
#pragma unroll
        for (int c = 0; c < 4; c++) dk[c] = src[32 + c];
#pragma unroll
        for (int c = 0; c < 4; c++) dv[c] = src[64 + c];
    }
    __syncthreads();

    uint32_t aq[2][2][4];
#pragma unroll
    for (int mi = 0; mi < 2; mi++)
#pragma unroll
        for (int kt = 0; kt < 2; kt++) {
            int row = wid * 32 + mi * 16 + (lane & 15);
            uint32_t addr = sbQ + row * ATTN_ROWB + (kt * 2 + (lane >> 4)) * 16;
            ldsm4(aq[mi][kt][0], aq[mi][kt][1], aq[mi][kt][2], aq[mi][kt][3], addr);
        }

    float o[2][4][4];
#pragma unroll
    for (int mi = 0; mi < 2; mi++)
#pragma unroll
        for (int ni = 0; ni < 4; ni++)
#pragma unroll
            for (int r = 0; r < 4; r++) o[mi][ni][r] = 0.f;
    float l[2][2] = {{0.f, 0.f}, {0.f, 0.f}};
    const float sc = 0.17677669529663687f * 1.4426950408889634f;

    for (int kc = 0; kc < 4; kc++) {
        float s[2][8][4];
#pragma unroll
        for (int mi = 0; mi < 2; mi++)
#pragma unroll
            for (int ni = 0; ni < 8; ni++)
#pragma unroll
                for (int r = 0; r < 4; r++) s[mi][ni][r] = 0.f;

#pragma unroll
        for (int nt = 0; nt < 4; nt++) {
            int keyrow = kc * 64 + nt * 16 + (lane & 15);
#pragma unroll
            for (int kt = 0; kt < 2; kt++) {
                uint32_t addr = sbK + keyrow * ATTN_ROWB + (kt * 2 + (lane >> 4)) * 16;
                uint32_t r0, r1, r2, r3;
                ldsm4(r0, r1, r2, r3, addr);
                uint32_t blo[2] = {r0, r2}, bhi[2] = {r1, r3};
#pragma unroll
                for (int mi = 0; mi < 2; mi++) {
                    mma16816(s[mi][nt * 2],     aq[mi][kt], blo);
                    mma16816(s[mi][nt * 2 + 1], aq[mi][kt], bhi);
                }
            }
        }

#pragma unroll
        for (int mi = 0; mi < 2; mi++)
#pragma unroll
            for (int ni = 0; ni < 8; ni++) {
                float p0 = exp2f(s[mi][ni][0] * sc);
                float p1 = exp2f(s[mi][ni][1] * sc);
                float p2 = exp2f(s[mi][ni][2] * sc);
                float p3 = exp2f(s[mi][ni][3] * sc);
                s[mi][ni][0] = p0; s[mi][ni][1] = p1;
                s[mi][ni][2] = p2; s[mi][ni][3] = p3;
                l[mi][0] += p0 + p1;
                l[mi][1] += p2 + p3;
            }

        uint32_t pa[2][4][4];
#pragma unroll
        for (int mi = 0; mi < 2; mi++)
#pragma unroll
            for (int kt = 0; kt < 4; kt++) {
                pa[mi][kt][0] = packh2(s[mi][kt * 2][0], s[mi][kt * 2][1]);
                pa[mi][kt][1] = packh2(s[mi][kt * 2][2], s[mi][kt * 2][3]);
                pa[mi][kt][2] = packh2(s[mi][kt * 2 + 1][0], s[mi][kt * 2 + 1][1]);
                pa[mi][kt][3] = packh2(s[mi][kt * 2 + 1][2], s[mi][kt * 2 + 1][3]);
            }

#pragma unroll
        for (int kt = 0; kt < 4; kt++) {
            int keyrow = kc * 64 + kt * 16 + (lane & 15);
#pragma unroll
            for (int dc = 0; dc < 2; dc++) {
                uint32_t addr = sbV + keyrow * ATTN_ROWB + (dc * 2 + (lane >> 4)) * 16;
                uint32_t r0, r1, r2, r3;
                ldsm4t(r0, r1, r2, r3, addr);
                uint32_t b0[2] = {r0, r1}, b1[2] = {r2, r3};
#pragma unroll
                for (int mi = 0; mi < 2; mi++) {
                    mma16816(o[mi][dc * 2],     pa[mi][kt], b0);
                    mma16816(o[mi][dc * 2 + 1], pa[mi][kt], b1);
                }
            }
        }
    }

#pragma unroll
    for (int mi = 0; mi < 2; mi++)
#pragma unroll
        for (int h = 0; h < 2; h++) {
            float v = l[mi][h];
            v += __shfl_xor_sync(0xffffffffu, v, 1);
            v += __shfl_xor_sync(0xffffffffu, v, 2);
            l[mi][h] = v;
        }

    int l4 = lane >> 2, l2 = (lane & 3) << 1;
#pragma unroll
    for (int mi = 0; mi < 2; mi++)
#pragma unroll
        for (int h = 0; h < 2; h++) {
            float inv = 1.f / l[mi][h];
            int row = wid * 32 + mi * 16 + l4 + h * 8;
            size_t ob = ((size_t)(win * 256 + row)) * 256 + head * 32;
#pragma unroll
            for (int ni = 0; ni < 4; ni++) {
                *(uint32_t*)(out + ob + ni * 8 + l2) =
                    packh2(o[mi][ni][h * 2] * inv, o[mi][ni][h * 2 + 1] * inv);
            }
        }
}

// ---------------------------------------------------------------------------
// Cross attention: 1 query x 16 keys, warp per head; fp16 Q and KV
// ---------------------------------------------------------------------------
__global__ void __launch_bounds__(256)
cross_attn_kernel(const __half* __restrict__ Q, const __half* __restrict__ KV,
                  __half* __restrict__ oh) {
    int g = blockIdx.x;
    int head = threadIdx.x >> 5, lane = threadIdx.x & 31;
    float qd = __half2float(Q[(size_t)g * 256 + head * 32 + lane]);
    size_t kvbase = (size_t)g * 16 * 512 + head * 32 + lane;
    const float sc = 0.17677669529663687f * 1.4426950408889634f;
    float s[16];
#pragma unroll
    for (int j = 0; j < 16; j++) {
        float p = qd * __half2float(KV[kvbase + (size_t)j * 512]);
#pragma unroll
        for (int o = 16; o; o >>= 1) p += __shfl_xor_sync(0xffffffffu, p, o);
        s[j] = p * sc;
    }
    float l = 0.f;
#pragma unroll
    for (int j = 0; j < 16; j++) { s[j] = exp2f(s[j]); l += s[j]; }
    float inv = 1.f / l, acc = 0.f;
#pragma unroll
    for (int j = 0; j < 16; j++)
        acc = fmaf(s[j], __half2float(KV[kvbase + 256 + (size_t)j * 512]), acc);
    oh[(size_t)g * 256 + head * 32 + lane] = __float2half(acc * inv);
}

// ---------------------------------------------------------------------------
// Host launch
// ---------------------------------------------------------------------------
extern "C" void kernel_launch(void* const* d_in, const int* in_sizes, int n_in,
                              void* d_out, int out_size) {
    const float* scale0 = (const float*)d_in[0];
    const float* scale1 = (const float*)d_in[1];
    const float* pe_w1  = (const float*)d_in[2];
    const float* pe_b1  = (const float*)d_in[3];
    const float* pe_w2  = (const float*)d_in[4];
    const float* ln1_g  = (const float*)d_in[5];
    const float* ln1_b  = (const float*)d_in[6];
    const float* wqkv   = (const float*)d_in[7];
    const float* bqkv   = (const float*)d_in[8];
    const float* wo     = (const float*)d_in[9];
    const float* bo     = (const float*)d_in[10];
    const float* ln2_g  = (const float*)d_in[11];
    const float* ln2_b  = (const float*)d_in[12];
    const float* mw1    = (const float*)d_in[13];
    const float* mb1    = (const float*)d_in[14];
    const float* mw2    = (const float*)d_in[15];
    const float* mb2    = (const float*)d_in[16];
    float* out = (float*)d_out;

    float* PE;
    __half *X0h, *X1h, *Gh, *Qbh, *QKVh, *QKVc, *A, *Ac, *H1, *H1c, *A3;
    __half *WqkvT, *WoT, *W1T, *W2T;
    cudaGetSymbolAddress((void**)&PE,   g_PE);
    cudaGetSymbolAddress((void**)&X0h,  g_X0h);
    cudaGetSymbolAddress((void**)&X1h,  g_X1h);
    cudaGetSymbolAddress((void**)&Gh,   g_Gh);
    cudaGetSymbolAddress((void**)&Qbh,  g_Qbh);
    cudaGetSymbolAddress((void**)&QKVh, g_QKVh);
    cudaGetSymbolAddress((void**)&QKVc, g_QKVc);
    cudaGetSymbolAddress((void**)&A,    g_A);
    cudaGetSymbolAddress((void**)&Ac,   g_Ac);
    cudaGetSymbolAddress((void**)&H1,   g_H1);
    cudaGetSymbolAddress((void**)&H1c,  g_H1c);
    cudaGetSymbolAddress((void**)&A3,   g_A3);
    cudaGetSymbolAddress((void**)&WqkvT, g_WqkvT);
    cudaGetSymbolAddress((void**)&WoT,   g_WoT);
    cudaGetSymbolAddress((void**)&W1T,   g_W1T);
    cudaGetSymbolAddress((void**)&W2T,   g_W2T);

    cudaFuncSetAttribute(attn_mma_kernel, cudaFuncAttributeMaxDynamicSharedMemorySize, ATTN_SMEM);
    cudaFuncSetAttribute(gemm_mma, cudaFuncAttributeMaxDynamicSharedMemorySize, GEMM_SMEM);

    // 0) weights + position embeddings
    wconv_all_kernel<<<4608, 256>>>(wqkv, wo, mw1, mw2, WqkvT, WoT, W1T, W2T);
    posemb_kernel<<<512, 256>>>(pe_w1, pe_b1, pe_w2, PE);

    // 1) inputs with fused LN1 (residual streams in fp16)
    add_pe0_ln_kernel<<<T0 / 8, 256>>>(scale0, PE, X0h, A, ln1_g, ln1_b);
    pool_add_ln_kernel<<<T1 / 8, 256>>>(scale1, PE, X0h, X1h, Ac,
                                        ln1_g + 256, ln1_b + 256);

    // 2) self-attention blocks, fine+coarse fused per launch
    gemm_mma<<<dim3(6, 512 + 32), 256, GEMM_SMEM>>>(
        A, WqkvT, bqkv, nullptr, nullptr, QKVh, 3,
        Ac, WqkvT + 196608, bqkv + 768, nullptr, nullptr, QKVc, 3,
        512, 256, 768, 768, 6);
    attn_mma_kernel<<<NWIN0 * 8 + NWIN1 * 8, 256, ATTN_SMEM>>>(
        QKVh, A, QKVc, Ac, NWIN0 * 8);
    gemm_mma<<<dim3(2, 512 + 32), 256, GEMM_SMEM>>>(
        A, WoT, bo, X0h, nullptr, X0h, 5,
        Ac, WoT + 65536, bo + 256, X1h, nullptr, X1h, 5,
        512, 256, 256, 256, 2);
    ln_half_h_kernel<<<T0 / 8 + T1 / 8, 256>>>(
        X0h, A, ln2_g, ln2_b, X1h, Ac, ln2_g + 256, ln2_b + 256, T0 / 8);
    gemm_mma<<<dim3(8, 512 + 32), 256, GEMM_SMEM>>>(
        A, W1T, mb1, nullptr, nullptr, H1, 1,
        Ac, W1T + 262144, mb1 + 1024, nullptr, nullptr, H1c, 1,
        512, 256, 1024, 1024, 8);
    // MLP2: fine -> out (fp32, epi2), coarse -> X1h (fp16, epi5)
    gemm_mma<<<dim3(2, 512 + 32), 256, GEMM_SMEM>>>(
        H1, W2T, mb2, X0h, out, nullptr, 2,
        H1c, W2T + 262144, mb2 + 256, X1h, nullptr, X1h, 5,
        512, 1024, 256, 256, 2);

    // 3) one2one cross-attention aggregation (scale-1 weights)
    ln_pre_cross_kernel<<<T0 / 8 + T1 / 8, 256>>>(
        out, A, X1h, Gh, A3, ln1_g + 256, ln1_b + 256, T0 / 8);
    gemm_mma<<<dim3(4, 512 + 32), 256, GEMM_SMEM>>>(
        A, WqkvT + 196608 + 65536, bqkv + 768 + 256, nullptr, nullptr, QKVh, 3,
        A3, WqkvT + 196608, bqkv + 768, nullptr, nullptr, Qbh, 3,
        512, 256, 512, 256, 2);
    cross_attn_kernel<<<T1, 256>>>(Qbh, QKVh, A3);
    gemm_mma<<<dim3(2, 32), 256, GEMM_SMEM>>>(
        A3, WoT + 65536, bo + 256, Gh, nullptr, Gh, 5,
        A3, WoT + 65536, bo + 256, Gh, nullptr, Gh, 5, 32, 256, 256, 256, 2);
    ln_half_h_kernel<<<T1 / 8, 256>>>(
        Gh, A3, ln2_g + 256, ln2_b + 256,
        Gh, A3, ln2_g + 256, ln2_b + 256, T1 / 8);
    gemm_mma<<<dim3(8, 32), 256, GEMM_SMEM>>>(
        A3, W1T + 262144, mb1 + 1024, nullptr, nullptr, H1, 1,
        A3, W1T + 262144, mb1 + 1024, nullptr, nullptr, H1, 1, 32, 256, 1024, 1024, 8);
    // MLP2 + residual, scattered directly into out1 (epi4)
    gemm_mma<<<dim3(2, 32), 256, GEMM_SMEM>>>(
        H1, W2T + 262144, mb2 + 256, Gh, out + (size_t)NWIN0 * 256 * 256, nullptr, 4,
        H1, W2T + 262144, mb2 + 256, Gh, out + (size_t)NWIN0 * 256 * 256, nullptr, 4,
        32, 1024, 256, 256, 2);
}

// round 14
// speedup vs baseline: 1.1461x; 1.0084x over previous
#include <cuda_runtime.h>
#include <cuda_fp16.h>
#include <cstdint>
#include <cstddef>

// ---------------------------------------------------------------------------
// Dimensions: B=4, H=W=8, M=16, C=256, NH=8, HD=32, GW=2
// ---------------------------------------------------------------------------
#define T0      65536
#define T1      4096
#define NWIN0   256
#define NWIN1   16

#define TILE_BYTES 16384
#define BUF_BYTES  (2 * TILE_BYTES)
#define GEMM_SMEM  (3 * BUF_BYTES)

#define ATTN_ROWB  80
#define ATTN_SMEM  (3 * 256 * ATTN_ROWB)

// ---------------------------------------------------------------------------
// PTX helpers
// ---------------------------------------------------------------------------
__device__ __forceinline__ uint32_t smem_u32(const void* p) {
    uint32_t a;
    asm("{ .reg .u64 t; cvta.to.shared.u64 t, %1; cvt.u32.u64 %0, t; }" : "=r"(a) : "l"(p));
    return a;
}
__device__ __forceinline__ void cp16(uint32_t dst, const void* src) {
    asm volatile("cp.async.cg.shared.global [%0], [%1], 16;" :: "r"(dst), "l"(src) : "memory");
}
#define CP_COMMIT() asm volatile("cp.async.commit_group;" ::: "memory")
#define CP_WAIT2()  asm volatile("cp.async.wait_group 2;" ::: "memory")
#define CP_WAIT1()  asm volatile("cp.async.wait_group 1;" ::: "memory")
#define CP_WAIT0()  asm volatile("cp.async.wait_group 0;" ::: "memory")

__device__ __forceinline__ void ldsm4(uint32_t& r0, uint32_t& r1, uint32_t& r2,
                                      uint32_t& r3, uint32_t addr) {
    asm volatile("ldmatrix.sync.aligned.m8n8.x4.shared.b16 {%0,%1,%2,%3}, [%4];"
                 : "=r"(r0), "=r"(r1), "=r"(r2), "=r"(r3) : "r"(addr));
}
__device__ __forceinline__ void ldsm4t(uint32_t& r0, uint32_t& r1, uint32_t& r2,
                                       uint32_t& r3, uint32_t addr) {
    asm volatile("ldmatrix.sync.aligned.m8n8.x4.trans.shared.b16 {%0,%1,%2,%3}, [%4];"
                 : "=r"(r0), "=r"(r1), "=r"(r2), "=r"(r3) : "r"(addr));
}
__device__ __forceinline__ void mma16816(float* c, const uint32_t* a, const uint32_t* b) {
    asm volatile(
        "mma.sync.aligned.m16n8k16.row.col.f32.f16.f16.f32 "
        "{%0,%1,%2,%3}, {%4,%5,%6,%7}, {%8,%9}, {%0,%1,%2,%3};"
        : "+f"(c[0]), "+f"(c[1]), "+f"(c[2]), "+f"(c[3])
        : "r"(a[0]), "r"(a[1]), "r"(a[2]), "r"(a[3]), "r"(b[0]), "r"(b[1]));
}
__device__ __forceinline__ uint32_t packh2(float a, float b) {
    __half2 h = __floats2half2_rn(a, b);
    return *(uint32_t*)&h;
}
__device__ __forceinline__ float2 unpackh2(uint32_t u) {
    return __half22float2(*(__half2*)&u);
}

// Row-level permutation: gidx -> o1-row
__device__ __forceinline__ int scatter_perm(int g) {
    int rr = g & 15, r1 = rr >> 2, r2 = rr & 3;
    int bhw = g >> 4;
    int w = bhw & 7, h = (bhw >> 3) & 7, b = bhw >> 6;
    int R = h * 4 + r1, Cc = w * 4 + r2;
    return (((b * 2 + (R >> 4)) * 2 + (Cc >> 4)) << 8) + (R & 15) * 16 + (Cc & 15);
}

// ---------------------------------------------------------------------------
// Scratch (residual streams in fp16)
// ---------------------------------------------------------------------------
__device__ float g_PE [2 * 256 * 256];
__device__ __half g_X0h[(size_t)T0 * 256];
__device__ __half g_X1h[(size_t)T1 * 256];
__device__ __half g_Gh [(size_t)T1 * 256];
__device__ __half g_Qbh[(size_t)T1 * 256];
__device__ __half g_QKVh[(size_t)T0 * 768];
__device__ __half g_QKVc[(size_t)T1 * 768];
__device__ __half g_A  [(size_t)T0 * 256];
__device__ __half g_Ac [(size_t)T1 * 256];
__device__ __half g_H1 [(size_t)T0 * 1024];
__device__ __half g_H1c[(size_t)T1 * 1024];
__device__ __half g_A3 [(size_t)T1 * 256];
__device__ __half g_WqkvT[2 * 768 * 256];
__device__ __half g_WoT  [2 * 256 * 256];
__device__ __half g_W1T  [2 * 1024 * 256];
__device__ __half g_W2T  [2 * 256 * 1024];

// ---------------------------------------------------------------------------
// Elementwise helpers: contiguous 8 channels per lane
// ---------------------------------------------------------------------------
__device__ __forceinline__ void load8h(const __half* row, int lane,
                                       float4& v0, float4& v1) {
    uint4 u = ((const uint4*)row)[lane];
    float2 f0 = unpackh2(u.x), f1 = unpackh2(u.y);
    float2 f2 = unpackh2(u.z), f3 = unpackh2(u.w);
    v0 = make_float4(f0.x, f0.y, f1.x, f1.y);
    v1 = make_float4(f2.x, f2.y, f3.x, f3.y);
}
__device__ __forceinline__ void store8h(__half* row, int lane, float4 v0, float4 v1) {
    uint4 u;
    u.x = packh2(v0.x, v0.y); u.y = packh2(v0.z, v0.w);
    u.z = packh2(v1.x, v1.y); u.w = packh2(v1.z, v1.w);
    ((uint4*)row)[lane] = u;
}
__device__ __forceinline__ void ln_store8(float4 v0, float4 v1, int lane,
                                          const float* __restrict__ gamma,
                                          const float* __restrict__ beta,
                                          __half* __restrict__ orow) {
    float s = v0.x + v0.y + v0.z + v0.w + v1.x + v1.y + v1.z + v1.w;
#pragma unroll
    for (int d = 16; d; d >>= 1) s += __shfl_xor_sync(0xffffffffu, s, d);
    float mean = s * (1.f / 256.f);
    float d0x = v0.x - mean, d0y = v0.y - mean, d0z = v0.z - mean, d0w = v0.w - mean;
    float d1x = v1.x - mean, d1y = v1.y - mean, d1z = v1.z - mean, d1w = v1.w - mean;
    float q = d0x*d0x + d0y*d0y + d0z*d0z + d0w*d0w +
              d1x*d1x + d1y*d1y + d1z*d1z + d1w*d1w;
#pragma unroll
    for (int d = 16; d; d >>= 1) q += __shfl_xor_sync(0xffffffffu, q, d);
    float rstd = rsqrtf(q * (1.f / 256.f) + 1e-5f);
    float4 g0 = ((const float4*)gamma)[2 * lane], g1 = ((const float4*)gamma)[2 * lane + 1];
    float4 b0 = ((const float4*)beta)[2 * lane],  b1 = ((const float4*)beta)[2 * lane + 1];
    uint4 u;
    u.x = packh2(fmaf(d0x * rstd, g0.x, b0.x), fmaf(d0y * rstd, g0.y, b0.y));
    u.y = packh2(fmaf(d0z * rstd, g0.z, b0.z), fmaf(d0w * rstd, g0.w, b0.w));
    u.z = packh2(fmaf(d1x * rstd, g1.x, b1.x), fmaf(d1y * rstd, g1.y, b1.y));
    u.w = packh2(fmaf(d1z * rstd, g1.z, b1.z), fmaf(d1w * rstd, g1.w, b1.w));
    ((uint4*)orow)[lane] = u;
}

// ---------------------------------------------------------------------------
// Small kernels
// ---------------------------------------------------------------------------
__global__ void posemb_kernel(const float* __restrict__ pe_w1,
                              const float* __restrict__ pe_b1,
                              const float* __restrict__ pe_w2,
                              float* __restrict__ PE) {
    int s = blockIdx.x >> 8;
    int n = blockIdx.x & 255;
    int i = n >> 4, j = n & 15;
    float cy = (i - 8) * 0.125f;
    float cx = (j - 8) * 0.125f;
    __shared__ float hid[512];
    const float* w1 = pe_w1 + s * 2 * 512;
    const float* b1 = pe_b1 + s * 512;
    for (int k = threadIdx.x; k < 512; k += 256)
        hid[k] = fmaxf(0.f, fmaf(cy, w1[k], fmaf(cx, w1[512 + k], b1[k])));
    __syncthreads();
    const float* w2 = pe_w2 + (size_t)s * 512 * 256;
    int c = threadIdx.x;
    float acc = 0.f;
#pragma unroll 8
    for (int k = 0; k < 512; k++) acc = fmaf(hid[k], w2[(size_t)k * 256 + c], acc);
    PE[((size_t)s * 256 + n) * 256 + c] = acc;
}

__global__ void __launch_bounds__(256)
add_pe0_ln_kernel(const float* __restrict__ s0, const float* __restrict__ PE,
                  __half* __restrict__ X0h, __half* __restrict__ A,
                  const float* __restrict__ gamma, const float* __restrict__ beta) {
    int token = blockIdx.x * 8 + (threadIdx.x >> 5);
    int lane = threadIdx.x & 31;
    const float4* sr = (const float4*)(s0 + (size_t)token * 256);
    const float4* pr = (const float4*)(PE + (size_t)(token & 255) * 256);
    float4 v0 = sr[2 * lane], v1 = sr[2 * lane + 1];
    float4 p0 = pr[2 * lane], p1 = pr[2 * lane + 1];
    v0.x += p0.x; v0.y += p0.y; v0.z += p0.z; v0.w += p0.w;
    v1.x += p1.x; v1.y += p1.y; v1.z += p1.z; v1.w += p1.w;
    store8h(X0h + (size_t)token * 256, lane, v0, v1);
    ln_store8(v0, v1, lane, gamma, beta, A + (size_t)token * 256);
}

__global__ void __launch_bounds__(256)
pool_add_ln_kernel(const float* __restrict__ s1, const float* __restrict__ PE,
                   const __half* __restrict__ X0h, __half* __restrict__ X1h,
                   __half* __restrict__ Ac,
                   const float* __restrict__ gamma, const float* __restrict__ beta) {
    int token = blockIdx.x * 8 + (threadIdx.x >> 5);
    int lane = threadIdx.x & 31;
    int t  = token & 255;
    int gw = token >> 8;
    int b = gw >> 2, gi = (gw >> 1) & 1, gj = gw & 1;
    int ti = t >> 4, tj = t & 15;
    int R  = gi * 16 + ti, Cc = gj * 16 + tj;
    int h = R >> 2, r1 = R & 3, w = Cc >> 2, r2 = Cc & 3;
    int fw = b * 64 + h * 8 + w;
    float4 m0 = make_float4(-1e30f, -1e30f, -1e30f, -1e30f), m1 = m0;
#pragma unroll
    for (int p1 = 0; p1 < 4; p1++)
#pragma unroll
        for (int p2 = 0; p2 < 4; p2++) {
            int n = (r1 * 4 + p1) * 16 + r2 * 4 + p2;
            float4 a, c;
            load8h(X0h + ((size_t)fw * 256 + n) * 256, lane, a, c);
            m0.x = fmaxf(m0.x, a.x); m0.y = fmaxf(m0.y, a.y);
            m0.z = fmaxf(m0.z, a.z); m0.w = fmaxf(m0.w, a.w);
            m1.x = fmaxf(m1.x, c.x); m1.y = fmaxf(m1.y, c.y);
            m1.z = fmaxf(m1.z, c.z); m1.w = fmaxf(m1.w, c.w);
        }
    const float4* sr = (const float4*)(s1 + (size_t)token * 256);
    const float4* pr = (const float4*)(PE + (size_t)(256 + t) * 256);
    float4 s0v = sr[2 * lane], s1v = sr[2 * lane + 1];
    float4 p0 = pr[2 * lane], p1v = pr[2 * lane + 1];
    m0.x += s0v.x + p0.x; m0.y += s0v.y + p0.y;
    m0.z += s0v.z + p0.z; m0.w += s0v.w + p0.w;
    m1.x += s1v.x + p1v.x; m1.y += s1v.y + p1v.y;
    m1.z += s1v.z + p1v.z; m1.w += s1v.w + p1v.w;
    store8h(X1h + (size_t)token * 256, lane, m0, m1);
    ln_store8(m0, m1, lane, gamma, beta, Ac + (size_t)token * 256);
}

__global__ void __launch_bounds__(256)
ln_half_h_kernel(const __half* __restrict__ x, __half* __restrict__ o,
                 const float* __restrict__ gamma, const float* __restrict__ beta,
                 const __half* __restrict__ x2, __half* __restrict__ o2,
                 const float* __restrict__ gamma2, const float* __restrict__ beta2,
                 int split) {
    int blk = blockIdx.x;
    const __half* xp = x; __half* op = o;
    const float* gp = gamma; const float* bp = beta;
    if (blk >= split) { blk -= split; xp = x2; op = o2; gp = gamma2; bp = beta2; }
    int token = blk * 8 + (threadIdx.x >> 5);
    int lane = threadIdx.x & 31;
    float4 v0, v1;
    load8h(xp + (size_t)token * 256, lane, v0, v1);
    ln_store8(v0, v1, lane, gp, bp, op + (size_t)token * 256);
}

__global__ void __launch_bounds__(256)
ln_pre_cross_kernel(const float* __restrict__ o0, __half* __restrict__ Afine,
                    const __half* __restrict__ X1h, __half* __restrict__ Gh,
                    __half* __restrict__ A3,
                    const float* __restrict__ gamma, const float* __restrict__ beta,
                    int split) {
    int blk = blockIdx.x;
    int lane = threadIdx.x & 31;
    if (blk < split) {
        int fidx = blk * 8 + (threadIdx.x >> 5);
        int pp = fidx & 15, p1 = pp >> 2, p2 = pp & 3;
        int grp = fidx >> 4;
        int rr = grp & 15, r1 = rr >> 2, r2 = rr & 3;
        int bhw = grp >> 4;
        int w = bhw & 7, h = (bhw >> 3) & 7, b = bhw >> 6;
        int fw = b * 64 + h * 8 + w;
        int n = (r1 * 4 + p1) * 16 + r2 * 4 + p2;
        const float4* xr = (const float4*)(o0 + ((size_t)fw * 256 + n) * 256);
        ln_store8(xr[2 * lane], xr[2 * lane + 1], lane, gamma, beta,
                  Afine + (size_t)fidx * 256);
    } else {
        int gidx = (blk - split) * 8 + (threadIdx.x >> 5);
        int rr = gidx & 15, r1 = rr >> 2, r2 = rr & 3;
        int bhw = gidx >> 4;
        int w = bhw & 7, h = (bhw >> 3) & 7, b = bhw >> 6;
        int R = h * 4 + r1, Cc = w * 4 + r2;
        int gi = R >> 4, ti = R & 15, gj = Cc >> 4, tj = Cc & 15;
        int win = (b * 2 + gi) * 2 + gj, tok = ti * 16 + tj;
        const __half* src = X1h + ((size_t)win * 256 + tok) * 256;
        uint4 raw = ((const uint4*)src)[lane];
        ((uint4*)(Gh + (size_t)gidx * 256))[lane] = raw;
        float4 v0, v1;
        load8h(src, lane, v0, v1);
        ln_store8(v0, v1, lane, gamma, beta, A3 + (size_t)gidx * 256);
    }
}

// Coalesced weight transpose-convert: W[K,N] fp32 -> T[N,K] fp16.
// 64x64 tiles via padded smem; reads and writes both coalesced.
// Tiles per scale: qkv 4x12=48 | wo 4x4=16 | mw1 4x16=64 | mw2 16x4=64 => 192.
__global__ void __launch_bounds__(256)
wconv_all_kernel(const float* __restrict__ wqkv, const float* __restrict__ wo,
                 const float* __restrict__ mw1, const float* __restrict__ mw2,
                 __half* __restrict__ Tqkv, __half* __restrict__ To,
                 __half* __restrict__ Tm1,  __half* __restrict__ Tm2) {
    __shared__ float sm[64][65];
    int bid = blockIdx.x;
    int s = bid / 192, r = bid % 192;
    const float* W; __half* T; int K, N, tk, tn;
    if (r < 48)      { W = wqkv + (size_t)s * 196608; T = Tqkv + (size_t)s * 196608;
                       K = 256;  N = 768;  tk = r % 4;          tn = r / 4; }
    else if (r < 64) { W = wo   + (size_t)s * 65536;  T = To   + (size_t)s * 65536;
                       K = 256;  N = 256;  tk = (r - 48) % 4;   tn = (r - 48) / 4; }
    else if (r < 128){ W = mw1  + (size_t)s * 262144; T = Tm1  + (size_t)s * 262144;
                       K = 256;  N = 1024; tk = (r - 64) % 4;   tn = (r - 64) / 4; }
    else             { W = mw2  + (size_t)s * 262144; T = Tm2  + (size_t)s * 262144;
                       K = 1024; N = 256;  tk = (r - 128) % 16; tn = (r - 128) / 16; }
    int k0 = tk * 64, n0 = tn * 64;
    int c = threadIdx.x & 63, rr = threadIdx.x >> 6;   // 4 rows per iter
#pragma unroll
    for (int i = 0; i < 16; i++) {
        int krow = rr + i * 4;
        sm[krow][c] = W[(size_t)(k0 + krow) * N + n0 + c];   // coalesced read
    }
    __syncthreads();
#pragma unroll
    for (int i = 0; i < 16; i++) {
        int nrow = rr + i * 4;
        T[(size_t)(n0 + nrow) * K + k0 + c] = __float2half(sm[c][nrow]);  // coalesced write
    }
}

// ---------------------------------------------------------------------------
// fp16 1-pass GEMM, dual-problem, runtime epilogue code per problem.
// epi 1: GELU -> Oh.  2: +resH -> Cp fp32.  3: -> Oh.
// epi 4: +resH -> Cp fp32 at scatter_perm(row).  5: +resH -> Oh fp16.
// ---------------------------------------------------------------------------
__global__ void __launch_bounds__(256)
gemm_mma(const __half* A, const __half* B,
         const float* bias, const __half* resH,
         float* Cp, __half* Oh, int epiA,
         const __half* A2, const __half* B2,
         const float* bias2, const __half* resH2,
         float* Cp2, __half* Oh2, int epiB,
         int bmSplit, int K, int ldc, int ldc2, int bn2Max) {
    extern __shared__ char smc[];
    const uint32_t sb = smem_u32(smc);
    int tid = threadIdx.x, lane = tid & 31, wid = tid >> 5;
    int wm = wid >> 2, wn = wid & 3;
    int bm = blockIdx.y, bn = blockIdx.x;
    int epi = epiA;
    if (bm >= bmSplit) {
        bm -= bmSplit;
        if (bn >= bn2Max) return;
        A = A2; B = B2; bias = bias2; resH = resH2; Cp = Cp2; Oh = Oh2;
        ldc = ldc2; epi = epiB;
    }

    const __half* src0 = A + (size_t)bm * 128 * K;
    const __half* src1 = B + (size_t)bn * 128 * K;

    int nc = K >> 6;
    int crow0 = tid >> 3, ccol = tid & 7;

#define PREFETCH(CH, BUF) do {                                                 \
    int _k0 = (CH) << 6;                                                       \
    const __half* _s[2] = {src0 + _k0, src1 + _k0};                            \
    _Pragma("unroll")                                                          \
    for (int _op = 0; _op < 2; _op++) {                                        \
        uint32_t _db = sb + (BUF) * BUF_BYTES + _op * TILE_BYTES;              \
        _Pragma("unroll")                                                      \
        for (int _i = 0; _i < 4; _i++) {                                       \
            int _row = crow0 + _i * 32;                                        \
            uint32_t _doff = _db + _row * 128 + ((ccol ^ (_row & 7)) << 4);    \
            cp16(_doff, _s[_op] + (size_t)_row * K + ccol * 8);                \
        }                                                                      \
    }                                                                          \
} while (0)

    float acc[4][4][4];
#pragma unroll
    for (int mi = 0; mi < 4; mi++)
#pragma unroll
        for (int ni = 0; ni < 4; ni++)
#pragma unroll
            for (int r = 0; r < 4; r++) acc[mi][ni][r] = 0.f;

    PREFETCH(0, 0);
    CP_COMMIT();
    if (nc > 1) { PREFETCH(1, 1); CP_COMMIT(); }

    int a_rl = lane & 15;
    int b_rl = ((lane >> 4) << 3) + (lane & 7);

    for (int ch = 0; ch < nc; ch++) {
        int buf = ch % 3;
        if (ch + 2 < nc) {
            PREFETCH(ch + 2, (ch + 2) % 3);
            CP_COMMIT();
            CP_WAIT2();
        } else if (ch + 1 < nc) {
            CP_WAIT1();
        } else {
            CP_WAIT0();
        }
        __syncthreads();

        uint32_t base = sb + buf * BUF_BYTES;
#pragma unroll
        for (int ks = 0; ks < 4; ks++) {
            uint32_t ah[4][4], bh[4][2];
            int achunk = ks * 2 + (lane >> 4);
            int bchunk = ks * 2 + ((lane >> 3) & 1);
#pragma unroll
            for (int mi = 0; mi < 4; mi++) {
                int row = wm * 64 + mi * 16 + a_rl;
                uint32_t off = (uint32_t)(row * 128 + ((achunk ^ (row & 7)) << 4));
                ldsm4(ah[mi][0], ah[mi][1], ah[mi][2], ah[mi][3], base + off);
            }
#pragma unroll
            for (int np = 0; np < 2; np++) {
                int row = wn * 32 + np * 16 + b_rl;
                uint32_t off = (uint32_t)(row * 128 + ((bchunk ^ (row & 7)) << 4));
                uint32_t r0, r1, r2, r3;
                ldsm4(r0, r1, r2, r3, base + TILE_BYTES + off);
                bh[np * 2][0] = r0; bh[np * 2][1] = r1;
                bh[np * 2 + 1][0] = r2; bh[np * 2 + 1][1] = r3;
            }
#pragma unroll
            for (int mi = 0; mi < 4; mi++)
#pragma unroll
                for (int ni = 0; ni < 4; ni++)
                    mma16816(acc[mi][ni], ah[mi], bh[ni]);
        }
        __syncthreads();
    }
#undef PREFETCH

    int l4 = lane >> 2, l2 = (lane & 3) << 1;
#pragma unroll
    for (int mi = 0; mi < 4; mi++) {
        int r0 = bm * 128 + wm * 64 + mi * 16 + l4;
        int sr0 = (epi == 4) ? scatter_perm(r0) : r0;
        int sr1 = (epi == 4) ? scatter_perm(r0 + 8) : r0 + 8;
#pragma unroll
        for (int ni = 0; ni < 4; ni++) {
            int cc = bn * 128 + wn * 32 + ni * 8 + l2;
            float b0 = bias[cc], b1 = bias[cc + 1];
            float v00 = acc[mi][ni][0] + b0, v01 = acc[mi][ni][1] + b1;
            float v10 = acc[mi][ni][2] + b0, v11 = acc[mi][ni][3] + b1;
            size_t o0 = (size_t)r0 * ldc + cc;
            size_t o1 = (size_t)(r0 + 8) * ldc + cc;
            if (epi == 1) {
                const float is2 = 0.7071067811865476f;
                float g00 = 0.5f * v00 * (1.f + erff(v00 * is2));
                float g01 = 0.5f * v01 * (1.f + erff(v01 * is2));
                float g10 = 0.5f * v10 * (1.f + erff(v10 * is2));
                float g11 = 0.5f * v11 * (1.f + erff(v11 * is2));
                *(uint32_t*)(Oh + o0) = packh2(g00, g01);
                *(uint32_t*)(Oh + o1) = packh2(g10, g11);
            } else if (epi == 3) {
                *(uint32_t*)(Oh + o0) = packh2(v00, v01);
                *(uint32_t*)(Oh + o1) = packh2(v10, v11);
            } else {
                float2 ra = unpackh2(*(const uint32_t*)(resH + o0));
                float2 rb = unpackh2(*(const uint32_t*)(resH + o1));
                v00 += ra.x; v01 += ra.y; v10 += rb.x; v11 += rb.y;
                if (epi == 5) {
                    *(uint32_t*)(Oh + o0) = packh2(v00, v01);
                    *(uint32_t*)(Oh + o1) = packh2(v10, v11);
                } else {
                    *(float2*)(Cp + (size_t)sr0 * ldc + cc) = make_float2(v00, v01);
                    *(float2*)(Cp + (size_t)sr1 * ldc + cc) = make_float2(v10, v11);
                }
            }
        }
    }
}

// ---------------------------------------------------------------------------
// Tensor-core flash attention (no-max softmax), dual-problem.
// ---------------------------------------------------------------------------
__global__ void __launch_bounds__(256)
attn_mma_kernel(const __half* qkv, __half* out,
                const __half* qkv2, __half* out2, int ctaSplit) {
    extern __shared__ char smc[];
    const uint32_t sb = smem_u32(smc);
    const uint32_t sbQ = sb, sbK = sb + 256 * ATTN_ROWB, sbV = sb + 512 * ATTN_ROWB;
    int cta = blockIdx.x;
    if (cta >= ctaSplit) { cta -= ctaSplit; qkv = qkv2; out = out2; }
    int win = cta >> 3, head = cta & 7;
    int tid = threadIdx.x, lane = tid & 31, wid = tid >> 5;

    {
        const uint4* src = (const uint4*)(qkv + ((size_t)(win * 256 + tid) * 768 + head * 32));
        uint4* dq = (uint4*)(smc + tid * ATTN_ROWB);
        uint4* dk = (uint4*)(smc + 256 * ATTN_ROWB + tid * ATTN_ROWB);
        uint4* dv = (uint4*)(smc + 512 * ATTN_ROWB + tid * ATTN_ROWB);
#pragma unroll
        for (int c = 0; c < 4; c++) dq[c] = src[c];
#pragma unroll
        for (int c = 0; c < 4; c++) dk[c] = src[32 + c];
#pragma unroll
        for (int c = 0; c < 4; c++) dv[c] = src[64 + c];
    }
    __syncthreads();

    uint32_t aq[2][2][4];
#pragma unroll
    for (int mi = 0; mi < 2; mi++)
#pragma unroll
        for (int kt = 0; kt < 2; kt++) {
            int row = wid * 32 + mi * 16 + (lane & 15);
            uint32_t addr = sbQ + row * ATTN_ROWB + (kt * 2 + (lane >> 4)) * 16;
            ldsm4(aq[mi][kt][0], aq[mi][kt][1], aq[mi][kt][2], aq[mi][kt][3], addr);
        }

    float o[2][4][4];
#pragma unroll
    for (int mi = 0; mi < 2; mi++)
#pragma unroll
        for (int ni = 0; ni < 4; ni++)
#pragma unroll
            for (int r = 0; r < 4; r++) o[mi][ni][r] = 0.f;
    float l[2][2] = {{0.f, 0.f}, {0.f, 0.f}};
    const float sc = 0.17677669529663687f * 1.4426950408889634f;

    for (int kc = 0; kc < 4; kc++) {
        float s[2][8][4];
#pragma unroll
        for (int mi = 0; mi < 2; mi++)
#pragma unroll
            for (int ni = 0; ni < 8; ni++)
#pragma unroll
                for (int r = 0; r < 4; r++) s[mi][ni][r] = 0.f;

#pragma unroll
        for (int nt = 0; nt < 4; nt++) {
            int keyrow = kc * 64 + nt * 16 + (lane & 15);
#pragma unroll
            for (int kt = 0; kt < 2; kt++) {
                uint32_t addr = sbK + keyrow * ATTN_ROWB + (kt * 2 + (lane >> 4)) * 16;
                uint32_t r0, r1, r2, r3;
                ldsm4(r0, r1, r2, r3, addr);
                uint32_t blo[2] = {r0, r2}, bhi[2] = {r1, r3};
#pragma unroll
                for (int mi = 0; mi < 2; mi++) {
                    mma16816(s[mi][nt * 2],     aq[mi][kt], blo);
                    mma16816(s[mi][nt * 2 + 1], aq[mi][kt], bhi);
                }
            }
        }

#pragma unroll
        for (int mi = 0; mi < 2; mi++)
#pragma unroll
            for (int ni = 0; ni < 8; ni++) {
                float p0 = exp2f(s[mi][ni][0] * sc);
                float p1 = exp2f(s[mi][ni][1] * sc);
                float p2 = exp2f(s[mi][ni][2] * sc);
                float p3 = exp2f(s[mi][ni][3] * sc);
                s[mi][ni][0] = p0; s[mi][ni][1] = p1;
                s[mi][ni][2] = p2; s[mi][ni][3] = p3;
                l[mi][0] += p0 + p1;
                l[mi][1] += p2 + p3;
            }

        uint32_t pa[2][4][4];
#pragma unroll
        for (int mi = 0; mi < 2; mi++)
#pragma unroll
            for (int kt = 0; kt < 4; kt++) {
                pa[mi][kt][0] = packh2(s[mi][kt * 2][0], s[mi][kt * 2][1]);
                pa[mi][kt][1] = packh2(s[mi][kt * 2][2], s[mi][kt * 2][3]);
                pa[mi][kt][2] = packh2(s[mi][kt * 2 + 1][0], s[mi][kt * 2 + 1][1]);
                pa[mi][kt][3] = packh2(s[mi][kt * 2 + 1][2], s[mi][kt * 2 + 1][3]);
            }

#pragma unroll
        for (int kt = 0; kt < 4; kt++) {
            int keyrow = kc * 64 + kt * 16 + (lane & 15);
#pragma unroll
            for (int dc = 0; dc < 2; dc++) {
                uint32_t addr = sbV + keyrow * ATTN_ROWB + (dc * 2 + (lane >> 4)) * 16;
                uint32_t r0, r1, r2, r3;
                ldsm4t(r0, r1, r2, r3, addr);
                uint32_t b0[2] = {r0, r1}, b1[2] = {r2, r3};
#pragma unroll
                for (int mi = 0; mi < 2; mi++) {
                    mma16816(o[mi][dc * 2],     pa[mi][kt], b0);
                    mma16816(o[mi][dc * 2 + 1], pa[mi][kt], b1);
                }
            }
        }
    }

#pragma unroll
    for (int mi = 0; mi < 2; mi++)
#pragma unroll
        for (int h = 0; h < 2; h++) {
            float v = l[mi][h];
            v += __shfl_xor_sync(0xffffffffu, v, 1);
            v += __shfl_xor_sync(0xffffffffu, v, 2);
            l[mi][h] = v;
        }

    int l4 = lane >> 2, l2 = (lane & 3) << 1;
#pragma unroll
    for (int mi = 0; mi < 2; mi++)
#pragma unroll
        for (int h = 0; h < 2; h++) {
            float inv = 1.f / l[mi][h];
            int row = wid * 32 + mi * 16 + l4 + h * 8;
            size_t ob = ((size_t)(win * 256 + row)) * 256 + head * 32;
#pragma unroll
            for (int ni = 0; ni < 4; ni++) {
                *(uint32_t*)(out + ob + ni * 8 + l2) =
                    packh2(o[mi][ni][h * 2] * inv, o[mi][ni][h * 2 + 1] * inv);
            }
        }
}

// ---------------------------------------------------------------------------
// Cross attention: 1 query x 16 keys, warp per head; fp16 Q and KV
// ---------------------------------------------------------------------------
__global__ void __launch_bounds__(256)
cross_attn_kernel(const __half* __restrict__ Q, const __half* __restrict__ KV,
                  __half* __restrict__ oh) {
    int g = blockIdx.x;
    int head = threadIdx.x >> 5, lane = threadIdx.x & 31;
    float qd = __half2float(Q[(size_t)g * 256 + head * 32 + lane]);
    size_t kvbase = (size_t)g * 16 * 512 + head * 32 + lane;
    const float sc = 0.17677669529663687f * 1.4426950408889634f;
    float s[16];
#pragma unroll
    for (int j = 0; j < 16; j++) {
        float p = qd * __half2float(KV[kvbase + (size_t)j * 512]);
#pragma unroll
        for (int o = 16; o; o >>= 1) p += __shfl_xor_sync(0xffffffffu, p, o);
        s[j] = p * sc;
    }
    float l = 0.f;
#pragma unroll
    for (int j = 0; j < 16; j++) { s[j] = exp2f(s[j]); l += s[j]; }
    float inv = 1.f / l, acc = 0.f;
#pragma unroll
    for (int j = 0; j < 16; j++)
        acc = fmaf(s[j], __half2float(KV[kvbase + 256 + (size_t)j * 512]), acc);
    oh[(size_t)g * 256 + head * 32 + lane] = __float2half(acc * inv);
}

// ---------------------------------------------------------------------------
// Host launch
// ---------------------------------------------------------------------------
extern "C" void kernel_launch(void* const* d_in, const int* in_sizes, int n_in,
                              void* d_out, int out_size) {
    const float* scale0 = (const float*)d_in[0];
    const float* scale1 = (const float*)d_in[1];
    const float* pe_w1  = (const float*)d_in[2];
    const float* pe_b1  = (const float*)d_in[3];
    const float* pe_w2  = (const float*)d_in[4];
    const float* ln1_g  = (const float*)d_in[5];
    const float* ln1_b  = (const float*)d_in[6];
    const float* wqkv   = (const float*)d_in[7];
    const float* bqkv   = (const float*)d_in[8];
    const float* wo     = (const float*)d_in[9];
    const float* bo     = (const float*)d_in[10];
    const float* ln2_g  = (const float*)d_in[11];
    const float* ln2_b  = (const float*)d_in[12];
    const float* mw1    = (const float*)d_in[13];
    const float* mb1    = (const float*)d_in[14];
    const float* mw2    = (const float*)d_in[15];
    const float* mb2    = (const float*)d_in[16];
    float* out = (float*)d_out;

    float* PE;
    __half *X0h, *X1h, *Gh, *Qbh, *QKVh, *QKVc, *A, *Ac, *H1, *H1c, *A3;
    __half *WqkvT, *WoT, *W1T, *W2T;
    cudaGetSymbolAddress((void**)&PE,   g_PE);
    cudaGetSymbolAddress((void**)&X0h,  g_X0h);
    cudaGetSymbolAddress((void**)&X1h,  g_X1h);
    cudaGetSymbolAddress((void**)&Gh,   g_Gh);
    cudaGetSymbolAddress((void**)&Qbh,  g_Qbh);
    cudaGetSymbolAddress((void**)&QKVh, g_QKVh);
    cudaGetSymbolAddress((void**)&QKVc, g_QKVc);
    cudaGetSymbolAddress((void**)&A,    g_A);
    cudaGetSymbolAddress((void**)&Ac,   g_Ac);
    cudaGetSymbolAddress((void**)&H1,   g_H1);
    cudaGetSymbolAddress((void**)&H1c,  g_H1c);
    cudaGetSymbolAddress((void**)&A3,   g_A3);
    cudaGetSymbolAddress((void**)&WqkvT, g_WqkvT);
    cudaGetSymbolAddress((void**)&WoT,   g_WoT);
    cudaGetSymbolAddress((void**)&W1T,   g_W1T);
    cudaGetSymbolAddress((void**)&W2T,   g_W2T);

    cudaFuncSetAttribute(attn_mma_kernel, cudaFuncAttributeMaxDynamicSharedMemorySize, ATTN_SMEM);
    cudaFuncSetAttribute(gemm_mma, cudaFuncAttributeMaxDynamicSharedMemorySize, GEMM_SMEM);

    // 0) weights (coalesced tile transpose) + position embeddings
    wconv_all_kernel<<<384, 256>>>(wqkv, wo, mw1, mw2, WqkvT, WoT, W1T, W2T);
    posemb_kernel<<<512, 256>>>(pe_w1, pe_b1, pe_w2, PE);

    // 1) inputs with fused LN1 (residual streams in fp16)
    add_pe0_ln_kernel<<<T0 / 8, 256>>>(scale0, PE, X0h, A, ln1_g, ln1_b);
    pool_add_ln_kernel<<<T1 / 8, 256>>>(scale1, PE, X0h, X1h, Ac,
                                        ln1_g + 256, ln1_b + 256);

    // 2) self-attention blocks, fine+coarse fused per launch
    gemm_mma<<<dim3(6, 512 + 32), 256, GEMM_SMEM>>>(
        A, WqkvT, bqkv, nullptr, nullptr, QKVh, 3,
        Ac, WqkvT + 196608, bqkv + 768, nullptr, nullptr, QKVc, 3,
        512, 256, 768, 768, 6);
    attn_mma_kernel<<<NWIN0 * 8 + NWIN1 * 8, 256, ATTN_SMEM>>>(
        QKVh, A, QKVc, Ac, NWIN0 * 8);
    gemm_mma<<<dim3(2, 512 + 32), 256, GEMM_SMEM>>>(
        A, WoT, bo, X0h, nullptr, X0h, 5,
        Ac, WoT + 65536, bo + 256, X1h, nullptr, X1h, 5,
        512, 256, 256, 256, 2);
    ln_half_h_kernel<<<T0 / 8 + T1 / 8, 256>>>(
        X0h, A, ln2_g, ln2_b, X1h, Ac, ln2_g + 256, ln2_b + 256, T0 / 8);
    gemm_mma<<<dim3(8, 512 + 32), 256, GEMM_SMEM>>>(
        A, W1T, mb1, nullptr, nullptr, H1, 1,
        Ac, W1T + 262144, mb1 + 1024, nullptr, nullptr, H1c, 1,
        512, 256, 1024, 1024, 8);
    gemm_mma<<<dim3(2, 512 + 32), 256, GEMM_SMEM>>>(
        H1, W2T, mb2, X0h, out, nullptr, 2,
        H1c, W2T + 262144, mb2 + 256, X1h, nullptr, X1h, 5,
        512, 1024, 256, 256, 2);

    // 3) one2one cross-attention aggregation (scale-1 weights)
    ln_pre_cross_kernel<<<T0 / 8 + T1 / 8, 256>>>(
        out, A, X1h, Gh, A3, ln1_g + 256, ln1_b + 256, T0 / 8);
    gemm_mma<<<dim3(4, 512 + 32), 256, GEMM_SMEM>>>(
        A, WqkvT + 196608 + 65536, bqkv + 768 + 256, nullptr, nullptr, QKVh, 3,
        A3, WqkvT + 196608, bqkv + 768, nullptr, nullptr, Qbh, 3,
        512, 256, 512, 256, 2);
    cross_attn_kernel<<<T1, 256>>>(Qbh, QKVh, A3);
    gemm_mma<<<dim3(2, 32), 256, GEMM_SMEM>>>(
        A3, WoT + 65536, bo + 256, Gh, nullptr, Gh, 5,
        A3, WoT + 65536, bo + 256, Gh, nullptr, Gh, 5, 32, 256, 256, 256, 2);
    ln_half_h_kernel<<<T1 / 8, 256>>>(
        Gh, A3, ln2_g + 256, ln2_b + 256,
        Gh, A3, ln2_g + 256, ln2_b + 256, T1 / 8);
    gemm_mma<<<dim3(8, 32), 256, GEMM_SMEM>>>(
        A3, W1T + 262144, mb1 + 1024, nullptr, nullptr, H1, 1,
        A3, W1T + 262144, mb1 + 1024, nullptr, nullptr, H1, 1, 32, 256, 1024, 1024, 8);
    gemm_mma<<<dim3(2, 32), 256, GEMM_SMEM>>>(
        H1, W2T + 262144, mb2 + 256, Gh, out + (size_t)NWIN0 * 256 * 256, nullptr, 4,
        H1, W2T + 262144, mb2 + 256, Gh, out + (size_t)NWIN0 * 256 * 256, nullptr, 4,
        32, 1024, 256, 256, 2);
}